// round 3
// baseline (speedup 1.0000x reference)
#include <cuda_runtime.h>

// Problem constants (shapes fixed by the dataset)
#define NMAX 50000
#define EMAX 800000

// ---------------- scratch (static device allocations; no cudaMalloc) ----------------
__device__ float g_a [(size_t)NMAX * 128];   // aggregated layer-1 input  (ÂX)
__device__ float g_x1[(size_t)NMAX * 256];   // layer-1 output (post ReLU+LN)
__device__ float g_h2[(size_t)NMAX * 128];   // layer-2 transformed, dinv-scaled
__device__ float g_dinv[NMAX];
__device__ int   g_cnt[NMAX];
__device__ int   g_rowptr[NMAX + 1];
__device__ int   g_fill[NMAX];
__device__ int   g_col[EMAX];                // raw src node index (for layer-2 agg)
__device__ int2  g_colid[EMAX];              // {embed id of src, dinv[src]} (for layer-1 agg)
__device__ int   g_bsum[64];
__device__ int   g_bflag[64];

// ---------------- CSR build ----------------
__global__ void k_hist(const int* __restrict__ dst, int E) {
    int i = blockIdx.x * blockDim.x + threadIdx.x;
    if (i < E) atomicAdd(&g_cnt[dst[i]], 1);
}

// Single-kernel exclusive scan over g_cnt via chained block sums.
// 49 blocks of 1024 threads: all resident simultaneously -> spin is deadlock-free.
__global__ void k_scan(int n, int E) {
    __shared__ int sh[1024];
    __shared__ int s_off;
    int tid = threadIdx.x, b = blockIdx.x;
    int i = b * 1024 + tid;
    int c = (i < n) ? g_cnt[i] : 0;
    sh[tid] = c;
    __syncthreads();
    for (int off = 1; off < 1024; off <<= 1) {
        int t = (tid >= off) ? sh[tid - off] : 0;
        __syncthreads();
        sh[tid] += t;
        __syncthreads();
    }
    if (tid == 1023) {
        g_bsum[b] = sh[1023];
        __threadfence();
        g_bflag[b] = 1;
    }
    if (tid == 0) {
        int off = 0;
        for (int j = 0; j < b; j++) {
            while (((volatile int*)g_bflag)[j] == 0) { }
            off += ((volatile int*)g_bsum)[j];
        }
        s_off = off;
    }
    __syncthreads();
    if (i < n) {
        int incl = sh[tid] + s_off;
        int excl = incl - c;
        g_rowptr[i] = excl;
        g_fill[i] = excl;
        g_dinv[i] = rsqrtf((float)(c + 1));   // +1 self loop
    }
    if (i == 0) g_rowptr[n] = E;
}

__global__ void k_fill(const int* __restrict__ src, const int* __restrict__ dst,
                       const int* __restrict__ x_ids, int E) {
    int i = blockIdx.x * blockDim.x + threadIdx.x;
    if (i < E) {
        int s = src[i];
        int d = dst[i];
        int pos = atomicAdd(&g_fill[d], 1);
        g_col[pos] = s;
        g_colid[pos] = make_int2(x_ids[s], __float_as_int(g_dinv[s]));
    }
}

// ---------------- layer-1 aggregation straight from the embedding table ----------------
// out[w] = dinv[w] * ( dinv[w]*embed[id_w] + sum_j dinv[j]*embed[id_j] )
__global__ void k_agg0(const int* __restrict__ x_ids, const float4* __restrict__ embed, int n) {
    int t = blockIdx.x * blockDim.x + threadIdx.x;
    int w = t >> 5, lane = t & 31;
    if (w >= n) return;
    float diw = g_dinv[w];
    int sid = x_ids[w];
    float4 sv = embed[(size_t)sid * 32 + lane];
    float4 acc = make_float4(sv.x * diw, sv.y * diw, sv.z * diw, sv.w * diw);
    int s = g_rowptr[w], e = g_rowptr[w + 1];
    for (int b0 = s; b0 < e; b0 += 32) {
        int m = min(32, e - b0);
        int2 ci = (lane < m) ? g_colid[b0 + lane] : make_int2(0, 0);
        int tt = 0;
        for (; tt + 8 <= m; tt += 8) {
            int   ji[8]; float dj[8]; float4 vv[8];
            #pragma unroll
            for (int u = 0; u < 8; u++) {
                ji[u] = __shfl_sync(0xffffffffu, ci.x, tt + u);
                dj[u] = __int_as_float(__shfl_sync(0xffffffffu, ci.y, tt + u));
            }
            #pragma unroll
            for (int u = 0; u < 8; u++) vv[u] = embed[(size_t)ji[u] * 32 + lane];
            #pragma unroll
            for (int u = 0; u < 8; u++) {
                acc.x = fmaf(vv[u].x, dj[u], acc.x);
                acc.y = fmaf(vv[u].y, dj[u], acc.y);
                acc.z = fmaf(vv[u].z, dj[u], acc.z);
                acc.w = fmaf(vv[u].w, dj[u], acc.w);
            }
        }
        for (; tt < m; tt++) {
            int   j = __shfl_sync(0xffffffffu, ci.x, tt);
            float d = __int_as_float(__shfl_sync(0xffffffffu, ci.y, tt));
            float4 v = embed[(size_t)j * 32 + lane];
            acc.x = fmaf(v.x, d, acc.x);
            acc.y = fmaf(v.y, d, acc.y);
            acc.z = fmaf(v.z, d, acc.z);
            acc.w = fmaf(v.w, d, acc.w);
        }
    }
    ((float4*)g_a)[(size_t)w * 32 + lane] =
        make_float4(acc.x * diw, acc.y * diw, acc.z * diw, acc.w * diw);
}

// ---------------- layer-2 aggregation + bias + LayerNorm (writes final output) ----------------
__global__ void k_agg1(const float* __restrict__ b, const float* __restrict__ gamma,
                       const float* __restrict__ beta, float4* __restrict__ outp, int n) {
    int t = blockIdx.x * blockDim.x + threadIdx.x;
    int w = t >> 5, lane = t & 31;
    if (w >= n) return;
    const float4* xs = (const float4*)g_h2;   // already scaled by dinv[src]
    float4 acc = xs[(size_t)w * 32 + lane];   // self message
    int s = g_rowptr[w], e = g_rowptr[w + 1];
    for (int b0 = s; b0 < e; b0 += 32) {
        int m = min(32, e - b0);
        int idx = (lane < m) ? g_col[b0 + lane] : 0;
        int tt = 0;
        for (; tt + 8 <= m; tt += 8) {
            int j[8]; float4 vv[8];
            #pragma unroll
            for (int u = 0; u < 8; u++) j[u] = __shfl_sync(0xffffffffu, idx, tt + u);
            #pragma unroll
            for (int u = 0; u < 8; u++) vv[u] = xs[(size_t)j[u] * 32 + lane];
            #pragma unroll
            for (int u = 0; u < 8; u++) {
                acc.x += vv[u].x; acc.y += vv[u].y; acc.z += vv[u].z; acc.w += vv[u].w;
            }
        }
        for (; tt < m; tt++) {
            int j = __shfl_sync(0xffffffffu, idx, tt);
            float4 v = xs[(size_t)j * 32 + lane];
            acc.x += v.x; acc.y += v.y; acc.z += v.z; acc.w += v.w;
        }
    }
    float di = g_dinv[w];
    float4 bb = ((const float4*)b)[lane];
    float4 y = make_float4(acc.x * di + bb.x, acc.y * di + bb.y,
                           acc.z * di + bb.z, acc.w * di + bb.w);
    float s1 = y.x + y.y + y.z + y.w;
    #pragma unroll
    for (int off = 16; off; off >>= 1) s1 += __shfl_xor_sync(0xffffffffu, s1, off);
    float mu = s1 * (1.0f / 128.0f);
    float dx = y.x - mu, dy = y.y - mu, dz = y.z - mu, dw = y.w - mu;
    float sq = dx * dx + dy * dy + dz * dz + dw * dw;
    #pragma unroll
    for (int off = 16; off; off >>= 1) sq += __shfl_xor_sync(0xffffffffu, sq, off);
    float rstd = rsqrtf(sq * (1.0f / 128.0f) + 1e-5f);
    float4 gg = ((const float4*)gamma)[lane];
    float4 bt = ((const float4*)beta)[lane];
    outp[(size_t)w * 32 + lane] = make_float4(dx * rstd * gg.x + bt.x,
                                              dy * rstd * gg.y + bt.y,
                                              dz * rstd * gg.z + bt.z,
                                              dw * rstd * gg.w + bt.w);
}

// ---------------- GEMM: A[M,K] @ W[K,N], W resident in smem, fused epilogues ----------------
// MODE 0: A=g_a  (K=128), out=g_x1 (N=256), epilogue = +bias, ReLU, LayerNorm(gamma,beta)
// MODE 1: A=g_x1 (K=256), out=g_h2 (N=128), epilogue = * dinv[row]
// 256 threads, tile 64 rows x N cols. Warp ty owns rows [8*ty, 8*ty+8); lane tx owns
// col-pairs {2*tx + 64*j | j < N/64}. fma.rn.f32x2 for full-rate fp32.
template<int K, int N, int MODE>
__global__ void __launch_bounds__(256, 1)
k_gemm(const float* __restrict__ W, const float* __restrict__ bias,
       const float* __restrict__ gamma, const float* __restrict__ beta, int M) {
    extern __shared__ float smem[];
    float* Ws = smem;             // K*N floats
    float* Xs = smem + K * N;     // 64*K floats
    constexpr int NJ = N / 64;
    constexpr int R = 8;

    const float* A = (MODE == 0) ? g_a : g_x1;
    float* out = (MODE == 0) ? g_x1 : g_h2;

    int tid = threadIdx.x;
    // Load W into smem once (float4 vectorized)
    {
        const float4* Wv = (const float4*)W;
        float4* Wsv = (float4*)Ws;
        for (int idx = tid; idx < K * N / 4; idx += 256) Wsv[idx] = Wv[idx];
    }

    int tx = tid & 31, ty = tid >> 5;

    for (int m0 = blockIdx.x * 64; m0 < M; m0 += gridDim.x * 64) {
        __syncthreads();  // previous tile compute done (and W load visible, first iter)
        // Load X tile (64 rows x K)
        for (int idx = tid; idx < 64 * (K / 4); idx += 256) {
            int r = idx / (K / 4), kk = idx % (K / 4);
            int row = m0 + r;
            float4 v = (row < M) ? ((const float4*)A)[(size_t)row * (K / 4) + kk]
                                 : make_float4(0.f, 0.f, 0.f, 0.f);
            ((float4*)Xs)[idx] = v;
        }
        __syncthreads();

        unsigned long long acc[R][NJ];
        #pragma unroll
        for (int q = 0; q < R; q++)
            #pragma unroll
            for (int j = 0; j < NJ; j++) acc[q][j] = 0ull;

        const float* xr = Xs + (ty * R) * K;
        for (int k0 = 0; k0 < K; k0 += 2) {
            float2 xv[R];
            #pragma unroll
            for (int q = 0; q < R; q++)
                xv[q] = *(const float2*)(xr + q * K + k0);
            #pragma unroll
            for (int kk = 0; kk < 2; kk++) {
                unsigned long long w2[NJ];
                #pragma unroll
                for (int j = 0; j < NJ; j++)
                    w2[j] = *reinterpret_cast<const unsigned long long*>(
                        Ws + (k0 + kk) * N + 2 * tx + 64 * j);
                #pragma unroll
                for (int q = 0; q < R; q++) {
                    unsigned xu = __float_as_uint(kk == 0 ? xv[q].x : xv[q].y);
                    unsigned long long x2;
                    asm("mov.b64 %0, {%1, %1};" : "=l"(x2) : "r"(xu));
                    #pragma unroll
                    for (int j = 0; j < NJ; j++)
                        asm("fma.rn.f32x2 %0, %1, %2, %0;"
                            : "+l"(acc[q][j]) : "l"(x2), "l"(w2[j]));
                }
            }
        }

        // Unpack accumulators
        float v[R][2 * NJ];
        #pragma unroll
        for (int q = 0; q < R; q++)
            #pragma unroll
            for (int j = 0; j < NJ; j++) {
                unsigned u0, u1;
                asm("mov.b64 {%0, %1}, %2;" : "=r"(u0), "=r"(u1) : "l"(acc[q][j]));
                v[q][2 * j] = __uint_as_float(u0);
                v[q][2 * j + 1] = __uint_as_float(u1);
            }

        if (MODE == 0) {
            // bias + relu
            #pragma unroll
            for (int j = 0; j < NJ; j++) {
                int c = 2 * tx + 64 * j;
                float2 bb = *(const float2*)(bias + c);
                #pragma unroll
                for (int q = 0; q < R; q++) {
                    v[q][2 * j]     = fmaxf(v[q][2 * j] + bb.x, 0.f);
                    v[q][2 * j + 1] = fmaxf(v[q][2 * j + 1] + bb.y, 0.f);
                }
            }
            // LayerNorm per row; each warp owns R full rows
            float s[R], mu[R], rstd[R];
            #pragma unroll
            for (int q = 0; q < R; q++) {
                float t = 0.f;
                #pragma unroll
                for (int jj = 0; jj < 2 * NJ; jj++) t += v[q][jj];
                s[q] = t;
            }
            #pragma unroll
            for (int off = 16; off; off >>= 1)
                #pragma unroll
                for (int q = 0; q < R; q++) s[q] += __shfl_xor_sync(0xffffffffu, s[q], off);
            #pragma unroll
            for (int q = 0; q < R; q++) mu[q] = s[q] * (1.0f / N);
            #pragma unroll
            for (int q = 0; q < R; q++) {
                float t = 0.f;
                #pragma unroll
                for (int jj = 0; jj < 2 * NJ; jj++) {
                    float d = v[q][jj] - mu[q];
                    t += d * d;
                }
                s[q] = t;
            }
            #pragma unroll
            for (int off = 16; off; off >>= 1)
                #pragma unroll
                for (int q = 0; q < R; q++) s[q] += __shfl_xor_sync(0xffffffffu, s[q], off);
            #pragma unroll
            for (int q = 0; q < R; q++) rstd[q] = rsqrtf(s[q] * (1.0f / N) + 1e-5f);

            #pragma unroll
            for (int q = 0; q < R; q++) {
                int row = m0 + ty * R + q;
                if (row < M) {
                    #pragma unroll
                    for (int j = 0; j < NJ; j++) {
                        int c = 2 * tx + 64 * j;
                        float2 gg = *(const float2*)(gamma + c);
                        float2 bt = *(const float2*)(beta + c);
                        float2 o;
                        o.x = (v[q][2 * j] - mu[q]) * rstd[q] * gg.x + bt.x;
                        o.y = (v[q][2 * j + 1] - mu[q]) * rstd[q] * gg.y + bt.y;
                        *(float2*)(out + (size_t)row * N + c) = o;
                    }
                }
            }
        } else {
            #pragma unroll
            for (int q = 0; q < R; q++) {
                int row = m0 + ty * R + q;
                if (row < M) {
                    float di = g_dinv[row];
                    #pragma unroll
                    for (int j = 0; j < NJ; j++) {
                        int c = 2 * tx + 64 * j;
                        float2 o;
                        o.x = v[q][2 * j] * di;
                        o.y = v[q][2 * j + 1] * di;
                        *(float2*)(out + (size_t)row * N + c) = o;
                    }
                }
            }
        }
    }
}

// ---------------- launch ----------------
extern "C" void kernel_launch(void* const* d_in, const int* in_sizes, int n_in,
                              void* d_out, int out_size) {
    const int*   x_ids = (const int*)d_in[0];
    const int*   ei    = (const int*)d_in[1];
    const float* embed = (const float*)d_in[2];
    const float* W1    = (const float*)d_in[3];
    const float* b1    = (const float*)d_in[4];
    const float* g1    = (const float*)d_in[5];
    const float* be1   = (const float*)d_in[6];
    const float* W2    = (const float*)d_in[7];
    const float* b2    = (const float*)d_in[8];
    const float* g2    = (const float*)d_in[9];
    const float* be2   = (const float*)d_in[10];
    float* out = (float*)d_out;

    int n = in_sizes[0];        // 50000
    int E = in_sizes[1] / 2;    // 800000
    const int* src = ei;
    const int* dst = ei + E;

    const int smem1 = (128 * 256 + 64 * 128) * (int)sizeof(float);   // 163840
    const int smem2 = (256 * 128 + 64 * 256) * (int)sizeof(float);   // 196608
    cudaFuncSetAttribute((const void*)k_gemm<128, 256, 0>,
                         cudaFuncAttributeMaxDynamicSharedMemorySize, smem1);
    cudaFuncSetAttribute((const void*)k_gemm<256, 128, 1>,
                         cudaFuncAttributeMaxDynamicSharedMemorySize, smem2);

    int nb = (n + 1023) / 1024;        // 49 blocks -> all resident, spin is safe
    int warps_grid = (n * 32 + 255) / 256;

    // memset nodes (not kernels): zero counters + scan flags
    void* p_cnt = nullptr;  cudaGetSymbolAddress(&p_cnt, g_cnt);
    void* p_flag = nullptr; cudaGetSymbolAddress(&p_flag, g_bflag);
    cudaMemsetAsync(p_cnt, 0, (size_t)n * sizeof(int), 0);
    cudaMemsetAsync(p_flag, 0, 64 * sizeof(int), 0);

    k_hist<<<(E + 255) / 256, 256>>>(dst, E);                  // kernel 0
    k_scan<<<nb, 1024>>>(n, E);                                // kernel 1
    k_fill<<<(E + 255) / 256, 256>>>(src, dst, x_ids, E);      // kernel 2

    // Layer 1: aggregate embeddings (128 cols), then GEMM 128->256 + bias+ReLU+LN
    k_agg0<<<warps_grid, 256>>>(x_ids, (const float4*)embed, n);   // kernel 3 (ncu target)
    k_gemm<128, 256, 0><<<152, 256, smem1>>>(W1, b1, g1, be1, n);  // kernel 4

    // Layer 2: GEMM 256->128 with fused dinv scaling, then aggregate + bias + LN
    k_gemm<256, 128, 1><<<152, 256, smem2>>>(W2, nullptr, nullptr, nullptr, n);  // kernel 5
    k_agg1<<<warps_grid, 256>>>(b2, g2, be2, (float4*)out, n);                   // kernel 6
}

// round 4
// speedup vs baseline: 1.0312x; 1.0312x over previous
#include <cuda_runtime.h>

// Problem constants (shapes fixed by the dataset)
#define NMAX 50000
#define EMAX 800000

// ---------------- scratch (static device allocations; no cudaMalloc) ----------------
__device__ float g_a [(size_t)NMAX * 128];   // aggregated layer-1 input  (ÂX)
__device__ float g_x1[(size_t)NMAX * 256];   // layer-1 output (post ReLU+LN)
__device__ float g_h2[(size_t)NMAX * 128];   // layer-2 transformed, dinv-scaled
__device__ float g_dinv[NMAX];
__device__ int   g_cnt[NMAX];
__device__ int   g_rowptr[NMAX + 1];
__device__ int   g_fill[NMAX];
__device__ int4  g_cols[EMAX];               // {x_id[src], dinv[src] bits, src, 0}
__device__ int   g_bsum[64];
__device__ int   g_bflag[64];                // [0..48] scan flags, [50] hist done counter

// ---------------- fused histogram + exclusive scan (one kernel, 49 resident blocks) ----------------
__global__ void k_histscan(const int* __restrict__ dst, int n, int E) {
    __shared__ int sh[1024];
    __shared__ int s_off;
    int tid = threadIdx.x, b = blockIdx.x;
    int i0 = b * 1024 + tid;

    // 1) histogram phase (grid-strided over edges)
    for (int i = i0; i < E; i += gridDim.x * 1024)
        atomicAdd(&g_cnt[dst[i]], 1);
    __threadfence();
    __syncthreads();
    // 2) grid-wide barrier via done counter (all 49 blocks resident -> no deadlock)
    if (tid == 0) {
        atomicAdd(&g_bflag[50], 1);
        while (((volatile int*)g_bflag)[50] < (int)gridDim.x) { }
    }
    __syncthreads();

    // 3) block-local inclusive scan of counts
    int c = (i0 < n) ? g_cnt[i0] : 0;
    sh[tid] = c;
    __syncthreads();
    for (int off = 1; off < 1024; off <<= 1) {
        int t = (tid >= off) ? sh[tid - off] : 0;
        __syncthreads();
        sh[tid] += t;
        __syncthreads();
    }
    if (tid == 1023) {
        g_bsum[b] = sh[1023];
        __threadfence();
        g_bflag[b] = 1;
    }
    // 4) chained block offsets
    if (tid == 0) {
        int off = 0;
        for (int j = 0; j < b; j++) {
            while (((volatile int*)g_bflag)[j] == 0) { }
            off += ((volatile int*)g_bsum)[j];
        }
        s_off = off;
    }
    __syncthreads();
    if (i0 < n) {
        int incl = sh[tid] + s_off;
        int excl = incl - c;
        g_rowptr[i0] = excl;
        g_fill[i0] = excl;
        g_dinv[i0] = rsqrtf((float)(c + 1));   // +1 self loop
    }
    if (i0 == 0) g_rowptr[n] = E;
}

__global__ void k_fill(const int* __restrict__ src, const int* __restrict__ dst,
                       const int* __restrict__ x_ids, int E) {
    int i = blockIdx.x * blockDim.x + threadIdx.x;
    if (i < E) {
        int s = src[i];
        int d = dst[i];
        int pos = atomicAdd(&g_fill[d], 1);
        g_cols[pos] = make_int4(x_ids[s], __float_as_int(g_dinv[s]), s, 0);
    }
}

// ---------------- layer-1 aggregation straight from the embedding table ----------------
// out[w] = dinv[w] * ( dinv[w]*embed[id_w] + sum_j dinv[j]*embed[id_j] )
// Neighbor records read via uniform (broadcast) loads — no shuffles.
__global__ void __launch_bounds__(256, 6)
k_agg0(const int* __restrict__ x_ids, const float4* __restrict__ embed, int n) {
    int t = blockIdx.x * blockDim.x + threadIdx.x;
    int w = t >> 5, lane = t & 31;
    if (w >= n) return;
    float diw = g_dinv[w];
    int sid = x_ids[w];
    float4 sv = embed[(size_t)sid * 32 + lane];
    float4 acc = make_float4(sv.x * diw, sv.y * diw, sv.z * diw, sv.w * diw);
    int s = g_rowptr[w], e = g_rowptr[w + 1];
    for (int p = s; p < e; p += 4) {
        int mm = e - p;
        float dj[4]; float4 vv[4];
        #pragma unroll
        for (int u = 0; u < 4; u++) {
            bool ok = u < mm;
            int4 c = g_cols[ok ? p + u : p];     // uniform address -> broadcast load
            dj[u] = ok ? __int_as_float(c.y) : 0.f;
            vv[u] = embed[(size_t)c.x * 32 + lane];
        }
        #pragma unroll
        for (int u = 0; u < 4; u++) {
            acc.x = fmaf(vv[u].x, dj[u], acc.x);
            acc.y = fmaf(vv[u].y, dj[u], acc.y);
            acc.z = fmaf(vv[u].z, dj[u], acc.z);
            acc.w = fmaf(vv[u].w, dj[u], acc.w);
        }
    }
    ((float4*)g_a)[(size_t)w * 32 + lane] =
        make_float4(acc.x * diw, acc.y * diw, acc.z * diw, acc.w * diw);
}

// ---------------- layer-2 aggregation + bias + LayerNorm (writes final output) ----------------
__global__ void __launch_bounds__(256, 6)
k_agg1(const float* __restrict__ b, const float* __restrict__ gamma,
       const float* __restrict__ beta, float4* __restrict__ outp, int n) {
    int t = blockIdx.x * blockDim.x + threadIdx.x;
    int w = t >> 5, lane = t & 31;
    if (w >= n) return;
    const float4* xs = (const float4*)g_h2;   // already scaled by dinv[src]
    float4 acc = xs[(size_t)w * 32 + lane];   // self message
    int s = g_rowptr[w], e = g_rowptr[w + 1];
    for (int p = s; p < e; p += 4) {
        int mm = e - p;
        float dj[4]; float4 vv[4];
        #pragma unroll
        for (int u = 0; u < 4; u++) {
            bool ok = u < mm;
            int4 c = g_cols[ok ? p + u : p];     // uniform address -> broadcast load
            dj[u] = ok ? 1.f : 0.f;
            vv[u] = xs[(size_t)c.z * 32 + lane];
        }
        #pragma unroll
        for (int u = 0; u < 4; u++) {
            acc.x = fmaf(vv[u].x, dj[u], acc.x);
            acc.y = fmaf(vv[u].y, dj[u], acc.y);
            acc.z = fmaf(vv[u].z, dj[u], acc.z);
            acc.w = fmaf(vv[u].w, dj[u], acc.w);
        }
    }
    float di = g_dinv[w];
    float4 bb = ((const float4*)b)[lane];
    float4 y = make_float4(acc.x * di + bb.x, acc.y * di + bb.y,
                           acc.z * di + bb.z, acc.w * di + bb.w);
    float s1 = y.x + y.y + y.z + y.w;
    #pragma unroll
    for (int off = 16; off; off >>= 1) s1 += __shfl_xor_sync(0xffffffffu, s1, off);
    float mu = s1 * (1.0f / 128.0f);
    float dx = y.x - mu, dy = y.y - mu, dz = y.z - mu, dw = y.w - mu;
    float sq = dx * dx + dy * dy + dz * dz + dw * dw;
    #pragma unroll
    for (int off = 16; off; off >>= 1) sq += __shfl_xor_sync(0xffffffffu, sq, off);
    float rstd = rsqrtf(sq * (1.0f / 128.0f) + 1e-5f);
    float4 gg = ((const float4*)gamma)[lane];
    float4 bt = ((const float4*)beta)[lane];
    outp[(size_t)w * 32 + lane] = make_float4(dx * rstd * gg.x + bt.x,
                                              dy * rstd * gg.y + bt.y,
                                              dz * rstd * gg.z + bt.z,
                                              dw * rstd * gg.w + bt.w);
}

// ---------------- GEMM: A[M,K] @ W[K,N], W resident in smem, fused epilogues ----------------
// MODE 0: A=g_a  (K=128), out=g_x1 (N=256), epilogue = +bias, ReLU, LayerNorm(gamma,beta)
// MODE 1: A=g_x1 (K=256), out=g_h2 (N=128), epilogue = * dinv[row]
// 256 threads, tile 32 rows x N cols (R=4 rows/warp, 32 acc regs -> no spills).
template<int K, int N, int MODE>
__global__ void __launch_bounds__(256, 1)
k_gemm(const float* __restrict__ W, const float* __restrict__ bias,
       const float* __restrict__ gamma, const float* __restrict__ beta, int M) {
    extern __shared__ float smem[];
    float* Ws = smem;             // K*N floats
    float* Xs = smem + K * N;     // 32*K floats
    constexpr int NJ = N / 64;

    const float* A = (MODE == 0) ? g_a : g_x1;
    float* out = (MODE == 0) ? g_x1 : g_h2;

    int tid = threadIdx.x;
    {
        const float4* Wv = (const float4*)W;
        float4* Wsv = (float4*)Ws;
        for (int idx = tid; idx < K * N / 4; idx += 256) Wsv[idx] = Wv[idx];
    }

    int tx = tid & 31, ty = tid >> 5;

    for (int m0 = blockIdx.x * 32; m0 < M; m0 += gridDim.x * 32) {
        __syncthreads();
        for (int idx = tid; idx < 32 * (K / 4); idx += 256) {
            int r = idx / (K / 4), kk = idx % (K / 4);
            int row = m0 + r;
            float4 v = (row < M) ? ((const float4*)A)[(size_t)row * (K / 4) + kk]
                                 : make_float4(0.f, 0.f, 0.f, 0.f);
            ((float4*)Xs)[idx] = v;
        }
        __syncthreads();

        unsigned long long acc[4][NJ];
        #pragma unroll
        for (int q = 0; q < 4; q++)
            #pragma unroll
            for (int j = 0; j < NJ; j++) acc[q][j] = 0ull;

        const float* xr = Xs + (ty * 4) * K;
        #pragma unroll 4
        for (int k = 0; k < K; k++) {
            unsigned long long w2[NJ];
            #pragma unroll
            for (int j = 0; j < NJ; j++)
                w2[j] = *reinterpret_cast<const unsigned long long*>(Ws + k * N + 2 * tx + 64 * j);
            #pragma unroll
            for (int q = 0; q < 4; q++) {
                unsigned xu = __float_as_uint(xr[q * K + k]);
                unsigned long long x2;
                asm("mov.b64 %0, {%1, %1};" : "=l"(x2) : "r"(xu));
                #pragma unroll
                for (int j = 0; j < NJ; j++)
                    asm("fma.rn.f32x2 %0, %1, %2, %0;" : "+l"(acc[q][j]) : "l"(x2), "l"(w2[j]));
            }
        }

        float v[4][2 * NJ];
        #pragma unroll
        for (int q = 0; q < 4; q++)
            #pragma unroll
            for (int j = 0; j < NJ; j++) {
                unsigned u0, u1;
                asm("mov.b64 {%0, %1}, %2;" : "=r"(u0), "=r"(u1) : "l"(acc[q][j]));
                v[q][2 * j] = __uint_as_float(u0);
                v[q][2 * j + 1] = __uint_as_float(u1);
            }

        if (MODE == 0) {
            #pragma unroll
            for (int j = 0; j < NJ; j++) {
                int c = 2 * tx + 64 * j;
                float2 bb = *(const float2*)(bias + c);
                #pragma unroll
                for (int q = 0; q < 4; q++) {
                    v[q][2 * j]     = fmaxf(v[q][2 * j] + bb.x, 0.f);
                    v[q][2 * j + 1] = fmaxf(v[q][2 * j + 1] + bb.y, 0.f);
                }
            }
            float s[4], mu[4], rstd[4];
            #pragma unroll
            for (int q = 0; q < 4; q++) {
                float t = 0.f;
                #pragma unroll
                for (int jj = 0; jj < 2 * NJ; jj++) t += v[q][jj];
                s[q] = t;
            }
            #pragma unroll
            for (int off = 16; off; off >>= 1)
                #pragma unroll
                for (int q = 0; q < 4; q++) s[q] += __shfl_xor_sync(0xffffffffu, s[q], off);
            #pragma unroll
            for (int q = 0; q < 4; q++) mu[q] = s[q] * (1.0f / N);
            #pragma unroll
            for (int q = 0; q < 4; q++) {
                float t = 0.f;
                #pragma unroll
                for (int jj = 0; jj < 2 * NJ; jj++) {
                    float d = v[q][jj] - mu[q];
                    t += d * d;
                }
                s[q] = t;
            }
            #pragma unroll
            for (int off = 16; off; off >>= 1)
                #pragma unroll
                for (int q = 0; q < 4; q++) s[q] += __shfl_xor_sync(0xffffffffu, s[q], off);
            #pragma unroll
            for (int q = 0; q < 4; q++) rstd[q] = rsqrtf(s[q] * (1.0f / N) + 1e-5f);

            #pragma unroll
            for (int q = 0; q < 4; q++) {
                int row = m0 + ty * 4 + q;
                if (row < M) {
                    #pragma unroll
                    for (int j = 0; j < NJ; j++) {
                        int c = 2 * tx + 64 * j;
                        float2 gg = *(const float2*)(gamma + c);
                        float2 bt = *(const float2*)(beta + c);
                        float2 o;
                        o.x = (v[q][2 * j] - mu[q]) * rstd[q] * gg.x + bt.x;
                        o.y = (v[q][2 * j + 1] - mu[q]) * rstd[q] * gg.y + bt.y;
                        *(float2*)(out + (size_t)row * N + c) = o;
                    }
                }
            }
        } else {
            #pragma unroll
            for (int q = 0; q < 4; q++) {
                int row = m0 + ty * 4 + q;
                if (row < M) {
                    float di = g_dinv[row];
                    #pragma unroll
                    for (int j = 0; j < NJ; j++) {
                        int c = 2 * tx + 64 * j;
                        float2 o;
                        o.x = v[q][2 * j] * di;
                        o.y = v[q][2 * j + 1] * di;
                        *(float2*)(out + (size_t)row * N + c) = o;
                    }
                }
            }
        }
    }
}

// ---------------- launch ----------------
extern "C" void kernel_launch(void* const* d_in, const int* in_sizes, int n_in,
                              void* d_out, int out_size) {
    const int*   x_ids = (const int*)d_in[0];
    const int*   ei    = (const int*)d_in[1];
    const float* embed = (const float*)d_in[2];
    const float* W1    = (const float*)d_in[3];
    const float* b1    = (const float*)d_in[4];
    const float* g1    = (const float*)d_in[5];
    const float* be1   = (const float*)d_in[6];
    const float* W2    = (const float*)d_in[7];
    const float* b2    = (const float*)d_in[8];
    const float* g2    = (const float*)d_in[9];
    const float* be2   = (const float*)d_in[10];
    float* out = (float*)d_out;

    int n = in_sizes[0];        // 50000
    int E = in_sizes[1] / 2;    // 800000
    const int* src = ei;
    const int* dst = ei + E;

    const int smem1 = (128 * 256 + 32 * 128) * (int)sizeof(float);   // 147456
    const int smem2 = (256 * 128 + 32 * 256) * (int)sizeof(float);   // 163840
    cudaFuncSetAttribute((const void*)k_gemm<128, 256, 0>,
                         cudaFuncAttributeMaxDynamicSharedMemorySize, smem1);
    cudaFuncSetAttribute((const void*)k_gemm<256, 128, 1>,
                         cudaFuncAttributeMaxDynamicSharedMemorySize, smem2);

    int nb = (n + 1023) / 1024;        // 49 blocks -> all resident, spins are safe
    int warps_grid = (n * 32 + 255) / 256;

    // memset nodes (not kernel launches): zero counters + flags/done-counter
    void* p_cnt = nullptr;  cudaGetSymbolAddress(&p_cnt, g_cnt);
    void* p_flag = nullptr; cudaGetSymbolAddress(&p_flag, g_bflag);
    cudaMemsetAsync(p_cnt, 0, (size_t)n * sizeof(int), 0);
    cudaMemsetAsync(p_flag, 0, 64 * sizeof(int), 0);

    k_histscan<<<nb, 1024>>>(dst, n, E);                       // kernel 0
    k_fill<<<(E + 255) / 256, 256>>>(src, dst, x_ids, E);      // kernel 1

    // Layer 1: aggregate embeddings (128 cols), then GEMM 128->256 + bias+ReLU+LN
    k_agg0<<<warps_grid, 256>>>(x_ids, (const float4*)embed, n);   // kernel 2
    k_gemm<128, 256, 0><<<152, 256, smem1>>>(W1, b1, g1, be1, n);  // kernel 3 (ncu target)

    // Layer 2: GEMM 256->128 with fused dinv scaling, then aggregate + bias + LN
    k_gemm<256, 128, 1><<<152, 256, smem2>>>(W2, nullptr, nullptr, nullptr, n);  // kernel 4
    k_agg1<<<warps_grid, 256>>>(b2, g2, be2, (float4*)out, n);                   // kernel 5
}

// round 5
// speedup vs baseline: 1.0509x; 1.0192x over previous
#include <cuda_runtime.h>

// Problem constants (shapes fixed by the dataset)
#define NMAX 50000
#define EMAX 800000

// ---------------- scratch (static device allocations; no cudaMalloc) ----------------
__device__ float g_a [(size_t)NMAX * 128];   // aggregated layer-1 input  (ÂX)
__device__ float g_x1[(size_t)NMAX * 256];   // layer-1 output (post ReLU+LN)
__device__ float g_h2[(size_t)NMAX * 128];   // layer-2 transformed, dinv-scaled
__device__ float g_dinv[NMAX];
__device__ int   g_cnt[NMAX];
__device__ int   g_rowptr[NMAX + 1];
__device__ int   g_fill[NMAX];
__device__ int4  g_cols[EMAX];               // {x_id[src], dinv[src] bits, src, 0}
__device__ int   g_bsum[64];
__device__ int   g_bflag[64];                // [0..48] scan flags, [50] hist done counter

// ---------------- fused histogram + exclusive scan (one kernel, 49 resident blocks) ----------------
__global__ void k_histscan(const int* __restrict__ dst, int n, int E) {
    __shared__ int sh[1024];
    __shared__ int s_off;
    int tid = threadIdx.x, b = blockIdx.x;
    int i0 = b * 1024 + tid;

    for (int i = i0; i < E; i += gridDim.x * 1024)
        atomicAdd(&g_cnt[dst[i]], 1);
    __threadfence();
    __syncthreads();
    if (tid == 0) {
        atomicAdd(&g_bflag[50], 1);
        while (((volatile int*)g_bflag)[50] < (int)gridDim.x) { }
    }
    __syncthreads();

    int c = (i0 < n) ? g_cnt[i0] : 0;
    sh[tid] = c;
    __syncthreads();
    for (int off = 1; off < 1024; off <<= 1) {
        int t = (tid >= off) ? sh[tid - off] : 0;
        __syncthreads();
        sh[tid] += t;
        __syncthreads();
    }
    if (tid == 1023) {
        g_bsum[b] = sh[1023];
        __threadfence();
        g_bflag[b] = 1;
    }
    if (tid == 0) {
        int off = 0;
        for (int j = 0; j < b; j++) {
            while (((volatile int*)g_bflag)[j] == 0) { }
            off += ((volatile int*)g_bsum)[j];
        }
        s_off = off;
    }
    __syncthreads();
    if (i0 < n) {
        int incl = sh[tid] + s_off;
        int excl = incl - c;
        g_rowptr[i0] = excl;
        g_fill[i0] = excl;
        g_dinv[i0] = rsqrtf((float)(c + 1));   // +1 self loop
    }
    if (i0 == 0) g_rowptr[n] = E;
}

__global__ void k_fill(const int* __restrict__ src, const int* __restrict__ dst,
                       const int* __restrict__ x_ids, int E) {
    int i = blockIdx.x * blockDim.x + threadIdx.x;
    if (i < E) {
        int s = src[i];
        int d = dst[i];
        int pos = atomicAdd(&g_fill[d], 1);
        g_cols[pos] = make_int4(x_ids[s], __float_as_int(g_dinv[s]), s, 0);
    }
}

// ---------------- layer-1 aggregation straight from the embedding table ----------------
__global__ void __launch_bounds__(256, 6)
k_agg0(const int* __restrict__ x_ids, const float4* __restrict__ embed, int n) {
    int t = blockIdx.x * blockDim.x + threadIdx.x;
    int w = t >> 5, lane = t & 31;
    if (w >= n) return;
    float diw = g_dinv[w];
    int sid = x_ids[w];
    float4 sv = embed[(size_t)sid * 32 + lane];
    float4 acc = make_float4(sv.x * diw, sv.y * diw, sv.z * diw, sv.w * diw);
    int s = g_rowptr[w], e = g_rowptr[w + 1];
    for (int p = s; p < e; p += 4) {
        int mm = e - p;
        float dj[4]; float4 vv[4];
        #pragma unroll
        for (int u = 0; u < 4; u++) {
            bool ok = u < mm;
            int4 c = g_cols[ok ? p + u : p];     // uniform address -> broadcast load
            dj[u] = ok ? __int_as_float(c.y) : 0.f;
            vv[u] = embed[(size_t)c.x * 32 + lane];
        }
        #pragma unroll
        for (int u = 0; u < 4; u++) {
            acc.x = fmaf(vv[u].x, dj[u], acc.x);
            acc.y = fmaf(vv[u].y, dj[u], acc.y);
            acc.z = fmaf(vv[u].z, dj[u], acc.z);
            acc.w = fmaf(vv[u].w, dj[u], acc.w);
        }
    }
    ((float4*)g_a)[(size_t)w * 32 + lane] =
        make_float4(acc.x * diw, acc.y * diw, acc.z * diw, acc.w * diw);
}

// ---------------- layer-2 aggregation + bias + LayerNorm (writes final output) ----------------
__global__ void __launch_bounds__(256, 6)
k_agg1(const float* __restrict__ b, const float* __restrict__ gamma,
       const float* __restrict__ beta, float4* __restrict__ outp, int n) {
    int t = blockIdx.x * blockDim.x + threadIdx.x;
    int w = t >> 5, lane = t & 31;
    if (w >= n) return;
    const float4* xs = (const float4*)g_h2;   // already scaled by dinv[src]
    float4 acc = xs[(size_t)w * 32 + lane];   // self message
    int s = g_rowptr[w], e = g_rowptr[w + 1];
    for (int p = s; p < e; p += 4) {
        int mm = e - p;
        float dj[4]; float4 vv[4];
        #pragma unroll
        for (int u = 0; u < 4; u++) {
            bool ok = u < mm;
            int4 c = g_cols[ok ? p + u : p];
            dj[u] = ok ? 1.f : 0.f;
            vv[u] = xs[(size_t)c.z * 32 + lane];
        }
        #pragma unroll
        for (int u = 0; u < 4; u++) {
            acc.x = fmaf(vv[u].x, dj[u], acc.x);
            acc.y = fmaf(vv[u].y, dj[u], acc.y);
            acc.z = fmaf(vv[u].z, dj[u], acc.z);
            acc.w = fmaf(vv[u].w, dj[u], acc.w);
        }
    }
    float di = g_dinv[w];
    float4 bb = ((const float4*)b)[lane];
    float4 y = make_float4(acc.x * di + bb.x, acc.y * di + bb.y,
                           acc.z * di + bb.z, acc.w * di + bb.w);
    float s1 = y.x + y.y + y.z + y.w;
    #pragma unroll
    for (int off = 16; off; off >>= 1) s1 += __shfl_xor_sync(0xffffffffu, s1, off);
    float mu = s1 * (1.0f / 128.0f);
    float dx = y.x - mu, dy = y.y - mu, dz = y.z - mu, dw = y.w - mu;
    float sq = dx * dx + dy * dy + dz * dz + dw * dw;
    #pragma unroll
    for (int off = 16; off; off >>= 1) sq += __shfl_xor_sync(0xffffffffu, sq, off);
    float rstd = rsqrtf(sq * (1.0f / 128.0f) + 1e-5f);
    float4 gg = ((const float4*)gamma)[lane];
    float4 bt = ((const float4*)beta)[lane];
    outp[(size_t)w * 32 + lane] = make_float4(dx * rstd * gg.x + bt.x,
                                              dy * rstd * gg.y + bt.y,
                                              dz * rstd * gg.z + bt.z,
                                              dw * rstd * gg.w + bt.w);
}

// ---------------- GEMM: A[M,K] @ W[K,N], W resident in smem, fused epilogues ----------------
// 512 threads (16 warps) per block for latency hiding; warp owns R=6 rows; 96-row tiles.
// MODE 0: A=g_a  (K=128), out=g_x1 (N=256), epilogue = +bias, ReLU, LayerNorm(gamma,beta)
// MODE 1: A=g_x1 (K=256), out=g_h2 (N=128), epilogue = * dinv[row]
template<int K, int N, int MODE>
__global__ void __launch_bounds__(512, 1)
k_gemm(const float* __restrict__ W, const float* __restrict__ bias,
       const float* __restrict__ gamma, const float* __restrict__ beta, int M) {
    extern __shared__ float smem[];
    float* Ws = smem;             // K*N floats
    float* Xs = smem + K * N;     // TR*K floats
    constexpr int NJ = N / 64;
    constexpr int R = 6;
    constexpr int TR = 16 * R;    // 96 rows per tile

    const float* A = (MODE == 0) ? g_a : g_x1;
    float* out = (MODE == 0) ? g_x1 : g_h2;

    int tid = threadIdx.x;
    {
        const float4* Wv = (const float4*)W;
        float4* Wsv = (float4*)Ws;
        for (int idx = tid; idx < K * N / 4; idx += 512) Wsv[idx] = Wv[idx];
    }

    int tx = tid & 31, ty = tid >> 5;   // ty in [0,16)

    for (int m0 = blockIdx.x * TR; m0 < M; m0 += gridDim.x * TR) {
        __syncthreads();
        for (int idx = tid; idx < TR * (K / 4); idx += 512) {
            int r = idx / (K / 4), kk = idx % (K / 4);
            int row = m0 + r;
            float4 v = (row < M) ? ((const float4*)A)[(size_t)row * (K / 4) + kk]
                                 : make_float4(0.f, 0.f, 0.f, 0.f);
            ((float4*)Xs)[idx] = v;
        }
        __syncthreads();

        unsigned long long acc[R][NJ];
        #pragma unroll
        for (int q = 0; q < R; q++)
            #pragma unroll
            for (int j = 0; j < NJ; j++) acc[q][j] = 0ull;

        const float* xr = Xs + (ty * R) * K;
        for (int k0 = 0; k0 < K; k0 += 2) {
            float2 xv[R];
            #pragma unroll
            for (int q = 0; q < R; q++)
                xv[q] = *(const float2*)(xr + q * K + k0);
            #pragma unroll
            for (int kk = 0; kk < 2; kk++) {
                unsigned long long w2[NJ];
                #pragma unroll
                for (int j = 0; j < NJ; j++)
                    w2[j] = *reinterpret_cast<const unsigned long long*>(
                        Ws + (k0 + kk) * N + 2 * tx + 64 * j);
                #pragma unroll
                for (int q = 0; q < R; q++) {
                    unsigned xu = __float_as_uint(kk == 0 ? xv[q].x : xv[q].y);
                    unsigned long long x2;
                    asm("mov.b64 %0, {%1, %1};" : "=l"(x2) : "r"(xu));
                    #pragma unroll
                    for (int j = 0; j < NJ; j++)
                        asm("fma.rn.f32x2 %0, %1, %2, %0;"
                            : "+l"(acc[q][j]) : "l"(x2), "l"(w2[j]));
                }
            }
        }

        float v[R][2 * NJ];
        #pragma unroll
        for (int q = 0; q < R; q++)
            #pragma unroll
            for (int j = 0; j < NJ; j++) {
                unsigned u0, u1;
                asm("mov.b64 {%0, %1}, %2;" : "=r"(u0), "=r"(u1) : "l"(acc[q][j]));
                v[q][2 * j] = __uint_as_float(u0);
                v[q][2 * j + 1] = __uint_as_float(u1);
            }

        if (MODE == 0) {
            #pragma unroll
            for (int j = 0; j < NJ; j++) {
                int c = 2 * tx + 64 * j;
                float2 bb = *(const float2*)(bias + c);
                #pragma unroll
                for (int q = 0; q < R; q++) {
                    v[q][2 * j]     = fmaxf(v[q][2 * j] + bb.x, 0.f);
                    v[q][2 * j + 1] = fmaxf(v[q][2 * j + 1] + bb.y, 0.f);
                }
            }
            float s[R], mu[R], rstd[R];
            #pragma unroll
            for (int q = 0; q < R; q++) {
                float t = 0.f;
                #pragma unroll
                for (int jj = 0; jj < 2 * NJ; jj++) t += v[q][jj];
                s[q] = t;
            }
            #pragma unroll
            for (int off = 16; off; off >>= 1)
                #pragma unroll
                for (int q = 0; q < R; q++) s[q] += __shfl_xor_sync(0xffffffffu, s[q], off);
            #pragma unroll
            for (int q = 0; q < R; q++) mu[q] = s[q] * (1.0f / N);
            #pragma unroll
            for (int q = 0; q < R; q++) {
                float t = 0.f;
                #pragma unroll
                for (int jj = 0; jj < 2 * NJ; jj++) {
                    float d = v[q][jj] - mu[q];
                    t += d * d;
                }
                s[q] = t;
            }
            #pragma unroll
            for (int off = 16; off; off >>= 1)
                #pragma unroll
                for (int q = 0; q < R; q++) s[q] += __shfl_xor_sync(0xffffffffu, s[q], off);
            #pragma unroll
            for (int q = 0; q < R; q++) rstd[q] = rsqrtf(s[q] * (1.0f / N) + 1e-5f);

            #pragma unroll
            for (int q = 0; q < R; q++) {
                int row = m0 + ty * R + q;
                if (row < M) {
                    #pragma unroll
                    for (int j = 0; j < NJ; j++) {
                        int c = 2 * tx + 64 * j;
                        float2 gg = *(const float2*)(gamma + c);
                        float2 bt = *(const float2*)(beta + c);
                        float2 o;
                        o.x = (v[q][2 * j] - mu[q]) * rstd[q] * gg.x + bt.x;
                        o.y = (v[q][2 * j + 1] - mu[q]) * rstd[q] * gg.y + bt.y;
                        *(float2*)(out + (size_t)row * N + c) = o;
                    }
                }
            }
        } else {
            #pragma unroll
            for (int q = 0; q < R; q++) {
                int row = m0 + ty * R + q;
                if (row < M) {
                    float di = g_dinv[row];
                    #pragma unroll
                    for (int j = 0; j < NJ; j++) {
                        int c = 2 * tx + 64 * j;
                        float2 o;
                        o.x = v[q][2 * j] * di;
                        o.y = v[q][2 * j + 1] * di;
                        *(float2*)(out + (size_t)row * N + c) = o;
                    }
                }
            }
        }
    }
}

// ---------------- launch ----------------
extern "C" void kernel_launch(void* const* d_in, const int* in_sizes, int n_in,
                              void* d_out, int out_size) {
    const int*   x_ids = (const int*)d_in[0];
    const int*   ei    = (const int*)d_in[1];
    const float* embed = (const float*)d_in[2];
    const float* W1    = (const float*)d_in[3];
    const float* b1    = (const float*)d_in[4];
    const float* g1    = (const float*)d_in[5];
    const float* be1   = (const float*)d_in[6];
    const float* W2    = (const float*)d_in[7];
    const float* b2    = (const float*)d_in[8];
    const float* g2    = (const float*)d_in[9];
    const float* be2   = (const float*)d_in[10];
    float* out = (float*)d_out;

    int n = in_sizes[0];        // 50000
    int E = in_sizes[1] / 2;    // 800000
    const int* src = ei;
    const int* dst = ei + E;

    const int smem1 = (128 * 256 + 96 * 128) * (int)sizeof(float);   // 180224
    const int smem2 = (256 * 128 + 96 * 256) * (int)sizeof(float);   // 229376
    cudaFuncSetAttribute((const void*)k_gemm<128, 256, 0>,
                         cudaFuncAttributeMaxDynamicSharedMemorySize, smem1);
    cudaFuncSetAttribute((const void*)k_gemm<256, 128, 1>,
                         cudaFuncAttributeMaxDynamicSharedMemorySize, smem2);

    int nb = (n + 1023) / 1024;        // 49 blocks -> all resident, spins are safe
    int warps_grid = (n * 32 + 255) / 256;

    void* p_cnt = nullptr;  cudaGetSymbolAddress(&p_cnt, g_cnt);
    void* p_flag = nullptr; cudaGetSymbolAddress(&p_flag, g_bflag);
    cudaMemsetAsync(p_cnt, 0, (size_t)n * sizeof(int), 0);
    cudaMemsetAsync(p_flag, 0, 64 * sizeof(int), 0);

    k_histscan<<<nb, 1024>>>(dst, n, E);                       // kernel 0
    k_fill<<<(E + 255) / 256, 256>>>(src, dst, x_ids, E);      // kernel 1

    k_agg0<<<warps_grid, 256>>>(x_ids, (const float4*)embed, n);   // kernel 2
    k_gemm<128, 256, 0><<<152, 512, smem1>>>(W1, b1, g1, be1, n);  // kernel 3 (ncu target)

    k_gemm<256, 128, 1><<<152, 512, smem2>>>(W2, nullptr, nullptr, nullptr, n);  // kernel 4
    k_agg1<<<warps_grid, 256>>>(b2, g2, be2, (float4*)out, n);                   // kernel 5
}

// round 7
// speedup vs baseline: 1.4198x; 1.3510x over previous
#include <cuda_runtime.h>
#include <cuda_bf16.h>
#include <cstdint>

#define NMAX 50000
#define EMAX 800000

// ---------------- scratch ----------------
__device__ float g_a [(size_t)NMAX * 128];
__device__ __nv_bfloat16 g_x1h[(size_t)NMAX * 256];   // layer-1 output, bf16 hi
__device__ __nv_bfloat16 g_x1l[(size_t)NMAX * 256];   // layer-1 output, bf16 lo
__device__ float g_h2[(size_t)NMAX * 128];
__device__ float g_dinv[NMAX];
__device__ int   g_cnt[NMAX];
__device__ int   g_rowptr[NMAX + 1];
__device__ int   g_fill[NMAX];
__device__ int4  g_cols[EMAX];
__device__ int   g_bsum[64];
__device__ int   g_bflag[64];

// ---------------- CSR build ----------------
__global__ void k_histscan(const int* __restrict__ dst, int n, int E) {
    __shared__ int sh[1024];
    __shared__ int s_off;
    int tid = threadIdx.x, b = blockIdx.x;
    int i0 = b * 1024 + tid;

    for (int i = i0; i < E; i += gridDim.x * 1024)
        atomicAdd(&g_cnt[dst[i]], 1);
    __threadfence();
    __syncthreads();
    if (tid == 0) {
        atomicAdd(&g_bflag[50], 1);
        while (((volatile int*)g_bflag)[50] < (int)gridDim.x) { }
    }
    __syncthreads();

    int c = (i0 < n) ? g_cnt[i0] : 0;
    sh[tid] = c;
    __syncthreads();
    for (int off = 1; off < 1024; off <<= 1) {
        int t = (tid >= off) ? sh[tid - off] : 0;
        __syncthreads();
        sh[tid] += t;
        __syncthreads();
    }
    if (tid == 1023) {
        g_bsum[b] = sh[1023];
        __threadfence();
        g_bflag[b] = 1;
    }
    if (tid == 0) {
        int off = 0;
        for (int j = 0; j < b; j++) {
            while (((volatile int*)g_bflag)[j] == 0) { }
            off += ((volatile int*)g_bsum)[j];
        }
        s_off = off;
    }
    __syncthreads();
    if (i0 < n) {
        int incl = sh[tid] + s_off;
        int excl = incl - c;
        g_rowptr[i0] = excl;
        g_fill[i0] = excl;
        g_dinv[i0] = rsqrtf((float)(c + 1));
    }
    if (i0 == 0) g_rowptr[n] = E;
}

__global__ void k_fill(const int* __restrict__ src, const int* __restrict__ dst,
                       const int* __restrict__ x_ids, int E) {
    int i = blockIdx.x * blockDim.x + threadIdx.x;
    if (i < E) {
        int s = src[i];
        int d = dst[i];
        int pos = atomicAdd(&g_fill[d], 1);
        g_cols[pos] = make_int4(x_ids[s], __float_as_int(g_dinv[s]), s, 0);
    }
}

// ---------------- layer-1 aggregation ----------------
__global__ void __launch_bounds__(256, 6)
k_agg0(const int* __restrict__ x_ids, const float4* __restrict__ embed, int n) {
    int t = blockIdx.x * blockDim.x + threadIdx.x;
    int w = t >> 5, lane = t & 31;
    if (w >= n) return;
    float diw = g_dinv[w];
    int sid = x_ids[w];
    float4 sv = embed[(size_t)sid * 32 + lane];
    float4 acc = make_float4(sv.x * diw, sv.y * diw, sv.z * diw, sv.w * diw);
    int s = g_rowptr[w], e = g_rowptr[w + 1];
    for (int p = s; p < e; p += 4) {
        int mm = e - p;
        float dj[4]; float4 vv[4];
        #pragma unroll
        for (int u = 0; u < 4; u++) {
            bool ok = u < mm;
            int4 c = g_cols[ok ? p + u : p];
            dj[u] = ok ? __int_as_float(c.y) : 0.f;
            vv[u] = embed[(size_t)c.x * 32 + lane];
        }
        #pragma unroll
        for (int u = 0; u < 4; u++) {
            acc.x = fmaf(vv[u].x, dj[u], acc.x);
            acc.y = fmaf(vv[u].y, dj[u], acc.y);
            acc.z = fmaf(vv[u].z, dj[u], acc.z);
            acc.w = fmaf(vv[u].w, dj[u], acc.w);
        }
    }
    ((float4*)g_a)[(size_t)w * 32 + lane] =
        make_float4(acc.x * diw, acc.y * diw, acc.z * diw, acc.w * diw);
}

// ---------------- layer-2 aggregation + bias + LayerNorm ----------------
__global__ void __launch_bounds__(256, 6)
k_agg1(const float* __restrict__ b, const float* __restrict__ gamma,
       const float* __restrict__ beta, float4* __restrict__ outp, int n) {
    int t = blockIdx.x * blockDim.x + threadIdx.x;
    int w = t >> 5, lane = t & 31;
    if (w >= n) return;
    const float4* xs = (const float4*)g_h2;
    float4 acc = xs[(size_t)w * 32 + lane];
    int s = g_rowptr[w], e = g_rowptr[w + 1];
    for (int p = s; p < e; p += 4) {
        int mm = e - p;
        float dj[4]; float4 vv[4];
        #pragma unroll
        for (int u = 0; u < 4; u++) {
            bool ok = u < mm;
            int4 c = g_cols[ok ? p + u : p];
            dj[u] = ok ? 1.f : 0.f;
            vv[u] = xs[(size_t)c.z * 32 + lane];
        }
        #pragma unroll
        for (int u = 0; u < 4; u++) {
            acc.x = fmaf(vv[u].x, dj[u], acc.x);
            acc.y = fmaf(vv[u].y, dj[u], acc.y);
            acc.z = fmaf(vv[u].z, dj[u], acc.z);
            acc.w = fmaf(vv[u].w, dj[u], acc.w);
        }
    }
    float di = g_dinv[w];
    float4 bb = ((const float4*)b)[lane];
    float4 y = make_float4(acc.x * di + bb.x, acc.y * di + bb.y,
                           acc.z * di + bb.z, acc.w * di + bb.w);
    float s1 = y.x + y.y + y.z + y.w;
    #pragma unroll
    for (int off = 16; off; off >>= 1) s1 += __shfl_xor_sync(0xffffffffu, s1, off);
    float mu = s1 * (1.0f / 128.0f);
    float dx = y.x - mu, dy = y.y - mu, dz = y.z - mu, dw = y.w - mu;
    float sq = dx * dx + dy * dy + dz * dz + dw * dw;
    #pragma unroll
    for (int off = 16; off; off >>= 1) sq += __shfl_xor_sync(0xffffffffu, sq, off);
    float rstd = rsqrtf(sq * (1.0f / 128.0f) + 1e-5f);
    float4 gg = ((const float4*)gamma)[lane];
    float4 bt = ((const float4*)beta)[lane];
    outp[(size_t)w * 32 + lane] = make_float4(dx * rstd * gg.x + bt.x,
                                              dy * rstd * gg.y + bt.y,
                                              dz * rstd * gg.z + bt.z,
                                              dw * rstd * gg.w + bt.w);
}

// ================= HMMA GEMM (mma.sync m16n8k16 bf16, 3-term split) =================

__device__ __forceinline__ void mma16816(float& c0, float& c1, float& c2, float& c3,
                                         uint32_t a0, uint32_t a1, uint32_t a2, uint32_t a3,
                                         uint32_t b0, uint32_t b1) {
    asm volatile(
        "mma.sync.aligned.m16n8k16.row.col.f32.bf16.bf16.f32 "
        "{%0,%1,%2,%3}, {%4,%5,%6,%7}, {%8,%9}, {%0,%1,%2,%3};"
        : "+f"(c0), "+f"(c1), "+f"(c2), "+f"(c3)
        : "r"(a0), "r"(a1), "r"(a2), "r"(a3), "r"(b0), "r"(b1));
}
__device__ __forceinline__ uint32_t bf2pack(float x, float y) {
    __nv_bfloat16 h0 = __float2bfloat16(x), h1 = __float2bfloat16(y);
    return (uint32_t)__bfloat16_as_ushort(h0) | ((uint32_t)__bfloat16_as_ushort(h1) << 16);
}

// D[M,N] = A[M,K] @ W[K,N]; 3-term bf16 split HMMA; W resident in smem.
// MODE 0: A = g_a fp32 (K=128), out = g_x1h/g_x1l (N=256), epilogue bias+ReLU+LN
// MODE 1: A = g_x1h/g_x1l bf16 (K=256), out = g_h2 fp32 (N=128), epilogue *dinv
template<int K, int N, int MODE>
__global__ void __launch_bounds__(256, 1)
k_gemm_mma(const float* __restrict__ W, const float* __restrict__ bias,
           const float* __restrict__ gamma, const float* __restrict__ beta, int M)
{
    constexpr int ST = K + 8;                    // padded stride (bf16 elems)
    constexpr int NQ = N / 64;                   // n-tiles per quarter... (N/4)/8 = N/32
    constexpr int NT = N / 32;                   // n-tiles (8 cols) per warp quarter
    extern __shared__ char sm[];
    __nv_bfloat16* Wh = (__nv_bfloat16*)sm;
    __nv_bfloat16* Wl = Wh + (size_t)N * ST;
    __nv_bfloat16* Ah = Wl + (size_t)N * ST;
    __nv_bfloat16* Al = Ah + (size_t)64 * ST;
    float* s_sum = (float*)(Al + (size_t)64 * ST);
    float* s_sq  = s_sum + 64 * 4;
    (void)NQ;

    int tid = threadIdx.x, lane = tid & 31, wid = tid >> 5;
    int wr = wid & 1;          // row group (32 rows)
    int wc = wid >> 1;         // col quarter (N/4 cols)
    int g = lane >> 2, t = lane & 3;

    // ---- W [k][n] fp32 -> Wh/Wl [n][k] bf16 ----
    for (int i = tid; i < K * N; i += 256) {
        int k = i / N, n = i % N;
        float w = W[i];
        __nv_bfloat16 h = __float2bfloat16(w);
        Wh[(size_t)n * ST + k] = h;
        Wl[(size_t)n * ST + k] = __float2bfloat16(w - __bfloat162float(h));
    }

    for (int m0 = blockIdx.x * 64; m0 < M; m0 += gridDim.x * 64) {
        __syncthreads();
        // ---- load A tile (64 x K) into Ah/Al ----
        if (MODE == 0) {
            for (int i = tid; i < 64 * (K / 4); i += 256) {
                int r = i / (K / 4), c4 = (i % (K / 4)) * 4;
                int row = m0 + r;
                float4 v = (row < M) ? *(const float4*)(g_a + (size_t)row * K + c4)
                                     : make_float4(0.f, 0.f, 0.f, 0.f);
                __nv_bfloat16 h0 = __float2bfloat16(v.x), h1 = __float2bfloat16(v.y);
                __nv_bfloat16 h2 = __float2bfloat16(v.z), h3 = __float2bfloat16(v.w);
                uint2 hp, lp;
                hp.x = (uint32_t)__bfloat16_as_ushort(h0) | ((uint32_t)__bfloat16_as_ushort(h1) << 16);
                hp.y = (uint32_t)__bfloat16_as_ushort(h2) | ((uint32_t)__bfloat16_as_ushort(h3) << 16);
                lp.x = bf2pack(v.x - __bfloat162float(h0), v.y - __bfloat162float(h1));
                lp.y = bf2pack(v.z - __bfloat162float(h2), v.w - __bfloat162float(h3));
                *(uint2*)(Ah + (size_t)r * ST + c4) = hp;
                *(uint2*)(Al + (size_t)r * ST + c4) = lp;
            }
        } else {
            for (int i = tid; i < 64 * (K / 8); i += 256) {
                int r = i / (K / 8), c8 = (i % (K / 8)) * 8;
                int row = m0 + r;
                uint4 vh = make_uint4(0, 0, 0, 0), vl = make_uint4(0, 0, 0, 0);
                if (row < M) {
                    vh = *(const uint4*)(g_x1h + (size_t)row * K + c8);
                    vl = *(const uint4*)(g_x1l + (size_t)row * K + c8);
                }
                *(uint4*)(Ah + (size_t)r * ST + c8) = vh;
                *(uint4*)(Al + (size_t)r * ST + c8) = vl;
            }
        }
        __syncthreads();

        float acc[2][NT][4];
        #pragma unroll
        for (int rt = 0; rt < 2; rt++)
            #pragma unroll
            for (int nt = 0; nt < NT; nt++)
                #pragma unroll
                for (int q = 0; q < 4; q++) acc[rt][nt][q] = 0.f;

        #pragma unroll
        for (int kt = 0; kt < K / 16; kt++) {
            int kc = kt * 16 + 2 * t;
            uint32_t ah[2][4], al[2][4];
            #pragma unroll
            for (int rt = 0; rt < 2; rt++) {
                int R = wr * 32 + rt * 16 + g;
                ah[rt][0] = *(const uint32_t*)(Ah + (size_t)R * ST + kc);
                ah[rt][1] = *(const uint32_t*)(Ah + (size_t)(R + 8) * ST + kc);
                ah[rt][2] = *(const uint32_t*)(Ah + (size_t)R * ST + kc + 8);
                ah[rt][3] = *(const uint32_t*)(Ah + (size_t)(R + 8) * ST + kc + 8);
                al[rt][0] = *(const uint32_t*)(Al + (size_t)R * ST + kc);
                al[rt][1] = *(const uint32_t*)(Al + (size_t)(R + 8) * ST + kc);
                al[rt][2] = *(const uint32_t*)(Al + (size_t)R * ST + kc + 8);
                al[rt][3] = *(const uint32_t*)(Al + (size_t)(R + 8) * ST + kc + 8);
            }
            #pragma unroll
            for (int nt = 0; nt < NT; nt++) {
                int n = wc * (N / 4) + nt * 8 + g;
                uint32_t b0h = *(const uint32_t*)(Wh + (size_t)n * ST + kc);
                uint32_t b1h = *(const uint32_t*)(Wh + (size_t)n * ST + kc + 8);
                uint32_t b0l = *(const uint32_t*)(Wl + (size_t)n * ST + kc);
                uint32_t b1l = *(const uint32_t*)(Wl + (size_t)n * ST + kc + 8);
                #pragma unroll
                for (int rt = 0; rt < 2; rt++) {
                    float* c = acc[rt][nt];
                    mma16816(c[0], c[1], c[2], c[3],
                             ah[rt][0], ah[rt][1], ah[rt][2], ah[rt][3], b0h, b1h);
                    mma16816(c[0], c[1], c[2], c[3],
                             al[rt][0], al[rt][1], al[rt][2], al[rt][3], b0h, b1h);
                    mma16816(c[0], c[1], c[2], c[3],
                             ah[rt][0], ah[rt][1], ah[rt][2], ah[rt][3], b0l, b1l);
                }
            }
        }

        if (MODE == 0) {
            // ---- bias + ReLU, per-row partial sums ----
            #pragma unroll
            for (int rt = 0; rt < 2; rt++) {
                float s0 = 0.f, s1 = 0.f, q0 = 0.f, q1 = 0.f;
                #pragma unroll
                for (int nt = 0; nt < NT; nt++) {
                    int c0 = wc * (N / 4) + nt * 8 + 2 * t;
                    float b0 = bias[c0], b1 = bias[c0 + 1];
                    float* c = acc[rt][nt];
                    c[0] = fmaxf(c[0] + b0, 0.f);
                    c[1] = fmaxf(c[1] + b1, 0.f);
                    c[2] = fmaxf(c[2] + b0, 0.f);
                    c[3] = fmaxf(c[3] + b1, 0.f);
                    s0 += c[0] + c[1]; q0 += c[0] * c[0] + c[1] * c[1];
                    s1 += c[2] + c[3]; q1 += c[2] * c[2] + c[3] * c[3];
                }
                #pragma unroll
                for (int off = 1; off <= 2; off <<= 1) {
                    s0 += __shfl_xor_sync(0xffffffffu, s0, off);
                    q0 += __shfl_xor_sync(0xffffffffu, q0, off);
                    s1 += __shfl_xor_sync(0xffffffffu, s1, off);
                    q1 += __shfl_xor_sync(0xffffffffu, q1, off);
                }
                if (t == 0) {
                    int lr = wr * 32 + rt * 16 + g;
                    s_sum[lr * 4 + wc] = s0; s_sq[lr * 4 + wc] = q0;
                    s_sum[(lr + 8) * 4 + wc] = s1; s_sq[(lr + 8) * 4 + wc] = q1;
                }
            }
            __syncthreads();
            #pragma unroll
            for (int rt = 0; rt < 2; rt++) {
                int lr0 = wr * 32 + rt * 16 + g;
                float4 fs0 = ((const float4*)s_sum)[lr0];
                float4 fq0 = ((const float4*)s_sq)[lr0];
                float4 fs1 = ((const float4*)s_sum)[lr0 + 8];
                float4 fq1 = ((const float4*)s_sq)[lr0 + 8];
                float mu0 = (fs0.x + fs0.y + fs0.z + fs0.w) * (1.f / 256.f);
                float mu1 = (fs1.x + fs1.y + fs1.z + fs1.w) * (1.f / 256.f);
                float v0 = (fq0.x + fq0.y + fq0.z + fq0.w) * (1.f / 256.f) - mu0 * mu0;
                float v1 = (fq1.x + fq1.y + fq1.z + fq1.w) * (1.f / 256.f) - mu1 * mu1;
                float rs0 = rsqrtf(v0 + 1e-5f), rs1 = rsqrtf(v1 + 1e-5f);
                int row0 = m0 + lr0, row1 = row0 + 8;
                #pragma unroll
                for (int nt = 0; nt < NT; nt++) {
                    int c0 = wc * (N / 4) + nt * 8 + 2 * t;
                    float ga0 = gamma[c0], ga1 = gamma[c0 + 1];
                    float be0 = beta[c0], be1 = beta[c0 + 1];
                    float* c = acc[rt][nt];
                    if (row0 < M) {
                        float o0 = (c[0] - mu0) * rs0 * ga0 + be0;
                        float o1 = (c[1] - mu0) * rs0 * ga1 + be1;
                        __nv_bfloat16 h0 = __float2bfloat16(o0), h1 = __float2bfloat16(o1);
                        uint32_t hp = (uint32_t)__bfloat16_as_ushort(h0)
                                    | ((uint32_t)__bfloat16_as_ushort(h1) << 16);
                        uint32_t lp = bf2pack(o0 - __bfloat162float(h0), o1 - __bfloat162float(h1));
                        *(uint32_t*)(g_x1h + (size_t)row0 * N + c0) = hp;
                        *(uint32_t*)(g_x1l + (size_t)row0 * N + c0) = lp;
                    }
                    if (row1 < M) {
                        float o2 = (c[2] - mu1) * rs1 * ga0 + be0;
                        float o3 = (c[3] - mu1) * rs1 * ga1 + be1;
                        __nv_bfloat16 h2 = __float2bfloat16(o2), h3 = __float2bfloat16(o3);
                        uint32_t hp = (uint32_t)__bfloat16_as_ushort(h2)
                                    | ((uint32_t)__bfloat16_as_ushort(h3) << 16);
                        uint32_t lp = bf2pack(o2 - __bfloat162float(h2), o3 - __bfloat162float(h3));
                        *(uint32_t*)(g_x1h + (size_t)row1 * N + c0) = hp;
                        *(uint32_t*)(g_x1l + (size_t)row1 * N + c0) = lp;
                    }
                }
            }
        } else {
            #pragma unroll
            for (int rt = 0; rt < 2; rt++) {
                int lr0 = wr * 32 + rt * 16 + g;
                int row0 = m0 + lr0, row1 = row0 + 8;
                float d0 = (row0 < M) ? g_dinv[row0] : 0.f;
                float d1 = (row1 < M) ? g_dinv[row1] : 0.f;
                #pragma unroll
                for (int nt = 0; nt < NT; nt++) {
                    int c0 = wc * (N / 4) + nt * 8 + 2 * t;
                    float* c = acc[rt][nt];
                    if (row0 < M)
                        *(float2*)(g_h2 + (size_t)row0 * N + c0) =
                            make_float2(c[0] * d0, c[1] * d0);
                    if (row1 < M)
                        *(float2*)(g_h2 + (size_t)row1 * N + c0) =
                            make_float2(c[2] * d1, c[3] * d1);
                }
            }
        }
    }
}

// ---------------- launch ----------------
extern "C" void kernel_launch(void* const* d_in, const int* in_sizes, int n_in,
                              void* d_out, int out_size) {
    const int*   x_ids = (const int*)d_in[0];
    const int*   ei    = (const int*)d_in[1];
    const float* embed = (const float*)d_in[2];
    const float* W1    = (const float*)d_in[3];
    const float* b1    = (const float*)d_in[4];
    const float* g1    = (const float*)d_in[5];
    const float* be1   = (const float*)d_in[6];
    const float* W2    = (const float*)d_in[7];
    const float* b2    = (const float*)d_in[8];
    const float* g2    = (const float*)d_in[9];
    const float* be2   = (const float*)d_in[10];
    float* out = (float*)d_out;

    int n = in_sizes[0];        // 50000
    int E = in_sizes[1] / 2;    // 800000
    const int* src = ei;
    const int* dst = ei + E;

    // smem sizes: (2*N*ST + 2*64*ST) bf16 + 2*256 floats
    const int smem1 = (2 * 256 * 136 + 2 * 64 * 136) * 2 + 2 * 256 * 4;   // 176128
    const int smem2 = (2 * 128 * 264 + 2 * 64 * 264) * 2 + 2 * 256 * 4;   // 204800
    cudaFuncSetAttribute((const void*)k_gemm_mma<128, 256, 0>,
                         cudaFuncAttributeMaxDynamicSharedMemorySize, smem1);
    cudaFuncSetAttribute((const void*)k_gemm_mma<256, 128, 1>,
                         cudaFuncAttributeMaxDynamicSharedMemorySize, smem2);

    int nb = (n + 1023) / 1024;
    int warps_grid = (n * 32 + 255) / 256;

    void* p_cnt = nullptr;  cudaGetSymbolAddress(&p_cnt, g_cnt);
    void* p_flag = nullptr; cudaGetSymbolAddress(&p_flag, g_bflag);
    cudaMemsetAsync(p_cnt, 0, (size_t)n * sizeof(int), 0);
    cudaMemsetAsync(p_flag, 0, 64 * sizeof(int), 0);

    k_histscan<<<nb, 1024>>>(dst, n, E);                       // kernel 0
    k_fill<<<(E + 255) / 256, 256>>>(src, dst, x_ids, E);      // kernel 1

    k_agg0<<<warps_grid, 256>>>(x_ids, (const float4*)embed, n);        // kernel 2
    k_gemm_mma<128, 256, 0><<<152, 256, smem1>>>(W1, b1, g1, be1, n);   // kernel 3 (ncu)

    k_gemm_mma<256, 128, 1><<<152, 256, smem2>>>(W2, nullptr, nullptr, nullptr, n);  // kernel 4
    k_agg1<<<warps_grid, 256>>>(b2, g2, be2, (float4*)out, n);                       // kernel 5
}

// round 8
// speedup vs baseline: 1.4726x; 1.0372x over previous
#include <cuda_runtime.h>
#include <cuda_bf16.h>
#include <cstdint>

#define NMAX 50000
#define EMAX 800000

// ---------------- scratch ----------------
__device__ float g_a [(size_t)NMAX * 128];
__device__ __nv_bfloat16 g_x1h[(size_t)NMAX * 256];   // layer-1 output, bf16 hi
__device__ __nv_bfloat16 g_x1l[(size_t)NMAX * 256];   // layer-1 output, bf16 lo
__device__ float g_h2[(size_t)NMAX * 128];
__device__ float g_dinv[NMAX];
__device__ int   g_cnt[NMAX];
__device__ int   g_rowptr[NMAX + 1];
__device__ int   g_fill[NMAX];
__device__ int4  g_cols[EMAX];
__device__ int   g_bsum[64];
__device__ int   g_bflag[64];

// ---------------- CSR build ----------------
__global__ void k_histscan(const int* __restrict__ dst, int n, int E) {
    __shared__ int sh[1024];
    __shared__ int s_off;
    int tid = threadIdx.x, b = blockIdx.x;
    int i0 = b * 1024 + tid;

    for (int i = i0; i < E; i += gridDim.x * 1024)
        atomicAdd(&g_cnt[dst[i]], 1);
    __threadfence();
    __syncthreads();
    if (tid == 0) {
        atomicAdd(&g_bflag[50], 1);
        while (((volatile int*)g_bflag)[50] < (int)gridDim.x) { }
    }
    __syncthreads();

    int c = (i0 < n) ? g_cnt[i0] : 0;
    sh[tid] = c;
    __syncthreads();
    for (int off = 1; off < 1024; off <<= 1) {
        int t = (tid >= off) ? sh[tid - off] : 0;
        __syncthreads();
        sh[tid] += t;
        __syncthreads();
    }
    if (tid == 1023) {
        g_bsum[b] = sh[1023];
        __threadfence();
        g_bflag[b] = 1;
    }
    if (tid == 0) {
        int off = 0;
        for (int j = 0; j < b; j++) {
            while (((volatile int*)g_bflag)[j] == 0) { }
            off += ((volatile int*)g_bsum)[j];
        }
        s_off = off;
    }
    __syncthreads();
    if (i0 < n) {
        int incl = sh[tid] + s_off;
        int excl = incl - c;
        g_rowptr[i0] = excl;
        g_fill[i0] = excl;
        g_dinv[i0] = rsqrtf((float)(c + 1));
    }
    if (i0 == 0) g_rowptr[n] = E;
}

__global__ void k_fill(const int* __restrict__ src, const int* __restrict__ dst,
                       const int* __restrict__ x_ids, int E) {
    int i = blockIdx.x * blockDim.x + threadIdx.x;
    if (i < E) {
        int s = src[i];
        int d = dst[i];
        int pos = atomicAdd(&g_fill[d], 1);
        g_cols[pos] = make_int4(x_ids[s], __float_as_int(g_dinv[s]), s, 0);
    }
}

// ---------------- layer-1 aggregation ----------------
__global__ void __launch_bounds__(256, 6)
k_agg0(const int* __restrict__ x_ids, const float4* __restrict__ embed, int n) {
    int t = blockIdx.x * blockDim.x + threadIdx.x;
    int w = t >> 5, lane = t & 31;
    if (w >= n) return;
    float diw = g_dinv[w];
    int sid = x_ids[w];
    float4 sv = embed[(size_t)sid * 32 + lane];
    float4 acc = make_float4(sv.x * diw, sv.y * diw, sv.z * diw, sv.w * diw);
    int s = g_rowptr[w], e = g_rowptr[w + 1];
    for (int p = s; p < e; p += 4) {
        int mm = e - p;
        float dj[4]; float4 vv[4];
        #pragma unroll
        for (int u = 0; u < 4; u++) {
            bool ok = u < mm;
            int4 c = g_cols[ok ? p + u : p];
            dj[u] = ok ? __int_as_float(c.y) : 0.f;
            vv[u] = embed[(size_t)c.x * 32 + lane];
        }
        #pragma unroll
        for (int u = 0; u < 4; u++) {
            acc.x = fmaf(vv[u].x, dj[u], acc.x);
            acc.y = fmaf(vv[u].y, dj[u], acc.y);
            acc.z = fmaf(vv[u].z, dj[u], acc.z);
            acc.w = fmaf(vv[u].w, dj[u], acc.w);
        }
    }
    ((float4*)g_a)[(size_t)w * 32 + lane] =
        make_float4(acc.x * diw, acc.y * diw, acc.z * diw, acc.w * diw);
}

// ---------------- layer-2 aggregation + bias + LayerNorm ----------------
__global__ void __launch_bounds__(256, 6)
k_agg1(const float* __restrict__ b, const float* __restrict__ gamma,
       const float* __restrict__ beta, float4* __restrict__ outp, int n) {
    int t = blockIdx.x * blockDim.x + threadIdx.x;
    int w = t >> 5, lane = t & 31;
    if (w >= n) return;
    const float4* xs = (const float4*)g_h2;
    float4 acc = xs[(size_t)w * 32 + lane];
    int s = g_rowptr[w], e = g_rowptr[w + 1];
    for (int p = s; p < e; p += 4) {
        int mm = e - p;
        float dj[4]; float4 vv[4];
        #pragma unroll
        for (int u = 0; u < 4; u++) {
            bool ok = u < mm;
            int4 c = g_cols[ok ? p + u : p];
            dj[u] = ok ? 1.f : 0.f;
            vv[u] = xs[(size_t)c.z * 32 + lane];
        }
        #pragma unroll
        for (int u = 0; u < 4; u++) {
            acc.x = fmaf(vv[u].x, dj[u], acc.x);
            acc.y = fmaf(vv[u].y, dj[u], acc.y);
            acc.z = fmaf(vv[u].z, dj[u], acc.z);
            acc.w = fmaf(vv[u].w, dj[u], acc.w);
        }
    }
    float di = g_dinv[w];
    float4 bb = ((const float4*)b)[lane];
    float4 y = make_float4(acc.x * di + bb.x, acc.y * di + bb.y,
                           acc.z * di + bb.z, acc.w * di + bb.w);
    float s1 = y.x + y.y + y.z + y.w;
    #pragma unroll
    for (int off = 16; off; off >>= 1) s1 += __shfl_xor_sync(0xffffffffu, s1, off);
    float mu = s1 * (1.0f / 128.0f);
    float dx = y.x - mu, dy = y.y - mu, dz = y.z - mu, dw = y.w - mu;
    float sq = dx * dx + dy * dy + dz * dz + dw * dw;
    #pragma unroll
    for (int off = 16; off; off >>= 1) sq += __shfl_xor_sync(0xffffffffu, sq, off);
    float rstd = rsqrtf(sq * (1.0f / 128.0f) + 1e-5f);
    float4 gg = ((const float4*)gamma)[lane];
    float4 bt = ((const float4*)beta)[lane];
    outp[(size_t)w * 32 + lane] = make_float4(dx * rstd * gg.x + bt.x,
                                              dy * rstd * gg.y + bt.y,
                                              dz * rstd * gg.z + bt.z,
                                              dw * rstd * gg.w + bt.w);
}

// ================= HMMA GEMM (mma.sync m16n8k16 bf16, 3-term split) =================

__device__ __forceinline__ void mma16816(float& c0, float& c1, float& c2, float& c3,
                                         uint32_t a0, uint32_t a1, uint32_t a2, uint32_t a3,
                                         uint32_t b0, uint32_t b1) {
    asm volatile(
        "mma.sync.aligned.m16n8k16.row.col.f32.bf16.bf16.f32 "
        "{%0,%1,%2,%3}, {%4,%5,%6,%7}, {%8,%9}, {%0,%1,%2,%3};"
        : "+f"(c0), "+f"(c1), "+f"(c2), "+f"(c3)
        : "r"(a0), "r"(a1), "r"(a2), "r"(a3), "r"(b0), "r"(b1));
}
__device__ __forceinline__ uint32_t bf2pack(float x, float y) {
    __nv_bfloat16 h0 = __float2bfloat16(x), h1 = __float2bfloat16(y);
    return (uint32_t)__bfloat16_as_ushort(h0) | ((uint32_t)__bfloat16_as_ushort(h1) << 16);
}

// D[M,N] = A[M,K] @ W[K,N]; 3-term bf16 split HMMA; W resident in smem. 512 threads.
// Warp grid: RG row-groups (32 rows, 2 rt) x NC col-groups (CW cols, NT n-tiles).
// MODE 0: K=128,N=256,TILE_M=128 -> RG=4,NC=4,CW=64,NT=8; out g_x1h/l + bias+ReLU+LN
// MODE 1: K=256,N=128,TILE_M=64  -> RG=2,NC=8,CW=16,NT=2; out g_h2 fp32 * dinv
template<int K, int N, int TILE_M, int MODE>
__global__ void __launch_bounds__(512, 1)
k_gemm_mma(const float* __restrict__ W, const float* __restrict__ bias,
           const float* __restrict__ gamma, const float* __restrict__ beta, int M)
{
    constexpr int ST = K + 8;
    constexpr int RG = TILE_M / 32;
    constexpr int NC = 16 / RG;
    constexpr int CW = N / NC;
    constexpr int NT = CW / 8;
    extern __shared__ char sm[];
    __nv_bfloat16* Wh = (__nv_bfloat16*)sm;
    __nv_bfloat16* Wl = Wh + (size_t)N * ST;
    __nv_bfloat16* Ah = Wl + (size_t)N * ST;
    __nv_bfloat16* Al = Ah + (size_t)TILE_M * ST;
    float* s_sum = (float*)(Al + (size_t)TILE_M * ST);
    float* s_sq  = s_sum + TILE_M * NC;

    int tid = threadIdx.x, lane = tid & 31, wid = tid >> 5;
    int wr = wid % RG;         // row group (32 rows)
    int wc = wid / RG;         // col group (CW cols)
    int g = lane >> 2, t = lane & 3;

    // ---- W [k][n] fp32 -> Wh/Wl [n][k] bf16 ----
    for (int i = tid; i < K * N; i += 512) {
        int k = i / N, n = i % N;
        float w = W[i];
        __nv_bfloat16 h = __float2bfloat16(w);
        Wh[(size_t)n * ST + k] = h;
        Wl[(size_t)n * ST + k] = __float2bfloat16(w - __bfloat162float(h));
    }

    for (int m0 = blockIdx.x * TILE_M; m0 < M; m0 += gridDim.x * TILE_M) {
        __syncthreads();
        // ---- load A tile (TILE_M x K) into Ah/Al ----
        if (MODE == 0) {
            for (int i = tid; i < TILE_M * (K / 4); i += 512) {
                int r = i / (K / 4), c4 = (i % (K / 4)) * 4;
                int row = m0 + r;
                float4 v = (row < M) ? *(const float4*)(g_a + (size_t)row * K + c4)
                                     : make_float4(0.f, 0.f, 0.f, 0.f);
                __nv_bfloat16 h0 = __float2bfloat16(v.x), h1 = __float2bfloat16(v.y);
                __nv_bfloat16 h2 = __float2bfloat16(v.z), h3 = __float2bfloat16(v.w);
                uint2 hp, lp;
                hp.x = (uint32_t)__bfloat16_as_ushort(h0) | ((uint32_t)__bfloat16_as_ushort(h1) << 16);
                hp.y = (uint32_t)__bfloat16_as_ushort(h2) | ((uint32_t)__bfloat16_as_ushort(h3) << 16);
                lp.x = bf2pack(v.x - __bfloat162float(h0), v.y - __bfloat162float(h1));
                lp.y = bf2pack(v.z - __bfloat162float(h2), v.w - __bfloat162float(h3));
                *(uint2*)(Ah + (size_t)r * ST + c4) = hp;
                *(uint2*)(Al + (size_t)r * ST + c4) = lp;
            }
        } else {
            for (int i = tid; i < TILE_M * (K / 8); i += 512) {
                int r = i / (K / 8), c8 = (i % (K / 8)) * 8;
                int row = m0 + r;
                uint4 vh = make_uint4(0, 0, 0, 0), vl = make_uint4(0, 0, 0, 0);
                if (row < M) {
                    vh = *(const uint4*)(g_x1h + (size_t)row * K + c8);
                    vl = *(const uint4*)(g_x1l + (size_t)row * K + c8);
                }
                *(uint4*)(Ah + (size_t)r * ST + c8) = vh;
                *(uint4*)(Al + (size_t)r * ST + c8) = vl;
            }
        }
        __syncthreads();

        float acc[2][NT][4];
        #pragma unroll
        for (int rt = 0; rt < 2; rt++)
            #pragma unroll
            for (int nt = 0; nt < NT; nt++)
                #pragma unroll
                for (int q = 0; q < 4; q++) acc[rt][nt][q] = 0.f;

        #pragma unroll
        for (int kt = 0; kt < K / 16; kt++) {
            int kc = kt * 16 + 2 * t;
            uint32_t ah[2][4], al[2][4];
            #pragma unroll
            for (int rt = 0; rt < 2; rt++) {
                int R = wr * 32 + rt * 16 + g;
                ah[rt][0] = *(const uint32_t*)(Ah + (size_t)R * ST + kc);
                ah[rt][1] = *(const uint32_t*)(Ah + (size_t)(R + 8) * ST + kc);
                ah[rt][2] = *(const uint32_t*)(Ah + (size_t)R * ST + kc + 8);
                ah[rt][3] = *(const uint32_t*)(Ah + (size_t)(R + 8) * ST + kc + 8);
                al[rt][0] = *(const uint32_t*)(Al + (size_t)R * ST + kc);
                al[rt][1] = *(const uint32_t*)(Al + (size_t)(R + 8) * ST + kc);
                al[rt][2] = *(const uint32_t*)(Al + (size_t)R * ST + kc + 8);
                al[rt][3] = *(const uint32_t*)(Al + (size_t)(R + 8) * ST + kc + 8);
            }
            #pragma unroll
            for (int nt = 0; nt < NT; nt++) {
                int n = wc * CW + nt * 8 + g;
                uint32_t b0h = *(const uint32_t*)(Wh + (size_t)n * ST + kc);
                uint32_t b1h = *(const uint32_t*)(Wh + (size_t)n * ST + kc + 8);
                uint32_t b0l = *(const uint32_t*)(Wl + (size_t)n * ST + kc);
                uint32_t b1l = *(const uint32_t*)(Wl + (size_t)n * ST + kc + 8);
                #pragma unroll
                for (int rt = 0; rt < 2; rt++) {
                    float* c = acc[rt][nt];
                    mma16816(c[0], c[1], c[2], c[3],
                             ah[rt][0], ah[rt][1], ah[rt][2], ah[rt][3], b0h, b1h);
                    mma16816(c[0], c[1], c[2], c[3],
                             al[rt][0], al[rt][1], al[rt][2], al[rt][3], b0h, b1h);
                    mma16816(c[0], c[1], c[2], c[3],
                             ah[rt][0], ah[rt][1], ah[rt][2], ah[rt][3], b0l, b1l);
                }
            }
        }

        if (MODE == 0) {
            // ---- bias + ReLU, per-row partial sums over this col group ----
            #pragma unroll
            for (int rt = 0; rt < 2; rt++) {
                float s0 = 0.f, s1 = 0.f, q0 = 0.f, q1 = 0.f;
                #pragma unroll
                for (int nt = 0; nt < NT; nt++) {
                    int c0 = wc * CW + nt * 8 + 2 * t;
                    float b0 = bias[c0], b1 = bias[c0 + 1];
                    float* c = acc[rt][nt];
                    c[0] = fmaxf(c[0] + b0, 0.f);
                    c[1] = fmaxf(c[1] + b1, 0.f);
                    c[2] = fmaxf(c[2] + b0, 0.f);
                    c[3] = fmaxf(c[3] + b1, 0.f);
                    s0 += c[0] + c[1]; q0 += c[0] * c[0] + c[1] * c[1];
                    s1 += c[2] + c[3]; q1 += c[2] * c[2] + c[3] * c[3];
                }
                #pragma unroll
                for (int off = 1; off <= 2; off <<= 1) {
                    s0 += __shfl_xor_sync(0xffffffffu, s0, off);
                    q0 += __shfl_xor_sync(0xffffffffu, q0, off);
                    s1 += __shfl_xor_sync(0xffffffffu, s1, off);
                    q1 += __shfl_xor_sync(0xffffffffu, q1, off);
                }
                if (t == 0) {
                    int lr = wr * 32 + rt * 16 + g;
                    s_sum[lr * NC + wc] = s0; s_sq[lr * NC + wc] = q0;
                    s_sum[(lr + 8) * NC + wc] = s1; s_sq[(lr + 8) * NC + wc] = q1;
                }
            }
            __syncthreads();
            #pragma unroll
            for (int rt = 0; rt < 2; rt++) {
                int lr0 = wr * 32 + rt * 16 + g;
                float4 fs0 = ((const float4*)s_sum)[lr0];
                float4 fq0 = ((const float4*)s_sq)[lr0];
                float4 fs1 = ((const float4*)s_sum)[lr0 + 8];
                float4 fq1 = ((const float4*)s_sq)[lr0 + 8];
                float mu0 = (fs0.x + fs0.y + fs0.z + fs0.w) * (1.f / 256.f);
                float mu1 = (fs1.x + fs1.y + fs1.z + fs1.w) * (1.f / 256.f);
                float v0 = (fq0.x + fq0.y + fq0.z + fq0.w) * (1.f / 256.f) - mu0 * mu0;
                float v1 = (fq1.x + fq1.y + fq1.z + fq1.w) * (1.f / 256.f) - mu1 * mu1;
                float rs0 = rsqrtf(v0 + 1e-5f), rs1 = rsqrtf(v1 + 1e-5f);
                int row0 = m0 + lr0, row1 = row0 + 8;
                #pragma unroll
                for (int nt = 0; nt < NT; nt++) {
                    int c0 = wc * CW + nt * 8 + 2 * t;
                    float ga0 = gamma[c0], ga1 = gamma[c0 + 1];
                    float be0 = beta[c0], be1 = beta[c0 + 1];
                    float* c = acc[rt][nt];
                    if (row0 < M) {
                        float o0 = (c[0] - mu0) * rs0 * ga0 + be0;
                        float o1 = (c[1] - mu0) * rs0 * ga1 + be1;
                        __nv_bfloat16 h0 = __float2bfloat16(o0), h1 = __float2bfloat16(o1);
                        uint32_t hp = (uint32_t)__bfloat16_as_ushort(h0)
                                    | ((uint32_t)__bfloat16_as_ushort(h1) << 16);
                        uint32_t lp = bf2pack(o0 - __bfloat162float(h0), o1 - __bfloat162float(h1));
                        *(uint32_t*)(g_x1h + (size_t)row0 * N + c0) = hp;
                        *(uint32_t*)(g_x1l + (size_t)row0 * N + c0) = lp;
                    }
                    if (row1 < M) {
                        float o2 = (c[2] - mu1) * rs1 * ga0 + be0;
                        float o3 = (c[3] - mu1) * rs1 * ga1 + be1;
                        __nv_bfloat16 h2 = __float2bfloat16(o2), h3 = __float2bfloat16(o3);
                        uint32_t hp = (uint32_t)__bfloat16_as_ushort(h2)
                                    | ((uint32_t)__bfloat16_as_ushort(h3) << 16);
                        uint32_t lp = bf2pack(o2 - __bfloat162float(h2), o3 - __bfloat162float(h3));
                        *(uint32_t*)(g_x1h + (size_t)row1 * N + c0) = hp;
                        *(uint32_t*)(g_x1l + (size_t)row1 * N + c0) = lp;
                    }
                }
            }
        } else {
            #pragma unroll
            for (int rt = 0; rt < 2; rt++) {
                int lr0 = wr * 32 + rt * 16 + g;
                int row0 = m0 + lr0, row1 = row0 + 8;
                float d0 = (row0 < M) ? g_dinv[row0] : 0.f;
                float d1 = (row1 < M) ? g_dinv[row1] : 0.f;
                #pragma unroll
                for (int nt = 0; nt < NT; nt++) {
                    int c0 = wc * CW + nt * 8 + 2 * t;
                    float* c = acc[rt][nt];
                    if (row0 < M)
                        *(float2*)(g_h2 + (size_t)row0 * N + c0) =
                            make_float2(c[0] * d0, c[1] * d0);
                    if (row1 < M)
                        *(float2*)(g_h2 + (size_t)row1 * N + c0) =
                            make_float2(c[2] * d1, c[3] * d1);
                }
            }
        }
    }
}

// ---------------- launch ----------------
extern "C" void kernel_launch(void* const* d_in, const int* in_sizes, int n_in,
                              void* d_out, int out_size) {
    const int*   x_ids = (const int*)d_in[0];
    const int*   ei    = (const int*)d_in[1];
    const float* embed = (const float*)d_in[2];
    const float* W1    = (const float*)d_in[3];
    const float* b1    = (const float*)d_in[4];
    const float* g1    = (const float*)d_in[5];
    const float* be1   = (const float*)d_in[6];
    const float* W2    = (const float*)d_in[7];
    const float* b2    = (const float*)d_in[8];
    const float* g2    = (const float*)d_in[9];
    const float* be2   = (const float*)d_in[10];
    float* out = (float*)d_out;

    int n = in_sizes[0];        // 50000
    int E = in_sizes[1] / 2;    // 800000
    const int* src = ei;
    const int* dst = ei + E;

    // smem: W (2*N*ST) + A (2*TILE_M*ST) bf16 + LN partials
    const int smem1 = (2 * 256 * 136 + 2 * 128 * 136) * 2 + 2 * 128 * 4 * 4;   // 212992
    const int smem2 = (2 * 128 * 264 + 2 * 64 * 264) * 2 + 2 * 128 * 4 * 4;    // 206848
    cudaFuncSetAttribute((const void*)k_gemm_mma<128, 256, 128, 0>,
                         cudaFuncAttributeMaxDynamicSharedMemorySize, smem1);
    cudaFuncSetAttribute((const void*)k_gemm_mma<256, 128, 64, 1>,
                         cudaFuncAttributeMaxDynamicSharedMemorySize, smem2);

    int nb = (n + 1023) / 1024;
    int warps_grid = (n * 32 + 255) / 256;

    void* p_cnt = nullptr;  cudaGetSymbolAddress(&p_cnt, g_cnt);
    void* p_flag = nullptr; cudaGetSymbolAddress(&p_flag, g_bflag);
    cudaMemsetAsync(p_cnt, 0, (size_t)n * sizeof(int), 0);
    cudaMemsetAsync(p_flag, 0, 64 * sizeof(int), 0);

    k_histscan<<<nb, 1024>>>(dst, n, E);                       // kernel 0
    k_fill<<<(E + 255) / 256, 256>>>(src, dst, x_ids, E);      // kernel 1

    k_agg0<<<warps_grid, 256>>>(x_ids, (const float4*)embed, n);             // kernel 2
    k_gemm_mma<128, 256, 128, 0><<<152, 512, smem1>>>(W1, b1, g1, be1, n);   // kernel 3 (ncu)

    k_gemm_mma<256, 128, 64, 1><<<152, 512, smem2>>>(W2, nullptr, nullptr, nullptr, n);  // kernel 4
    k_agg1<<<warps_grid, 256>>>(b2, g2, be2, (float4*)out, n);                           // kernel 5
}

// round 9
// speedup vs baseline: 1.4849x; 1.0083x over previous
#include <cuda_runtime.h>
#include <cuda_bf16.h>
#include <cstdint>

#define NMAX 50000
#define EMAX 800000

// ---------------- scratch ----------------
__device__ float g_a [(size_t)NMAX * 128];
__device__ __nv_bfloat16 g_x1h[(size_t)NMAX * 256];   // layer-1 output, bf16 hi
__device__ __nv_bfloat16 g_x1l[(size_t)NMAX * 256];   // layer-1 output, bf16 lo
__device__ float g_h2[(size_t)NMAX * 128];
__device__ float g_dinv[NMAX];
__device__ int   g_cnt[NMAX];
__device__ int   g_rowptr[NMAX + 1];
__device__ int   g_fill[NMAX];
__device__ int4  g_cols[EMAX];
__device__ int   g_bsum[64];
__device__ int   g_bflag[64];

// ---------------- CSR build ----------------
__global__ void k_histscan(const int* __restrict__ dst, int n, int E) {
    __shared__ int sh[1024];
    __shared__ int s_off;
    int tid = threadIdx.x, b = blockIdx.x;
    int i0 = b * 1024 + tid;

    for (int i = i0; i < E; i += gridDim.x * 1024)
        atomicAdd(&g_cnt[dst[i]], 1);
    __threadfence();
    __syncthreads();
    if (tid == 0) {
        atomicAdd(&g_bflag[50], 1);
        while (((volatile int*)g_bflag)[50] < (int)gridDim.x) { }
    }
    __syncthreads();

    int c = (i0 < n) ? g_cnt[i0] : 0;
    sh[tid] = c;
    __syncthreads();
    for (int off = 1; off < 1024; off <<= 1) {
        int t = (tid >= off) ? sh[tid - off] : 0;
        __syncthreads();
        sh[tid] += t;
        __syncthreads();
    }
    if (tid == 1023) {
        g_bsum[b] = sh[1023];
        __threadfence();
        g_bflag[b] = 1;
    }
    if (tid == 0) {
        int off = 0;
        for (int j = 0; j < b; j++) {
            while (((volatile int*)g_bflag)[j] == 0) { }
            off += ((volatile int*)g_bsum)[j];
        }
        s_off = off;
    }
    __syncthreads();
    if (i0 < n) {
        int incl = sh[tid] + s_off;
        int excl = incl - c;
        g_rowptr[i0] = excl;
        g_fill[i0] = excl;
        g_dinv[i0] = rsqrtf((float)(c + 1));
    }
    if (i0 == 0) g_rowptr[n] = E;
}

__global__ void k_fill(const int* __restrict__ src, const int* __restrict__ dst,
                       const int* __restrict__ x_ids, int E) {
    int i = blockIdx.x * blockDim.x + threadIdx.x;
    if (i < E) {
        int s = src[i];
        int d = dst[i];
        int pos = atomicAdd(&g_fill[d], 1);
        g_cols[pos] = make_int4(x_ids[s], __float_as_int(g_dinv[s]), s, 0);
    }
}

// ---------------- layer-1 aggregation ----------------
__global__ void __launch_bounds__(256, 6)
k_agg0(const int* __restrict__ x_ids, const float4* __restrict__ embed, int n) {
    int t = blockIdx.x * blockDim.x + threadIdx.x;
    int w = t >> 5, lane = t & 31;
    if (w >= n) return;
    float diw = g_dinv[w];
    int sid = x_ids[w];
    float4 sv = embed[(size_t)sid * 32 + lane];
    float4 acc = make_float4(sv.x * diw, sv.y * diw, sv.z * diw, sv.w * diw);
    int s = g_rowptr[w], e = g_rowptr[w + 1];
    for (int p = s; p < e; p += 4) {
        int mm = e - p;
        float dj[4]; float4 vv[4];
        #pragma unroll
        for (int u = 0; u < 4; u++) {
            bool ok = u < mm;
            int4 c = g_cols[ok ? p + u : p];
            dj[u] = ok ? __int_as_float(c.y) : 0.f;
            vv[u] = embed[(size_t)c.x * 32 + lane];
        }
        #pragma unroll
        for (int u = 0; u < 4; u++) {
            acc.x = fmaf(vv[u].x, dj[u], acc.x);
            acc.y = fmaf(vv[u].y, dj[u], acc.y);
            acc.z = fmaf(vv[u].z, dj[u], acc.z);
            acc.w = fmaf(vv[u].w, dj[u], acc.w);
        }
    }
    ((float4*)g_a)[(size_t)w * 32 + lane] =
        make_float4(acc.x * diw, acc.y * diw, acc.z * diw, acc.w * diw);
}

// ---------------- layer-2 aggregation + bias + LayerNorm ----------------
__global__ void __launch_bounds__(256, 6)
k_agg1(const float* __restrict__ b, const float* __restrict__ gamma,
       const float* __restrict__ beta, float4* __restrict__ outp, int n) {
    int t = blockIdx.x * blockDim.x + threadIdx.x;
    int w = t >> 5, lane = t & 31;
    if (w >= n) return;
    const float4* xs = (const float4*)g_h2;
    float4 acc = xs[(size_t)w * 32 + lane];
    int s = g_rowptr[w], e = g_rowptr[w + 1];
    for (int p = s; p < e; p += 4) {
        int mm = e - p;
        float dj[4]; float4 vv[4];
        #pragma unroll
        for (int u = 0; u < 4; u++) {
            bool ok = u < mm;
            int4 c = g_cols[ok ? p + u : p];
            dj[u] = ok ? 1.f : 0.f;
            vv[u] = xs[(size_t)c.z * 32 + lane];
        }
        #pragma unroll
        for (int u = 0; u < 4; u++) {
            acc.x = fmaf(vv[u].x, dj[u], acc.x);
            acc.y = fmaf(vv[u].y, dj[u], acc.y);
            acc.z = fmaf(vv[u].z, dj[u], acc.z);
            acc.w = fmaf(vv[u].w, dj[u], acc.w);
        }
    }
    float di = g_dinv[w];
    float4 bb = ((const float4*)b)[lane];
    float4 y = make_float4(acc.x * di + bb.x, acc.y * di + bb.y,
                           acc.z * di + bb.z, acc.w * di + bb.w);
    float s1 = y.x + y.y + y.z + y.w;
    #pragma unroll
    for (int off = 16; off; off >>= 1) s1 += __shfl_xor_sync(0xffffffffu, s1, off);
    float mu = s1 * (1.0f / 128.0f);
    float dx = y.x - mu, dy = y.y - mu, dz = y.z - mu, dw = y.w - mu;
    float sq = dx * dx + dy * dy + dz * dz + dw * dw;
    #pragma unroll
    for (int off = 16; off; off >>= 1) sq += __shfl_xor_sync(0xffffffffu, sq, off);
    float rstd = rsqrtf(sq * (1.0f / 128.0f) + 1e-5f);
    float4 gg = ((const float4*)gamma)[lane];
    float4 bt = ((const float4*)beta)[lane];
    outp[(size_t)w * 32 + lane] = make_float4(dx * rstd * gg.x + bt.x,
                                              dy * rstd * gg.y + bt.y,
                                              dz * rstd * gg.z + bt.z,
                                              dw * rstd * gg.w + bt.w);
}

// ================= HMMA GEMM (mma.sync m16n8k16 bf16, 3-term split, ldmatrix) ============

__device__ __forceinline__ void mma16816(float& c0, float& c1, float& c2, float& c3,
                                         uint32_t a0, uint32_t a1, uint32_t a2, uint32_t a3,
                                         uint32_t b0, uint32_t b1) {
    asm volatile(
        "mma.sync.aligned.m16n8k16.row.col.f32.bf16.bf16.f32 "
        "{%0,%1,%2,%3}, {%4,%5,%6,%7}, {%8,%9}, {%0,%1,%2,%3};"
        : "+f"(c0), "+f"(c1), "+f"(c2), "+f"(c3)
        : "r"(a0), "r"(a1), "r"(a2), "r"(a3), "r"(b0), "r"(b1));
}
__device__ __forceinline__ void ldm_x4(uint32_t addr, uint32_t& r0, uint32_t& r1,
                                       uint32_t& r2, uint32_t& r3) {
    asm volatile("ldmatrix.sync.aligned.m8n8.x4.shared.b16 {%0,%1,%2,%3}, [%4];"
                 : "=r"(r0), "=r"(r1), "=r"(r2), "=r"(r3) : "r"(addr));
}
__device__ __forceinline__ uint32_t bf2pack(float x, float y) {
    __nv_bfloat16 h0 = __float2bfloat16(x), h1 = __float2bfloat16(y);
    return (uint32_t)__bfloat16_as_ushort(h0) | ((uint32_t)__bfloat16_as_ushort(h1) << 16);
}
__device__ __forceinline__ uint32_t smem_u32(const void* p) {
    return (uint32_t)__cvta_generic_to_shared(p);
}

// D[M,N] = A[M,K] @ W[K,N]; 3-term bf16 split HMMA; W resident in smem. 512 threads.
// MODE 0: K=128,N=256,TILE_M=128 -> RG=4,NC=4,CW=64,NT=8; out g_x1h/l + bias+ReLU+LN
// MODE 1: K=256,N=128,TILE_M=64  -> RG=2,NC=8,CW=16,NT=2; out g_h2 fp32 * dinv
template<int K, int N, int TILE_M, int MODE>
__global__ void __launch_bounds__(512, 1)
k_gemm_mma(const float* __restrict__ W, const float* __restrict__ bias,
           const float* __restrict__ gamma, const float* __restrict__ beta, int M)
{
    constexpr int ST = K + 8;
    constexpr int RG = TILE_M / 32;
    constexpr int NC = 16 / RG;
    constexpr int CW = N / NC;
    constexpr int NT = CW / 8;
    extern __shared__ char sm[];
    __nv_bfloat16* Wh = (__nv_bfloat16*)sm;
    __nv_bfloat16* Wl = Wh + (size_t)N * ST;
    __nv_bfloat16* Ah = Wl + (size_t)N * ST;
    __nv_bfloat16* Al = Ah + (size_t)TILE_M * ST;
    float* s_sum = (float*)(Al + (size_t)TILE_M * ST);
    float* s_sq  = s_sum + TILE_M * NC;

    int tid = threadIdx.x, lane = tid & 31, wid = tid >> 5;
    int wr = wid % RG;         // row group (32 rows)
    int wc = wid / RG;         // col group (CW cols)
    int g = lane >> 2, t = lane & 3;

    // ---- W [k][n] fp32 -> Wh/Wl [n][k] bf16 ----
    for (int i = tid; i < K * N; i += 512) {
        int k = i / N, n = i % N;
        float w = W[i];
        __nv_bfloat16 h = __float2bfloat16(w);
        Wh[(size_t)n * ST + k] = h;
        Wl[(size_t)n * ST + k] = __float2bfloat16(w - __bfloat162float(h));
    }

    // ---- ldmatrix per-lane base addresses ----
    int tl = lane >> 3, tr = lane & 7;     // tile index, row-in-tile
    // A x4 tiles: t0 rows+0 @k0, t1 rows+8 @k0, t2 rows+0 @k8, t3 rows+8 @k8
    uint32_t a_addr[2];
    #pragma unroll
    for (int rt = 0; rt < 2; rt++) {
        int row = wr * 32 + rt * 16 + tr + 8 * (tl & 1);
        a_addr[rt] = smem_u32(Ah) + (uint32_t)((row * ST + 8 * (tl >> 1)) * 2);
    }
    const uint32_t lo_off = (uint32_t)(TILE_M * ST * 2);
    // W x4 tiles: t0 Wh@k0, t1 Wh@k8, t2 Wl@k0, t3 Wl@k8
    uint32_t w_addr[NT];
    #pragma unroll
    for (int nt = 0; nt < NT; nt++) {
        int n = wc * CW + nt * 8 + tr;
        w_addr[nt] = smem_u32(Wh) + (uint32_t)((n * ST + 8 * (tl & 1)) * 2)
                   + ((tl & 2) ? (uint32_t)(N * ST * 2) : 0u);
    }

    for (int m0 = blockIdx.x * TILE_M; m0 < M; m0 += gridDim.x * TILE_M) {
        __syncthreads();
        // ---- load A tile (TILE_M x K) into Ah/Al ----
        if (MODE == 0) {
            for (int i = tid; i < TILE_M * (K / 4); i += 512) {
                int r = i / (K / 4), c4 = (i % (K / 4)) * 4;
                int row = m0 + r;
                float4 v = (row < M) ? *(const float4*)(g_a + (size_t)row * K + c4)
                                     : make_float4(0.f, 0.f, 0.f, 0.f);
                __nv_bfloat16 h0 = __float2bfloat16(v.x), h1 = __float2bfloat16(v.y);
                __nv_bfloat16 h2 = __float2bfloat16(v.z), h3 = __float2bfloat16(v.w);
                uint2 hp, lp;
                hp.x = (uint32_t)__bfloat16_as_ushort(h0) | ((uint32_t)__bfloat16_as_ushort(h1) << 16);
                hp.y = (uint32_t)__bfloat16_as_ushort(h2) | ((uint32_t)__bfloat16_as_ushort(h3) << 16);
                lp.x = bf2pack(v.x - __bfloat162float(h0), v.y - __bfloat162float(h1));
                lp.y = bf2pack(v.z - __bfloat162float(h2), v.w - __bfloat162float(h3));
                *(uint2*)(Ah + (size_t)r * ST + c4) = hp;
                *(uint2*)(Al + (size_t)r * ST + c4) = lp;
            }
        } else {
            for (int i = tid; i < TILE_M * (K / 8); i += 512) {
                int r = i / (K / 8), c8 = (i % (K / 8)) * 8;
                int row = m0 + r;
                uint4 vh = make_uint4(0, 0, 0, 0), vl = make_uint4(0, 0, 0, 0);
                if (row < M) {
                    vh = *(const uint4*)(g_x1h + (size_t)row * K + c8);
                    vl = *(const uint4*)(g_x1l + (size_t)row * K + c8);
                }
                *(uint4*)(Ah + (size_t)r * ST + c8) = vh;
                *(uint4*)(Al + (size_t)r * ST + c8) = vl;
            }
        }
        __syncthreads();

        float acc[2][NT][4];
        #pragma unroll
        for (int rt = 0; rt < 2; rt++)
            #pragma unroll
            for (int nt = 0; nt < NT; nt++)
                #pragma unroll
                for (int q = 0; q < 4; q++) acc[rt][nt][q] = 0.f;

        #pragma unroll
        for (int kt = 0; kt < K / 16; kt++) {
            uint32_t koff = (uint32_t)kt * 32u;
            uint32_t ah[2][4], al[2][4];
            #pragma unroll
            for (int rt = 0; rt < 2; rt++) {
                ldm_x4(a_addr[rt] + koff, ah[rt][0], ah[rt][1], ah[rt][2], ah[rt][3]);
                ldm_x4(a_addr[rt] + koff + lo_off, al[rt][0], al[rt][1], al[rt][2], al[rt][3]);
            }
            #pragma unroll
            for (int nt = 0; nt < NT; nt++) {
                uint32_t b0h, b1h, b0l, b1l;
                ldm_x4(w_addr[nt] + koff, b0h, b1h, b0l, b1l);
                #pragma unroll
                for (int rt = 0; rt < 2; rt++) {
                    float* c = acc[rt][nt];
                    mma16816(c[0], c[1], c[2], c[3],
                             ah[rt][0], ah[rt][1], ah[rt][2], ah[rt][3], b0h, b1h);
                    mma16816(c[0], c[1], c[2], c[3],
                             al[rt][0], al[rt][1], al[rt][2], al[rt][3], b0h, b1h);
                    mma16816(c[0], c[1], c[2], c[3],
                             ah[rt][0], ah[rt][1], ah[rt][2], ah[rt][3], b0l, b1l);
                }
            }
        }

        if (MODE == 0) {
            // ---- bias + ReLU, per-row partial sums over this col group ----
            #pragma unroll
            for (int rt = 0; rt < 2; rt++) {
                float s0 = 0.f, s1 = 0.f, q0 = 0.f, q1 = 0.f;
                #pragma unroll
                for (int nt = 0; nt < NT; nt++) {
                    int c0 = wc * CW + nt * 8 + 2 * t;
                    float b0 = bias[c0], b1 = bias[c0 + 1];
                    float* c = acc[rt][nt];
                    c[0] = fmaxf(c[0] + b0, 0.f);
                    c[1] = fmaxf(c[1] + b1, 0.f);
                    c[2] = fmaxf(c[2] + b0, 0.f);
                    c[3] = fmaxf(c[3] + b1, 0.f);
                    s0 += c[0] + c[1]; q0 += c[0] * c[0] + c[1] * c[1];
                    s1 += c[2] + c[3]; q1 += c[2] * c[2] + c[3] * c[3];
                }
                #pragma unroll
                for (int off = 1; off <= 2; off <<= 1) {
                    s0 += __shfl_xor_sync(0xffffffffu, s0, off);
                    q0 += __shfl_xor_sync(0xffffffffu, q0, off);
                    s1 += __shfl_xor_sync(0xffffffffu, s1, off);
                    q1 += __shfl_xor_sync(0xffffffffu, q1, off);
                }
                if (t == 0) {
                    int lr = wr * 32 + rt * 16 + g;
                    s_sum[lr * NC + wc] = s0; s_sq[lr * NC + wc] = q0;
                    s_sum[(lr + 8) * NC + wc] = s1; s_sq[(lr + 8) * NC + wc] = q1;
                }
            }
            __syncthreads();
            #pragma unroll
            for (int rt = 0; rt < 2; rt++) {
                int lr0 = wr * 32 + rt * 16 + g;
                float4 fs0 = ((const float4*)s_sum)[lr0];
                float4 fq0 = ((const float4*)s_sq)[lr0];
                float4 fs1 = ((const float4*)s_sum)[lr0 + 8];
                float4 fq1 = ((const float4*)s_sq)[lr0 + 8];
                float mu0 = (fs0.x + fs0.y + fs0.z + fs0.w) * (1.f / 256.f);
                float mu1 = (fs1.x + fs1.y + fs1.z + fs1.w) * (1.f / 256.f);
                float v0 = (fq0.x + fq0.y + fq0.z + fq0.w) * (1.f / 256.f) - mu0 * mu0;
                float v1 = (fq1.x + fq1.y + fq1.z + fq1.w) * (1.f / 256.f) - mu1 * mu1;
                float rs0 = rsqrtf(v0 + 1e-5f), rs1 = rsqrtf(v1 + 1e-5f);
                int row0 = m0 + lr0, row1 = row0 + 8;
                #pragma unroll
                for (int nt = 0; nt < NT; nt++) {
                    int c0 = wc * CW + nt * 8 + 2 * t;
                    float ga0 = gamma[c0], ga1 = gamma[c0 + 1];
                    float be0 = beta[c0], be1 = beta[c0 + 1];
                    float* c = acc[rt][nt];
                    if (row0 < M) {
                        float o0 = (c[0] - mu0) * rs0 * ga0 + be0;
                        float o1 = (c[1] - mu0) * rs0 * ga1 + be1;
                        __nv_bfloat16 h0 = __float2bfloat16(o0), h1 = __float2bfloat16(o1);
                        uint32_t hp = (uint32_t)__bfloat16_as_ushort(h0)
                                    | ((uint32_t)__bfloat16_as_ushort(h1) << 16);
                        uint32_t lp = bf2pack(o0 - __bfloat162float(h0), o1 - __bfloat162float(h1));
                        *(uint32_t*)(g_x1h + (size_t)row0 * N + c0) = hp;
                        *(uint32_t*)(g_x1l + (size_t)row0 * N + c0) = lp;
                    }
                    if (row1 < M) {
                        float o2 = (c[2] - mu1) * rs1 * ga0 + be0;
                        float o3 = (c[3] - mu1) * rs1 * ga1 + be1;
                        __nv_bfloat16 h2 = __float2bfloat16(o2), h3 = __float2bfloat16(o3);
                        uint32_t hp = (uint32_t)__bfloat16_as_ushort(h2)
                                    | ((uint32_t)__bfloat16_as_ushort(h3) << 16);
                        uint32_t lp = bf2pack(o2 - __bfloat162float(h2), o3 - __bfloat162float(h3));
                        *(uint32_t*)(g_x1h + (size_t)row1 * N + c0) = hp;
                        *(uint32_t*)(g_x1l + (size_t)row1 * N + c0) = lp;
                    }
                }
            }
        } else {
            #pragma unroll
            for (int rt = 0; rt < 2; rt++) {
                int lr0 = wr * 32 + rt * 16 + g;
                int row0 = m0 + lr0, row1 = row0 + 8;
                float d0 = (row0 < M) ? g_dinv[row0] : 0.f;
                float d1 = (row1 < M) ? g_dinv[row1] : 0.f;
                #pragma unroll
                for (int nt = 0; nt < NT; nt++) {
                    int c0 = wc * CW + nt * 8 + 2 * t;
                    float* c = acc[rt][nt];
                    if (row0 < M)
                        *(float2*)(g_h2 + (size_t)row0 * N + c0) =
                            make_float2(c[0] * d0, c[1] * d0);
                    if (row1 < M)
                        *(float2*)(g_h2 + (size_t)row1 * N + c0) =
                            make_float2(c[2] * d1, c[3] * d1);
                }
            }
        }
    }
}

// ---------------- launch ----------------
extern "C" void kernel_launch(void* const* d_in, const int* in_sizes, int n_in,
                              void* d_out, int out_size) {
    const int*   x_ids = (const int*)d_in[0];
    const int*   ei    = (const int*)d_in[1];
    const float* embed = (const float*)d_in[2];
    const float* W1    = (const float*)d_in[3];
    const float* b1    = (const float*)d_in[4];
    const float* g1    = (const float*)d_in[5];
    const float* be1   = (const float*)d_in[6];
    const float* W2    = (const float*)d_in[7];
    const float* b2    = (const float*)d_in[8];
    const float* g2    = (const float*)d_in[9];
    const float* be2   = (const float*)d_in[10];
    float* out = (float*)d_out;

    int n = in_sizes[0];        // 50000
    int E = in_sizes[1] / 2;    // 800000
    const int* src = ei;
    const int* dst = ei + E;

    // smem: W (2*N*ST) + A (2*TILE_M*ST) bf16 + LN partials
    const int smem1 = (2 * 256 * 136 + 2 * 128 * 136) * 2 + 2 * 128 * 4 * 4;   // 212992
    const int smem2 = (2 * 128 * 264 + 2 * 64 * 264) * 2 + 2 * 128 * 4 * 4;    // 206848
    cudaFuncSetAttribute((const void*)k_gemm_mma<128, 256, 128, 0>,
                         cudaFuncAttributeMaxDynamicSharedMemorySize, smem1);
    cudaFuncSetAttribute((const void*)k_gemm_mma<256, 128, 64, 1>,
                         cudaFuncAttributeMaxDynamicSharedMemorySize, smem2);

    int nb = (n + 1023) / 1024;
    int warps_grid = (n * 32 + 255) / 256;

    void* p_cnt = nullptr;  cudaGetSymbolAddress(&p_cnt, g_cnt);
    void* p_flag = nullptr; cudaGetSymbolAddress(&p_flag, g_bflag);
    cudaMemsetAsync(p_cnt, 0, (size_t)n * sizeof(int), 0);
    cudaMemsetAsync(p_flag, 0, 64 * sizeof(int), 0);

    k_histscan<<<nb, 1024>>>(dst, n, E);                       // kernel 0
    k_fill<<<(E + 255) / 256, 256>>>(src, dst, x_ids, E);      // kernel 1

    k_agg0<<<warps_grid, 256>>>(x_ids, (const float4*)embed, n);             // kernel 2
    k_gemm_mma<128, 256, 128, 0><<<152, 512, smem1>>>(W1, b1, g1, be1, n);   // kernel 3 (ncu)

    k_gemm_mma<256, 128, 64, 1><<<152, 512, smem2>>>(W2, nullptr, nullptr, nullptr, n);  // kernel 4
    k_agg1<<<warps_grid, 256>>>(b2, g2, be2, (float4*)out, n);                           // kernel 5
}

// round 10
// speedup vs baseline: 1.5577x; 1.0490x over previous
#include <cuda_runtime.h>
#include <cuda_bf16.h>
#include <cstdint>

#define NMAX 50000
#define EMAX 800000

// ---------------- scratch ----------------
__device__ __nv_bfloat16 g_ah[(size_t)NMAX * 128];    // layer-1 agg output, bf16 hi
__device__ __nv_bfloat16 g_al[(size_t)NMAX * 128];    // layer-1 agg output, bf16 lo
__device__ __nv_bfloat16 g_x1h[(size_t)NMAX * 256];   // layer-1 output, bf16 hi
__device__ __nv_bfloat16 g_x1l[(size_t)NMAX * 256];   // layer-1 output, bf16 lo
__device__ float g_h2[(size_t)NMAX * 128];
__device__ float g_dinv[NMAX];
__device__ int   g_cnt[NMAX];
__device__ int   g_rowptr[NMAX + 1];
__device__ int   g_fill[NMAX];
__device__ int4  g_cols[EMAX];
__device__ int   g_bsum[64];
__device__ int   g_bflag[64];

// ---------------- CSR build ----------------
__global__ void k_histscan(const int* __restrict__ dst, int n, int E) {
    __shared__ int sh[1024];
    __shared__ int s_off;
    int tid = threadIdx.x, b = blockIdx.x;
    int i0 = b * 1024 + tid;

    for (int i = i0; i < E; i += gridDim.x * 1024)
        atomicAdd(&g_cnt[dst[i]], 1);
    __threadfence();
    __syncthreads();
    if (tid == 0) {
        atomicAdd(&g_bflag[50], 1);
        while (((volatile int*)g_bflag)[50] < (int)gridDim.x) { }
    }
    __syncthreads();

    int c = (i0 < n) ? g_cnt[i0] : 0;
    sh[tid] = c;
    __syncthreads();
    for (int off = 1; off < 1024; off <<= 1) {
        int t = (tid >= off) ? sh[tid - off] : 0;
        __syncthreads();
        sh[tid] += t;
        __syncthreads();
    }
    if (tid == 1023) {
        g_bsum[b] = sh[1023];
        __threadfence();
        g_bflag[b] = 1;
    }
    if (tid == 0) {
        int off = 0;
        for (int j = 0; j < b; j++) {
            while (((volatile int*)g_bflag)[j] == 0) { }
            off += ((volatile int*)g_bsum)[j];
        }
        s_off = off;
    }
    __syncthreads();
    if (i0 < n) {
        int incl = sh[tid] + s_off;
        int excl = incl - c;
        g_rowptr[i0] = excl;
        g_fill[i0] = excl;
        g_dinv[i0] = rsqrtf((float)(c + 1));
    }
    if (i0 == 0) g_rowptr[n] = E;
}

__global__ void k_fill(const int* __restrict__ src, const int* __restrict__ dst,
                       const int* __restrict__ x_ids, int E) {
    int i = blockIdx.x * blockDim.x + threadIdx.x;
    if (i < E) {
        int s = src[i];
        int d = dst[i];
        int pos = atomicAdd(&g_fill[d], 1);
        g_cols[pos] = make_int4(x_ids[s], __float_as_int(g_dinv[s]), s, 0);
    }
}

__device__ __forceinline__ uint32_t bf2pack(float x, float y) {
    __nv_bfloat16 h0 = __float2bfloat16(x), h1 = __float2bfloat16(y);
    return (uint32_t)__bfloat16_as_ushort(h0) | ((uint32_t)__bfloat16_as_ushort(h1) << 16);
}

// ---------------- layer-1 aggregation (writes bf16 hi/lo split) ----------------
__global__ void __launch_bounds__(256, 6)
k_agg0(const int* __restrict__ x_ids, const float4* __restrict__ embed, int n) {
    int t = blockIdx.x * blockDim.x + threadIdx.x;
    int w = t >> 5, lane = t & 31;
    if (w >= n) return;
    float diw = g_dinv[w];
    int sid = x_ids[w];
    float4 sv = embed[(size_t)sid * 32 + lane];
    float4 acc = make_float4(sv.x * diw, sv.y * diw, sv.z * diw, sv.w * diw);
    int s = g_rowptr[w], e = g_rowptr[w + 1];
    for (int p = s; p < e; p += 4) {
        int mm = e - p;
        float dj[4]; float4 vv[4];
        #pragma unroll
        for (int u = 0; u < 4; u++) {
            bool ok = u < mm;
            int4 c = g_cols[ok ? p + u : p];
            dj[u] = ok ? __int_as_float(c.y) : 0.f;
            vv[u] = embed[(size_t)c.x * 32 + lane];
        }
        #pragma unroll
        for (int u = 0; u < 4; u++) {
            acc.x = fmaf(vv[u].x, dj[u], acc.x);
            acc.y = fmaf(vv[u].y, dj[u], acc.y);
            acc.z = fmaf(vv[u].z, dj[u], acc.z);
            acc.w = fmaf(vv[u].w, dj[u], acc.w);
        }
    }
    float4 o = make_float4(acc.x * diw, acc.y * diw, acc.z * diw, acc.w * diw);
    __nv_bfloat16 h0 = __float2bfloat16(o.x), h1 = __float2bfloat16(o.y);
    __nv_bfloat16 h2 = __float2bfloat16(o.z), h3 = __float2bfloat16(o.w);
    uint2 hp, lp;
    hp.x = (uint32_t)__bfloat16_as_ushort(h0) | ((uint32_t)__bfloat16_as_ushort(h1) << 16);
    hp.y = (uint32_t)__bfloat16_as_ushort(h2) | ((uint32_t)__bfloat16_as_ushort(h3) << 16);
    lp.x = bf2pack(o.x - __bfloat162float(h0), o.y - __bfloat162float(h1));
    lp.y = bf2pack(o.z - __bfloat162float(h2), o.w - __bfloat162float(h3));
    *(uint2*)(g_ah + (size_t)w * 128 + lane * 4) = hp;
    *(uint2*)(g_al + (size_t)w * 128 + lane * 4) = lp;
}

// ---------------- layer-2 aggregation + bias + LayerNorm ----------------
__global__ void __launch_bounds__(256, 6)
k_agg1(const float* __restrict__ b, const float* __restrict__ gamma,
       const float* __restrict__ beta, float4* __restrict__ outp, int n) {
    int t = blockIdx.x * blockDim.x + threadIdx.x;
    int w = t >> 5, lane = t & 31;
    if (w >= n) return;
    const float4* xs = (const float4*)g_h2;
    float4 acc = xs[(size_t)w * 32 + lane];
    int s = g_rowptr[w], e = g_rowptr[w + 1];
    for (int p = s; p < e; p += 4) {
        int mm = e - p;
        float dj[4]; float4 vv[4];
        #pragma unroll
        for (int u = 0; u < 4; u++) {
            bool ok = u < mm;
            int4 c = g_cols[ok ? p + u : p];
            dj[u] = ok ? 1.f : 0.f;
            vv[u] = xs[(size_t)c.z * 32 + lane];
        }
        #pragma unroll
        for (int u = 0; u < 4; u++) {
            acc.x = fmaf(vv[u].x, dj[u], acc.x);
            acc.y = fmaf(vv[u].y, dj[u], acc.y);
            acc.z = fmaf(vv[u].z, dj[u], acc.z);
            acc.w = fmaf(vv[u].w, dj[u], acc.w);
        }
    }
    float di = g_dinv[w];
    float4 bb = ((const float4*)b)[lane];
    float4 y = make_float4(acc.x * di + bb.x, acc.y * di + bb.y,
                           acc.z * di + bb.z, acc.w * di + bb.w);
    float s1 = y.x + y.y + y.z + y.w;
    #pragma unroll
    for (int off = 16; off; off >>= 1) s1 += __shfl_xor_sync(0xffffffffu, s1, off);
    float mu = s1 * (1.0f / 128.0f);
    float dx = y.x - mu, dy = y.y - mu, dz = y.z - mu, dw = y.w - mu;
    float sq = dx * dx + dy * dy + dz * dz + dw * dw;
    #pragma unroll
    for (int off = 16; off; off >>= 1) sq += __shfl_xor_sync(0xffffffffu, sq, off);
    float rstd = rsqrtf(sq * (1.0f / 128.0f) + 1e-5f);
    float4 gg = ((const float4*)gamma)[lane];
    float4 bt = ((const float4*)beta)[lane];
    outp[(size_t)w * 32 + lane] = make_float4(dx * rstd * gg.x + bt.x,
                                              dy * rstd * gg.y + bt.y,
                                              dz * rstd * gg.z + bt.z,
                                              dw * rstd * gg.w + bt.w);
}

// ================= HMMA GEMM (bf16 3-term split, ldmatrix, reg-prefetch pipeline) ========

__device__ __forceinline__ void mma16816(float& c0, float& c1, float& c2, float& c3,
                                         uint32_t a0, uint32_t a1, uint32_t a2, uint32_t a3,
                                         uint32_t b0, uint32_t b1) {
    asm volatile(
        "mma.sync.aligned.m16n8k16.row.col.f32.bf16.bf16.f32 "
        "{%0,%1,%2,%3}, {%4,%5,%6,%7}, {%8,%9}, {%0,%1,%2,%3};"
        : "+f"(c0), "+f"(c1), "+f"(c2), "+f"(c3)
        : "r"(a0), "r"(a1), "r"(a2), "r"(a3), "r"(b0), "r"(b1));
}
__device__ __forceinline__ void ldm_x4(uint32_t addr, uint32_t& r0, uint32_t& r1,
                                       uint32_t& r2, uint32_t& r3) {
    asm volatile("ldmatrix.sync.aligned.m8n8.x4.shared.b16 {%0,%1,%2,%3}, [%4];"
                 : "=r"(r0), "=r"(r1), "=r"(r2), "=r"(r3) : "r"(addr));
}
__device__ __forceinline__ uint32_t smem_u32(const void* p) {
    return (uint32_t)__cvta_generic_to_shared(p);
}

// D[M,N] = A[M,K] @ W[K,N]; A already split bf16 hi/lo in gmem. TILE_M=64, 512 threads.
// Pipeline: prefetch next tile's A to regs before MMA loop (gmem latency hides under MMA).
// MODE 0: K=128,N=256 (A=g_ah/g_al)  -> out g_x1h/l + bias+ReLU+LN
// MODE 1: K=256,N=128 (A=g_x1h/g_x1l)-> out g_h2 fp32 * dinv
template<int K, int N, int MODE>
__global__ void __launch_bounds__(512, 1)
k_gemm_mma(const float* __restrict__ W, const float* __restrict__ bias,
           const float* __restrict__ gamma, const float* __restrict__ beta, int M)
{
    constexpr int TILE_M = 64;
    constexpr int ST = K + 8;
    constexpr int RG = 2;              // row groups of 32
    constexpr int NC = 8;              // col groups
    constexpr int CW = N / NC;
    constexpr int NT = CW / 8;
    constexpr int PF = (TILE_M * (K / 8)) / 512;   // uint4 prefetch chunks per matrix
    extern __shared__ char sm[];
    __nv_bfloat16* Wh = (__nv_bfloat16*)sm;
    __nv_bfloat16* Wl = Wh + (size_t)N * ST;
    __nv_bfloat16* Ah = Wl + (size_t)N * ST;
    __nv_bfloat16* Al = Ah + (size_t)TILE_M * ST;
    float* s_sum = (float*)(Al + (size_t)TILE_M * ST);
    float* s_sq  = s_sum + TILE_M * NC;

    int tid = threadIdx.x, lane = tid & 31, wid = tid >> 5;
    int wr = wid % RG;
    int wc = wid / RG;
    int g = lane >> 2, t = lane & 3;

    const __nv_bfloat16* Agh = (MODE == 0) ? g_ah : g_x1h;
    const __nv_bfloat16* Agl = (MODE == 0) ? g_al : g_x1l;

    // ---- W [k][n] fp32 -> Wh/Wl [n][k] bf16 ----
    for (int i = tid; i < K * N; i += 512) {
        int k = i / N, n = i % N;
        float w = W[i];
        __nv_bfloat16 h = __float2bfloat16(w);
        Wh[(size_t)n * ST + k] = h;
        Wl[(size_t)n * ST + k] = __float2bfloat16(w - __bfloat162float(h));
    }

    // ---- ldmatrix per-lane base addresses ----
    int tl = lane >> 3, tr = lane & 7;
    uint32_t a_addr[2];
    #pragma unroll
    for (int rt = 0; rt < 2; rt++) {
        int row = wr * 32 + rt * 16 + tr + 8 * (tl & 1);
        a_addr[rt] = smem_u32(Ah) + (uint32_t)((row * ST + 8 * (tl >> 1)) * 2);
    }
    const uint32_t lo_off = (uint32_t)(TILE_M * ST * 2);
    uint32_t w_addr[NT];
    #pragma unroll
    for (int nt = 0; nt < NT; nt++) {
        int n = wc * CW + nt * 8 + tr;
        w_addr[nt] = smem_u32(Wh) + (uint32_t)((n * ST + 8 * (tl & 1)) * 2)
                   + ((tl & 2) ? (uint32_t)(N * ST * 2) : 0u);
    }

    // ---- prefetch registers ----
    uint4 pf_h[PF], pf_l[PF];
    const uint4 zero4 = make_uint4(0, 0, 0, 0);
    int m0 = blockIdx.x * TILE_M;
    {
        #pragma unroll
        for (int c = 0; c < PF; c++) {
            int idx = tid + c * 512;
            int r = idx / (K / 8), c8 = (idx % (K / 8)) * 8;
            int row = m0 + r;
            bool ok = row < M;
            pf_h[c] = ok ? *(const uint4*)(Agh + (size_t)row * K + c8) : zero4;
            pf_l[c] = ok ? *(const uint4*)(Agl + (size_t)row * K + c8) : zero4;
        }
    }

    for (; m0 < M; m0 += gridDim.x * TILE_M) {
        __syncthreads();   // A smem free (previous tile's MMA done)
        #pragma unroll
        for (int c = 0; c < PF; c++) {
            int idx = tid + c * 512;
            int r = idx / (K / 8), c8 = (idx % (K / 8)) * 8;
            *(uint4*)(Ah + (size_t)r * ST + c8) = pf_h[c];
            *(uint4*)(Al + (size_t)r * ST + c8) = pf_l[c];
        }
        __syncthreads();

        // issue next tile's gmem loads; latency overlaps the MMA loop below
        int m1 = m0 + gridDim.x * TILE_M;
        if (m1 < M) {
            #pragma unroll
            for (int c = 0; c < PF; c++) {
                int idx = tid + c * 512;
                int r = idx / (K / 8), c8 = (idx % (K / 8)) * 8;
                int row = m1 + r;
                bool ok = row < M;
                pf_h[c] = ok ? *(const uint4*)(Agh + (size_t)row * K + c8) : zero4;
                pf_l[c] = ok ? *(const uint4*)(Agl + (size_t)row * K + c8) : zero4;
            }
        }

        float acc[2][NT][4];
        #pragma unroll
        for (int rt = 0; rt < 2; rt++)
            #pragma unroll
            for (int nt = 0; nt < NT; nt++)
                #pragma unroll
                for (int q = 0; q < 4; q++) acc[rt][nt][q] = 0.f;

        #pragma unroll
        for (int kt = 0; kt < K / 16; kt++) {
            uint32_t koff = (uint32_t)kt * 32u;
            uint32_t ah[2][4], al[2][4];
            #pragma unroll
            for (int rt = 0; rt < 2; rt++) {
                ldm_x4(a_addr[rt] + koff, ah[rt][0], ah[rt][1], ah[rt][2], ah[rt][3]);
                ldm_x4(a_addr[rt] + koff + lo_off, al[rt][0], al[rt][1], al[rt][2], al[rt][3]);
            }
            #pragma unroll
            for (int nt = 0; nt < NT; nt++) {
                uint32_t b0h, b1h, b0l, b1l;
                ldm_x4(w_addr[nt] + koff, b0h, b1h, b0l, b1l);
                #pragma unroll
                for (int rt = 0; rt < 2; rt++) {
                    float* c = acc[rt][nt];
                    mma16816(c[0], c[1], c[2], c[3],
                             ah[rt][0], ah[rt][1], ah[rt][2], ah[rt][3], b0h, b1h);
                    mma16816(c[0], c[1], c[2], c[3],
                             al[rt][0], al[rt][1], al[rt][2], al[rt][3], b0h, b1h);
                    mma16816(c[0], c[1], c[2], c[3],
                             ah[rt][0], ah[rt][1], ah[rt][2], ah[rt][3], b0l, b1l);
                }
            }
        }

        if (MODE == 0) {
            #pragma unroll
            for (int rt = 0; rt < 2; rt++) {
                float s0 = 0.f, s1 = 0.f, q0 = 0.f, q1 = 0.f;
                #pragma unroll
                for (int nt = 0; nt < NT; nt++) {
                    int c0 = wc * CW + nt * 8 + 2 * t;
                    float b0 = bias[c0], b1 = bias[c0 + 1];
                    float* c = acc[rt][nt];
                    c[0] = fmaxf(c[0] + b0, 0.f);
                    c[1] = fmaxf(c[1] + b1, 0.f);
                    c[2] = fmaxf(c[2] + b0, 0.f);
                    c[3] = fmaxf(c[3] + b1, 0.f);
                    s0 += c[0] + c[1]; q0 += c[0] * c[0] + c[1] * c[1];
                    s1 += c[2] + c[3]; q1 += c[2] * c[2] + c[3] * c[3];
                }
                #pragma unroll
                for (int off = 1; off <= 2; off <<= 1) {
                    s0 += __shfl_xor_sync(0xffffffffu, s0, off);
                    q0 += __shfl_xor_sync(0xffffffffu, q0, off);
                    s1 += __shfl_xor_sync(0xffffffffu, s1, off);
                    q1 += __shfl_xor_sync(0xffffffffu, q1, off);
                }
                if (t == 0) {
                    int lr = wr * 32 + rt * 16 + g;
                    s_sum[lr * NC + wc] = s0; s_sq[lr * NC + wc] = q0;
                    s_sum[(lr + 8) * NC + wc] = s1; s_sq[(lr + 8) * NC + wc] = q1;
                }
            }
            __syncthreads();
            #pragma unroll
            for (int rt = 0; rt < 2; rt++) {
                int lr0 = wr * 32 + rt * 16 + g;
                float ts0 = 0.f, tq0 = 0.f, ts1 = 0.f, tq1 = 0.f;
                #pragma unroll
                for (int j = 0; j < NC; j += 4) {
                    float4 a0 = *(const float4*)(s_sum + lr0 * NC + j);
                    float4 b0v = *(const float4*)(s_sq + lr0 * NC + j);
                    float4 a1 = *(const float4*)(s_sum + (lr0 + 8) * NC + j);
                    float4 b1v = *(const float4*)(s_sq + (lr0 + 8) * NC + j);
                    ts0 += (a0.x + a0.y) + (a0.z + a0.w);
                    tq0 += (b0v.x + b0v.y) + (b0v.z + b0v.w);
                    ts1 += (a1.x + a1.y) + (a1.z + a1.w);
                    tq1 += (b1v.x + b1v.y) + (b1v.z + b1v.w);
                }
                float mu0 = ts0 * (1.f / 256.f);
                float mu1 = ts1 * (1.f / 256.f);
                float v0 = tq0 * (1.f / 256.f) - mu0 * mu0;
                float v1 = tq1 * (1.f / 256.f) - mu1 * mu1;
                float rs0 = rsqrtf(v0 + 1e-5f), rs1 = rsqrtf(v1 + 1e-5f);
                int row0 = m0 + lr0, row1 = row0 + 8;
                #pragma unroll
                for (int nt = 0; nt < NT; nt++) {
                    int c0 = wc * CW + nt * 8 + 2 * t;
                    float ga0 = gamma[c0], ga1 = gamma[c0 + 1];
                    float be0 = beta[c0], be1 = beta[c0 + 1];
                    float* c = acc[rt][nt];
                    if (row0 < M) {
                        float o0 = (c[0] - mu0) * rs0 * ga0 + be0;
                        float o1 = (c[1] - mu0) * rs0 * ga1 + be1;
                        __nv_bfloat16 h0 = __float2bfloat16(o0), h1 = __float2bfloat16(o1);
                        uint32_t hp = (uint32_t)__bfloat16_as_ushort(h0)
                                    | ((uint32_t)__bfloat16_as_ushort(h1) << 16);
                        uint32_t lp = bf2pack(o0 - __bfloat162float(h0), o1 - __bfloat162float(h1));
                        *(uint32_t*)(g_x1h + (size_t)row0 * N + c0) = hp;
                        *(uint32_t*)(g_x1l + (size_t)row0 * N + c0) = lp;
                    }
                    if (row1 < M) {
                        float o2 = (c[2] - mu1) * rs1 * ga0 + be0;
                        float o3 = (c[3] - mu1) * rs1 * ga1 + be1;
                        __nv_bfloat16 h2 = __float2bfloat16(o2), h3 = __float2bfloat16(o3);
                        uint32_t hp = (uint32_t)__bfloat16_as_ushort(h2)
                                    | ((uint32_t)__bfloat16_as_ushort(h3) << 16);
                        uint32_t lp = bf2pack(o2 - __bfloat162float(h2), o3 - __bfloat162float(h3));
                        *(uint32_t*)(g_x1h + (size_t)row1 * N + c0) = hp;
                        *(uint32_t*)(g_x1l + (size_t)row1 * N + c0) = lp;
                    }
                }
            }
        } else {
            #pragma unroll
            for (int rt = 0; rt < 2; rt++) {
                int lr0 = wr * 32 + rt * 16 + g;
                int row0 = m0 + lr0, row1 = row0 + 8;
                float d0 = (row0 < M) ? g_dinv[row0] : 0.f;
                float d1 = (row1 < M) ? g_dinv[row1] : 0.f;
                #pragma unroll
                for (int nt = 0; nt < NT; nt++) {
                    int c0 = wc * CW + nt * 8 + 2 * t;
                    float* c = acc[rt][nt];
                    if (row0 < M)
                        *(float2*)(g_h2 + (size_t)row0 * N + c0) =
                            make_float2(c[0] * d0, c[1] * d0);
                    if (row1 < M)
                        *(float2*)(g_h2 + (size_t)row1 * N + c0) =
                            make_float2(c[2] * d1, c[3] * d1);
                }
            }
        }
    }
}

// ---------------- launch ----------------
extern "C" void kernel_launch(void* const* d_in, const int* in_sizes, int n_in,
                              void* d_out, int out_size) {
    const int*   x_ids = (const int*)d_in[0];
    const int*   ei    = (const int*)d_in[1];
    const float* embed = (const float*)d_in[2];
    const float* W1    = (const float*)d_in[3];
    const float* b1    = (const float*)d_in[4];
    const float* g1    = (const float*)d_in[5];
    const float* be1   = (const float*)d_in[6];
    const float* W2    = (const float*)d_in[7];
    const float* b2    = (const float*)d_in[8];
    const float* g2    = (const float*)d_in[9];
    const float* be2   = (const float*)d_in[10];
    float* out = (float*)d_out;

    int n = in_sizes[0];        // 50000
    int E = in_sizes[1] / 2;    // 800000
    const int* src = ei;
    const int* dst = ei + E;

    // smem: W (2*N*ST) + A (2*64*ST) bf16 + LN partials (2*64*8 fl)
    const int smem1 = (2 * 256 * 136 + 2 * 64 * 136) * 2 + 2 * 64 * 8 * 4;   // 178176
    const int smem2 = (2 * 128 * 264 + 2 * 64 * 264) * 2 + 2 * 64 * 8 * 4;   // 206848
    cudaFuncSetAttribute((const void*)k_gemm_mma<128, 256, 0>,
                         cudaFuncAttributeMaxDynamicSharedMemorySize, smem1);
    cudaFuncSetAttribute((const void*)k_gemm_mma<256, 128, 1>,
                         cudaFuncAttributeMaxDynamicSharedMemorySize, smem2);

    int nb = (n + 1023) / 1024;
    int warps_grid = (n * 32 + 255) / 256;

    void* p_cnt = nullptr;  cudaGetSymbolAddress(&p_cnt, g_cnt);
    void* p_flag = nullptr; cudaGetSymbolAddress(&p_flag, g_bflag);
    cudaMemsetAsync(p_cnt, 0, (size_t)n * sizeof(int), 0);
    cudaMemsetAsync(p_flag, 0, 64 * sizeof(int), 0);

    k_histscan<<<nb, 1024>>>(dst, n, E);                       // kernel 0
    k_fill<<<(E + 255) / 256, 256>>>(src, dst, x_ids, E);      // kernel 1

    k_agg0<<<warps_grid, 256>>>(x_ids, (const float4*)embed, n);        // kernel 2
    k_gemm_mma<128, 256, 0><<<152, 512, smem1>>>(W1, b1, g1, be1, n);   // kernel 3 (ncu)

    k_gemm_mma<256, 128, 1><<<152, 512, smem2>>>(W2, nullptr, nullptr, nullptr, n);  // kernel 4
    k_agg1<<<warps_grid, 256>>>(b2, g2, be2, (float4*)out, n);                       // kernel 5
}

// round 11
// speedup vs baseline: 1.5894x; 1.0204x over previous
#include <cuda_runtime.h>
#include <cuda_fp16.h>
#include <cstdint>

#define NMAX 50000
#define EMAX 800000

// ---------------- scratch ----------------
__device__ __half g_ah[(size_t)NMAX * 128];    // layer-1 agg output, fp16 hi
__device__ __half g_al[(size_t)NMAX * 128];    // layer-1 agg output, fp16 lo
__device__ __half g_x1h[(size_t)NMAX * 256];   // layer-1 output, fp16 hi
__device__ __half g_x1l[(size_t)NMAX * 256];   // layer-1 output, fp16 lo
__device__ float g_h2[(size_t)NMAX * 128];
__device__ float g_dinv[NMAX];
__device__ int   g_cnt[NMAX];
__device__ int   g_rowptr[NMAX + 1];
__device__ int   g_fill[NMAX];
__device__ int4  g_cols[EMAX];
__device__ int   g_bsum[64];
__device__ int   g_bflag[64];

// ---------------- CSR build ----------------
__global__ void k_histscan(const int* __restrict__ dst, int n, int E) {
    __shared__ int sh[1024];
    __shared__ int s_off;
    int tid = threadIdx.x, b = blockIdx.x;
    int i0 = b * 1024 + tid;

    for (int i = i0; i < E; i += gridDim.x * 1024)
        atomicAdd(&g_cnt[dst[i]], 1);
    __threadfence();
    __syncthreads();
    if (tid == 0) {
        atomicAdd(&g_bflag[50], 1);
        while (((volatile int*)g_bflag)[50] < (int)gridDim.x) { }
    }
    __syncthreads();

    int c = (i0 < n) ? g_cnt[i0] : 0;
    sh[tid] = c;
    __syncthreads();
    for (int off = 1; off < 1024; off <<= 1) {
        int t = (tid >= off) ? sh[tid - off] : 0;
        __syncthreads();
        sh[tid] += t;
        __syncthreads();
    }
    if (tid == 1023) {
        g_bsum[b] = sh[1023];
        __threadfence();
        g_bflag[b] = 1;
    }
    if (tid == 0) {
        int off = 0;
        for (int j = 0; j < b; j++) {
            while (((volatile int*)g_bflag)[j] == 0) { }
            off += ((volatile int*)g_bsum)[j];
        }
        s_off = off;
    }
    __syncthreads();
    if (i0 < n) {
        int incl = sh[tid] + s_off;
        int excl = incl - c;
        g_rowptr[i0] = excl;
        g_fill[i0] = excl;
        g_dinv[i0] = rsqrtf((float)(c + 1));
    }
    if (i0 == 0) g_rowptr[n] = E;
}

__global__ void k_fill(const int* __restrict__ src, const int* __restrict__ dst,
                       const int* __restrict__ x_ids, int E) {
    int i = blockIdx.x * blockDim.x + threadIdx.x;
    if (i < E) {
        int s = src[i];
        int d = dst[i];
        int pos = atomicAdd(&g_fill[d], 1);
        g_cols[pos] = make_int4(x_ids[s], __float_as_int(g_dinv[s]), s, 0);
    }
}

__device__ __forceinline__ uint32_t h2pack(__half a, __half b) {
    return (uint32_t)__half_as_ushort(a) | ((uint32_t)__half_as_ushort(b) << 16);
}

// ---------------- layer-1 aggregation (writes fp16 hi/lo split) ----------------
__global__ void __launch_bounds__(256, 6)
k_agg0(const int* __restrict__ x_ids, const float4* __restrict__ embed, int n) {
    int t = blockIdx.x * blockDim.x + threadIdx.x;
    int w = t >> 5, lane = t & 31;
    if (w >= n) return;
    float diw = g_dinv[w];
    int sid = x_ids[w];
    float4 sv = embed[(size_t)sid * 32 + lane];
    float4 acc = make_float4(sv.x * diw, sv.y * diw, sv.z * diw, sv.w * diw);
    int s = g_rowptr[w], e = g_rowptr[w + 1];
    for (int p = s; p < e; p += 4) {
        int mm = e - p;
        float dj[4]; float4 vv[4];
        #pragma unroll
        for (int u = 0; u < 4; u++) {
            bool ok = u < mm;
            int4 c = g_cols[ok ? p + u : p];
            dj[u] = ok ? __int_as_float(c.y) : 0.f;
            vv[u] = embed[(size_t)c.x * 32 + lane];
        }
        #pragma unroll
        for (int u = 0; u < 4; u++) {
            acc.x = fmaf(vv[u].x, dj[u], acc.x);
            acc.y = fmaf(vv[u].y, dj[u], acc.y);
            acc.z = fmaf(vv[u].z, dj[u], acc.z);
            acc.w = fmaf(vv[u].w, dj[u], acc.w);
        }
    }
    float4 o = make_float4(acc.x * diw, acc.y * diw, acc.z * diw, acc.w * diw);
    __half h0 = __float2half_rn(o.x), h1 = __float2half_rn(o.y);
    __half h2 = __float2half_rn(o.z), h3 = __float2half_rn(o.w);
    uint2 hp, lp;
    hp.x = h2pack(h0, h1); hp.y = h2pack(h2, h3);
    lp.x = h2pack(__float2half_rn(o.x - __half2float(h0)), __float2half_rn(o.y - __half2float(h1)));
    lp.y = h2pack(__float2half_rn(o.z - __half2float(h2)), __float2half_rn(o.w - __half2float(h3)));
    *(uint2*)(g_ah + (size_t)w * 128 + lane * 4) = hp;
    *(uint2*)(g_al + (size_t)w * 128 + lane * 4) = lp;
}

// ---------------- layer-2 aggregation + bias + LayerNorm ----------------
__global__ void __launch_bounds__(256, 6)
k_agg1(const float* __restrict__ b, const float* __restrict__ gamma,
       const float* __restrict__ beta, float4* __restrict__ outp, int n) {
    int t = blockIdx.x * blockDim.x + threadIdx.x;
    int w = t >> 5, lane = t & 31;
    if (w >= n) return;
    const float4* xs = (const float4*)g_h2;
    float4 acc = xs[(size_t)w * 32 + lane];
    int s = g_rowptr[w], e = g_rowptr[w + 1];
    for (int p = s; p < e; p += 4) {
        int mm = e - p;
        float dj[4]; float4 vv[4];
        #pragma unroll
        for (int u = 0; u < 4; u++) {
            bool ok = u < mm;
            int4 c = g_cols[ok ? p + u : p];
            dj[u] = ok ? 1.f : 0.f;
            vv[u] = xs[(size_t)c.z * 32 + lane];
        }
        #pragma unroll
        for (int u = 0; u < 4; u++) {
            acc.x = fmaf(vv[u].x, dj[u], acc.x);
            acc.y = fmaf(vv[u].y, dj[u], acc.y);
            acc.z = fmaf(vv[u].z, dj[u], acc.z);
            acc.w = fmaf(vv[u].w, dj[u], acc.w);
        }
    }
    float di = g_dinv[w];
    float4 bb = ((const float4*)b)[lane];
    float4 y = make_float4(acc.x * di + bb.x, acc.y * di + bb.y,
                           acc.z * di + bb.z, acc.w * di + bb.w);
    float s1 = y.x + y.y + y.z + y.w;
    #pragma unroll
    for (int off = 16; off; off >>= 1) s1 += __shfl_xor_sync(0xffffffffu, s1, off);
    float mu = s1 * (1.0f / 128.0f);
    float dx = y.x - mu, dy = y.y - mu, dz = y.z - mu, dw = y.w - mu;
    float sq = dx * dx + dy * dy + dz * dz + dw * dw;
    #pragma unroll
    for (int off = 16; off; off >>= 1) sq += __shfl_xor_sync(0xffffffffu, sq, off);
    float rstd = rsqrtf(sq * (1.0f / 128.0f) + 1e-5f);
    float4 gg = ((const float4*)gamma)[lane];
    float4 bt = ((const float4*)beta)[lane];
    outp[(size_t)w * 32 + lane] = make_float4(dx * rstd * gg.x + bt.x,
                                              dy * rstd * gg.y + bt.y,
                                              dz * rstd * gg.z + bt.z,
                                              dw * rstd * gg.w + bt.w);
}

// ======== HMMA GEMM (fp16 2-term split: AhWh + AlWh; ldmatrix; 2 blocks/SM) ========

__device__ __forceinline__ void mma16816(float& c0, float& c1, float& c2, float& c3,
                                         uint32_t a0, uint32_t a1, uint32_t a2, uint32_t a3,
                                         uint32_t b0, uint32_t b1) {
    asm volatile(
        "mma.sync.aligned.m16n8k16.row.col.f32.f16.f16.f32 "
        "{%0,%1,%2,%3}, {%4,%5,%6,%7}, {%8,%9}, {%0,%1,%2,%3};"
        : "+f"(c0), "+f"(c1), "+f"(c2), "+f"(c3)
        : "r"(a0), "r"(a1), "r"(a2), "r"(a3), "r"(b0), "r"(b1));
}
__device__ __forceinline__ void ldm_x4(uint32_t addr, uint32_t& r0, uint32_t& r1,
                                       uint32_t& r2, uint32_t& r3) {
    asm volatile("ldmatrix.sync.aligned.m8n8.x4.shared.b16 {%0,%1,%2,%3}, [%4];"
                 : "=r"(r0), "=r"(r1), "=r"(r2), "=r"(r3) : "r"(addr));
}
__device__ __forceinline__ uint32_t smem_u32(const void* p) {
    return (uint32_t)__cvta_generic_to_shared(p);
}

// D[M,N] = A[M,K] @ W[K,N]; A pre-split fp16 hi/lo in gmem; W hi-only fp16 in smem.
// TILE_M=32, 256 threads (8 warps = 8 col groups, all warps cover all 32 rows).
// MODE 0: K=128,N=256 (A=g_ah/g_al)  -> out g_x1h/l + bias+ReLU+LN
// MODE 1: K=256,N=128 (A=g_x1h/g_x1l)-> out g_h2 fp32 * dinv
template<int K, int N, int MODE>
__global__ void __launch_bounds__(256, 2)
k_gemm_mma(const float* __restrict__ W, const float* __restrict__ bias,
           const float* __restrict__ gamma, const float* __restrict__ beta, int M)
{
    constexpr int TILE_M = 32;
    constexpr int ST = K + 8;
    constexpr int NC = 8;              // col groups (one per warp)
    constexpr int CW = N / NC;         // 32 (MODE0) / 16 (MODE1)
    constexpr int NT = CW / 8;         // 4 / 2
    constexpr int NP = NT / 2;         // W ldmatrix pairs: 2 / 1
    constexpr int PF = (TILE_M * (K / 8)) / 256;   // uint4 chunks: 2 / 4
    extern __shared__ char sm[];
    __half* Wh = (__half*)sm;
    __half* Ah = Wh + (size_t)N * ST;
    __half* Al = Ah + (size_t)TILE_M * ST;
    float* s_sum = (float*)(Al + (size_t)TILE_M * ST);
    float* s_sq  = s_sum + TILE_M * NC;

    int tid = threadIdx.x, lane = tid & 31, wid = tid >> 5;
    int wc = wid;
    int g = lane >> 2, t = lane & 3;

    const __half* Agh = (MODE == 0) ? g_ah : g_x1h;
    const __half* Agl = (MODE == 0) ? g_al : g_x1l;

    // ---- W [k][n] fp32 -> Wh [n][k] fp16 ----
    for (int i = tid; i < K * N; i += 256) {
        int k = i / N, n = i % N;
        Wh[(size_t)n * ST + k] = __float2half_rn(W[i]);
    }

    // ---- ldmatrix per-lane base addresses ----
    int tl = lane >> 3, tr = lane & 7;
    // A x4: t0 rows0-7@k0, t1 rows8-15@k0, t2 rows0-7@k8, t3 rows8-15@k8
    uint32_t a_addr[2];
    #pragma unroll
    for (int rt = 0; rt < 2; rt++) {
        int row = rt * 16 + tr + 8 * (tl & 1);
        a_addr[rt] = smem_u32(Ah) + (uint32_t)((row * ST + 8 * (tl >> 1)) * 2);
    }
    const uint32_t lo_off = (uint32_t)(TILE_M * ST * 2);
    // W x4 per pair p (covers nt=2p,2p+1): t0 (2p,k0), t1 (2p,k8), t2 (2p+1,k0), t3 (2p+1,k8)
    uint32_t w_addr[NP];
    #pragma unroll
    for (int p = 0; p < NP; p++) {
        int n = wc * CW + p * 16 + (tl >> 1) * 8 + tr;
        w_addr[p] = smem_u32(Wh) + (uint32_t)((n * ST + 8 * (tl & 1)) * 2);
    }

    // ---- prefetch registers ----
    uint4 pf_h[PF], pf_l[PF];
    const uint4 zero4 = make_uint4(0, 0, 0, 0);
    int m0 = blockIdx.x * TILE_M;
    {
        #pragma unroll
        for (int c = 0; c < PF; c++) {
            int idx = tid + c * 256;
            int r = idx / (K / 8), c8 = (idx % (K / 8)) * 8;
            int row = m0 + r;
            bool ok = row < M;
            pf_h[c] = ok ? *(const uint4*)(Agh + (size_t)row * K + c8) : zero4;
            pf_l[c] = ok ? *(const uint4*)(Agl + (size_t)row * K + c8) : zero4;
        }
    }

    for (; m0 < M; m0 += gridDim.x * TILE_M) {
        __syncthreads();   // A smem free
        #pragma unroll
        for (int c = 0; c < PF; c++) {
            int idx = tid + c * 256;
            int r = idx / (K / 8), c8 = (idx % (K / 8)) * 8;
            *(uint4*)(Ah + (size_t)r * ST + c8) = pf_h[c];
            *(uint4*)(Al + (size_t)r * ST + c8) = pf_l[c];
        }
        __syncthreads();

        int m1 = m0 + gridDim.x * TILE_M;
        if (m1 < M) {
            #pragma unroll
            for (int c = 0; c < PF; c++) {
                int idx = tid + c * 256;
                int r = idx / (K / 8), c8 = (idx % (K / 8)) * 8;
                int row = m1 + r;
                bool ok = row < M;
                pf_h[c] = ok ? *(const uint4*)(Agh + (size_t)row * K + c8) : zero4;
                pf_l[c] = ok ? *(const uint4*)(Agl + (size_t)row * K + c8) : zero4;
            }
        }

        float acc[2][NT][4];
        #pragma unroll
        for (int rt = 0; rt < 2; rt++)
            #pragma unroll
            for (int nt = 0; nt < NT; nt++)
                #pragma unroll
                for (int q = 0; q < 4; q++) acc[rt][nt][q] = 0.f;

        #pragma unroll
        for (int kt = 0; kt < K / 16; kt++) {
            uint32_t koff = (uint32_t)kt * 32u;
            uint32_t ah[2][4], al[2][4], wb[NP][4];
            #pragma unroll
            for (int rt = 0; rt < 2; rt++) {
                ldm_x4(a_addr[rt] + koff, ah[rt][0], ah[rt][1], ah[rt][2], ah[rt][3]);
                ldm_x4(a_addr[rt] + koff + lo_off, al[rt][0], al[rt][1], al[rt][2], al[rt][3]);
            }
            #pragma unroll
            for (int p = 0; p < NP; p++)
                ldm_x4(w_addr[p] + koff, wb[p][0], wb[p][1], wb[p][2], wb[p][3]);
            #pragma unroll
            for (int nt = 0; nt < NT; nt++) {
                uint32_t b0 = wb[nt >> 1][(nt & 1) * 2];
                uint32_t b1 = wb[nt >> 1][(nt & 1) * 2 + 1];
                #pragma unroll
                for (int rt = 0; rt < 2; rt++) {
                    float* c = acc[rt][nt];
                    mma16816(c[0], c[1], c[2], c[3],
                             ah[rt][0], ah[rt][1], ah[rt][2], ah[rt][3], b0, b1);
                    mma16816(c[0], c[1], c[2], c[3],
                             al[rt][0], al[rt][1], al[rt][2], al[rt][3], b0, b1);
                }
            }
        }

        if (MODE == 0) {
            #pragma unroll
            for (int rt = 0; rt < 2; rt++) {
                float s0 = 0.f, s1 = 0.f, q0 = 0.f, q1 = 0.f;
                #pragma unroll
                for (int nt = 0; nt < NT; nt++) {
                    int c0 = wc * CW + nt * 8 + 2 * t;
                    float b0 = bias[c0], b1 = bias[c0 + 1];
                    float* c = acc[rt][nt];
                    c[0] = fmaxf(c[0] + b0, 0.f);
                    c[1] = fmaxf(c[1] + b1, 0.f);
                    c[2] = fmaxf(c[2] + b0, 0.f);
                    c[3] = fmaxf(c[3] + b1, 0.f);
                    s0 += c[0] + c[1]; q0 += c[0] * c[0] + c[1] * c[1];
                    s1 += c[2] + c[3]; q1 += c[2] * c[2] + c[3] * c[3];
                }
                #pragma unroll
                for (int off = 1; off <= 2; off <<= 1) {
                    s0 += __shfl_xor_sync(0xffffffffu, s0, off);
                    q0 += __shfl_xor_sync(0xffffffffu, q0, off);
                    s1 += __shfl_xor_sync(0xffffffffu, s1, off);
                    q1 += __shfl_xor_sync(0xffffffffu, q1, off);
                }
                if (t == 0) {
                    int lr = rt * 16 + g;
                    s_sum[lr * NC + wc] = s0; s_sq[lr * NC + wc] = q0;
                    s_sum[(lr + 8) * NC + wc] = s1; s_sq[(lr + 8) * NC + wc] = q1;
                }
            }
            __syncthreads();
            #pragma unroll
            for (int rt = 0; rt < 2; rt++) {
                int lr0 = rt * 16 + g;
                float ts0 = 0.f, tq0 = 0.f, ts1 = 0.f, tq1 = 0.f;
                #pragma unroll
                for (int j = 0; j < NC; j += 4) {
                    float4 a0 = *(const float4*)(s_sum + lr0 * NC + j);
                    float4 b0v = *(const float4*)(s_sq + lr0 * NC + j);
                    float4 a1 = *(const float4*)(s_sum + (lr0 + 8) * NC + j);
                    float4 b1v = *(const float4*)(s_sq + (lr0 + 8) * NC + j);
                    ts0 += (a0.x + a0.y) + (a0.z + a0.w);
                    tq0 += (b0v.x + b0v.y) + (b0v.z + b0v.w);
                    ts1 += (a1.x + a1.y) + (a1.z + a1.w);
                    tq1 += (b1v.x + b1v.y) + (b1v.z + b1v.w);
                }
                float mu0 = ts0 * (1.f / 256.f);
                float mu1 = ts1 * (1.f / 256.f);
                float v0 = tq0 * (1.f / 256.f) - mu0 * mu0;
                float v1 = tq1 * (1.f / 256.f) - mu1 * mu1;
                float rs0 = rsqrtf(v0 + 1e-5f), rs1 = rsqrtf(v1 + 1e-5f);
                int row0 = m0 + lr0, row1 = row0 + 8;
                #pragma unroll
                for (int nt = 0; nt < NT; nt++) {
                    int c0 = wc * CW + nt * 8 + 2 * t;
                    float ga0 = gamma[c0], ga1 = gamma[c0 + 1];
                    float be0 = beta[c0], be1 = beta[c0 + 1];
                    float* c = acc[rt][nt];
                    if (row0 < M) {
                        float o0 = (c[0] - mu0) * rs0 * ga0 + be0;
                        float o1 = (c[1] - mu0) * rs0 * ga1 + be1;
                        __half h0 = __float2half_rn(o0), h1 = __float2half_rn(o1);
                        *(uint32_t*)(g_x1h + (size_t)row0 * N + c0) = h2pack(h0, h1);
                        *(uint32_t*)(g_x1l + (size_t)row0 * N + c0) =
                            h2pack(__float2half_rn(o0 - __half2float(h0)),
                                   __float2half_rn(o1 - __half2float(h1)));
                    }
                    if (row1 < M) {
                        float o2 = (c[2] - mu1) * rs1 * ga0 + be0;
                        float o3 = (c[3] - mu1) * rs1 * ga1 + be1;
                        __half h2 = __float2half_rn(o2), h3 = __float2half_rn(o3);
                        *(uint32_t*)(g_x1h + (size_t)row1 * N + c0) = h2pack(h2, h3);
                        *(uint32_t*)(g_x1l + (size_t)row1 * N + c0) =
                            h2pack(__float2half_rn(o2 - __half2float(h2)),
                                   __float2half_rn(o3 - __half2float(h3)));
                    }
                }
            }
        } else {
            #pragma unroll
            for (int rt = 0; rt < 2; rt++) {
                int lr0 = rt * 16 + g;
                int row0 = m0 + lr0, row1 = row0 + 8;
                float d0 = (row0 < M) ? g_dinv[row0] : 0.f;
                float d1 = (row1 < M) ? g_dinv[row1] : 0.f;
                #pragma unroll
                for (int nt = 0; nt < NT; nt++) {
                    int c0 = wc * CW + nt * 8 + 2 * t;
                    float* c = acc[rt][nt];
                    if (row0 < M)
                        *(float2*)(g_h2 + (size_t)row0 * N + c0) =
                            make_float2(c[0] * d0, c[1] * d0);
                    if (row1 < M)
                        *(float2*)(g_h2 + (size_t)row1 * N + c0) =
                            make_float2(c[2] * d1, c[3] * d1);
                }
            }
        }
    }
}

// ---------------- launch ----------------
extern "C" void kernel_launch(void* const* d_in, const int* in_sizes, int n_in,
                              void* d_out, int out_size) {
    const int*   x_ids = (const int*)d_in[0];
    const int*   ei    = (const int*)d_in[1];
    const float* embed = (const float*)d_in[2];
    const float* W1    = (const float*)d_in[3];
    const float* b1    = (const float*)d_in[4];
    const float* g1    = (const float*)d_in[5];
    const float* be1   = (const float*)d_in[6];
    const float* W2    = (const float*)d_in[7];
    const float* b2    = (const float*)d_in[8];
    const float* g2    = (const float*)d_in[9];
    const float* be2   = (const float*)d_in[10];
    float* out = (float*)d_out;

    int n = in_sizes[0];        // 50000
    int E = in_sizes[1] / 2;    // 800000
    const int* src = ei;
    const int* dst = ei + E;

    // smem: Wh (N*ST) + A hi/lo (2*32*ST) fp16 + LN partials (2*32*8 fl)
    const int smem1 = (256 * 136 + 2 * 32 * 136) * 2 + 2 * 32 * 8 * 4;   // 89088
    const int smem2 = (128 * 264 + 2 * 32 * 264) * 2 + 2 * 32 * 8 * 4;   // 103424
    cudaFuncSetAttribute((const void*)k_gemm_mma<128, 256, 0>,
                         cudaFuncAttributeMaxDynamicSharedMemorySize, smem1);
    cudaFuncSetAttribute((const void*)k_gemm_mma<256, 128, 1>,
                         cudaFuncAttributeMaxDynamicSharedMemorySize, smem2);

    int nb = (n + 1023) / 1024;
    int warps_grid = (n * 32 + 255) / 256;

    void* p_cnt = nullptr;  cudaGetSymbolAddress(&p_cnt, g_cnt);
    void* p_flag = nullptr; cudaGetSymbolAddress(&p_flag, g_bflag);
    cudaMemsetAsync(p_cnt, 0, (size_t)n * sizeof(int), 0);
    cudaMemsetAsync(p_flag, 0, 64 * sizeof(int), 0);

    k_histscan<<<nb, 1024>>>(dst, n, E);                       // kernel 0
    k_fill<<<(E + 255) / 256, 256>>>(src, dst, x_ids, E);      // kernel 1

    k_agg0<<<warps_grid, 256>>>(x_ids, (const float4*)embed, n);        // kernel 2
    k_gemm_mma<128, 256, 0><<<304, 256, smem1>>>(W1, b1, g1, be1, n);   // kernel 3 (ncu)

    k_gemm_mma<256, 128, 1><<<304, 256, smem2>>>(W2, nullptr, nullptr, nullptr, n);  // kernel 4
    k_agg1<<<warps_grid, 256>>>(b2, g2, be2, (float4*)out, n);                       // kernel 5
}

// round 12
// speedup vs baseline: 1.5914x; 1.0012x over previous
#include <cuda_runtime.h>
#include <cuda_fp16.h>
#include <cstdint>

#define NMAX 50000
#define EMAX 800000

// ---------------- scratch ----------------
__device__ __half g_ah[(size_t)NMAX * 128];    // layer-1 agg output, fp16 hi
__device__ __half g_al[(size_t)NMAX * 128];    // layer-1 agg output, fp16 lo
__device__ float g_h2[(size_t)NMAX * 128];
__device__ float g_dinv[NMAX];
__device__ int   g_cnt[NMAX];
__device__ int   g_rowptr[NMAX + 1];
__device__ int   g_fill[NMAX];
__device__ int4  g_cols[EMAX];
__device__ int   g_bsum[64];
__device__ int   g_bflag[64];

// ---------------- CSR build ----------------
__global__ void k_histscan(const int* __restrict__ dst, int n, int E) {
    __shared__ int sh[1024];
    __shared__ int s_off;
    int tid = threadIdx.x, b = blockIdx.x;
    int i0 = b * 1024 + tid;

    for (int i = i0; i < E; i += gridDim.x * 1024)
        atomicAdd(&g_cnt[dst[i]], 1);
    __threadfence();
    __syncthreads();
    if (tid == 0) {
        atomicAdd(&g_bflag[50], 1);
        while (((volatile int*)g_bflag)[50] < (int)gridDim.x) { }
    }
    __syncthreads();

    int c = (i0 < n) ? g_cnt[i0] : 0;
    sh[tid] = c;
    __syncthreads();
    for (int off = 1; off < 1024; off <<= 1) {
        int t = (tid >= off) ? sh[tid - off] : 0;
        __syncthreads();
        sh[tid] += t;
        __syncthreads();
    }
    if (tid == 1023) {
        g_bsum[b] = sh[1023];
        __threadfence();
        g_bflag[b] = 1;
    }
    if (tid == 0) {
        int off = 0;
        for (int j = 0; j < b; j++) {
            while (((volatile int*)g_bflag)[j] == 0) { }
            off += ((volatile int*)g_bsum)[j];
        }
        s_off = off;
    }
    __syncthreads();
    if (i0 < n) {
        int incl = sh[tid] + s_off;
        int excl = incl - c;
        g_rowptr[i0] = excl;
        g_fill[i0] = excl;
        g_dinv[i0] = rsqrtf((float)(c + 1));
    }
    if (i0 == 0) g_rowptr[n] = E;
}

__global__ void k_fill(const int* __restrict__ src, const int* __restrict__ dst,
                       const int* __restrict__ x_ids, int E) {
    int i = blockIdx.x * blockDim.x + threadIdx.x;
    if (i < E) {
        int s = src[i];
        int d = dst[i];
        int pos = atomicAdd(&g_fill[d], 1);
        g_cols[pos] = make_int4(x_ids[s], __float_as_int(g_dinv[s]), s, 0);
    }
}

__device__ __forceinline__ uint32_t h2pack(__half a, __half b) {
    return (uint32_t)__half_as_ushort(a) | ((uint32_t)__half_as_ushort(b) << 16);
}

// ---------------- layer-1 aggregation (writes fp16 hi/lo split) ----------------
__global__ void __launch_bounds__(256, 6)
k_agg0(const int* __restrict__ x_ids, const float4* __restrict__ embed, int n) {
    int t = blockIdx.x * blockDim.x + threadIdx.x;
    int w = t >> 5, lane = t & 31;
    if (w >= n) return;
    float diw = g_dinv[w];
    int sid = x_ids[w];
    float4 sv = embed[(size_t)sid * 32 + lane];
    float4 acc = make_float4(sv.x * diw, sv.y * diw, sv.z * diw, sv.w * diw);
    int s = g_rowptr[w], e = g_rowptr[w + 1];
    for (int p = s; p < e; p += 4) {
        int mm = e - p;
        float dj[4]; float4 vv[4];
        #pragma unroll
        for (int u = 0; u < 4; u++) {
            bool ok = u < mm;
            int4 c = g_cols[ok ? p + u : p];
            dj[u] = ok ? __int_as_float(c.y) : 0.f;
            vv[u] = embed[(size_t)c.x * 32 + lane];
        }
        #pragma unroll
        for (int u = 0; u < 4; u++) {
            acc.x = fmaf(vv[u].x, dj[u], acc.x);
            acc.y = fmaf(vv[u].y, dj[u], acc.y);
            acc.z = fmaf(vv[u].z, dj[u], acc.z);
            acc.w = fmaf(vv[u].w, dj[u], acc.w);
        }
    }
    float4 o = make_float4(acc.x * diw, acc.y * diw, acc.z * diw, acc.w * diw);
    __half h0 = __float2half_rn(o.x), h1 = __float2half_rn(o.y);
    __half h2 = __float2half_rn(o.z), h3 = __float2half_rn(o.w);
    uint2 hp, lp;
    hp.x = h2pack(h0, h1); hp.y = h2pack(h2, h3);
    lp.x = h2pack(__float2half_rn(o.x - __half2float(h0)), __float2half_rn(o.y - __half2float(h1)));
    lp.y = h2pack(__float2half_rn(o.z - __half2float(h2)), __float2half_rn(o.w - __half2float(h3)));
    *(uint2*)(g_ah + (size_t)w * 128 + lane * 4) = hp;
    *(uint2*)(g_al + (size_t)w * 128 + lane * 4) = lp;
}

// ---------------- layer-2 aggregation + bias + LayerNorm ----------------
__global__ void __launch_bounds__(256, 6)
k_agg1(const float* __restrict__ b, const float* __restrict__ gamma,
       const float* __restrict__ beta, float4* __restrict__ outp, int n) {
    int t = blockIdx.x * blockDim.x + threadIdx.x;
    int w = t >> 5, lane = t & 31;
    if (w >= n) return;
    const float4* xs = (const float4*)g_h2;
    float4 acc = xs[(size_t)w * 32 + lane];
    int s = g_rowptr[w], e = g_rowptr[w + 1];
    for (int p = s; p < e; p += 4) {
        int mm = e - p;
        float dj[4]; float4 vv[4];
        #pragma unroll
        for (int u = 0; u < 4; u++) {
            bool ok = u < mm;
            int4 c = g_cols[ok ? p + u : p];
            dj[u] = ok ? 1.f : 0.f;
            vv[u] = xs[(size_t)c.z * 32 + lane];
        }
        #pragma unroll
        for (int u = 0; u < 4; u++) {
            acc.x = fmaf(vv[u].x, dj[u], acc.x);
            acc.y = fmaf(vv[u].y, dj[u], acc.y);
            acc.z = fmaf(vv[u].z, dj[u], acc.z);
            acc.w = fmaf(vv[u].w, dj[u], acc.w);
        }
    }
    float di = g_dinv[w];
    float4 bb = ((const float4*)b)[lane];
    float4 y = make_float4(acc.x * di + bb.x, acc.y * di + bb.y,
                           acc.z * di + bb.z, acc.w * di + bb.w);
    float s1 = y.x + y.y + y.z + y.w;
    #pragma unroll
    for (int off = 16; off; off >>= 1) s1 += __shfl_xor_sync(0xffffffffu, s1, off);
    float mu = s1 * (1.0f / 128.0f);
    float dx = y.x - mu, dy = y.y - mu, dz = y.z - mu, dw = y.w - mu;
    float sq = dx * dx + dy * dy + dz * dz + dw * dw;
    #pragma unroll
    for (int off = 16; off; off >>= 1) sq += __shfl_xor_sync(0xffffffffu, sq, off);
    float rstd = rsqrtf(sq * (1.0f / 128.0f) + 1e-5f);
    float4 gg = ((const float4*)gamma)[lane];
    float4 bt = ((const float4*)beta)[lane];
    outp[(size_t)w * 32 + lane] = make_float4(dx * rstd * gg.x + bt.x,
                                              dy * rstd * gg.y + bt.y,
                                              dz * rstd * gg.z + bt.z,
                                              dw * rstd * gg.w + bt.w);
}

// ======== FUSED double GEMM (fp16 2-term split HMMA; x1 stays in smem) ========
// h2 = (LN(relu(agg @ W1 + b1)) ) @ W2 * dinv   — one persistent kernel.
// TILE_M=32 rows/tile, 512 threads = 16 warps = 16 col groups.

__device__ __forceinline__ void mma16816(float& c0, float& c1, float& c2, float& c3,
                                         uint32_t a0, uint32_t a1, uint32_t a2, uint32_t a3,
                                         uint32_t b0, uint32_t b1) {
    asm volatile(
        "mma.sync.aligned.m16n8k16.row.col.f32.f16.f16.f32 "
        "{%0,%1,%2,%3}, {%4,%5,%6,%7}, {%8,%9}, {%0,%1,%2,%3};"
        : "+f"(c0), "+f"(c1), "+f"(c2), "+f"(c3)
        : "r"(a0), "r"(a1), "r"(a2), "r"(a3), "r"(b0), "r"(b1));
}
__device__ __forceinline__ void ldm_x4(uint32_t addr, uint32_t& r0, uint32_t& r1,
                                       uint32_t& r2, uint32_t& r3) {
    asm volatile("ldmatrix.sync.aligned.m8n8.x4.shared.b16 {%0,%1,%2,%3}, [%4];"
                 : "=r"(r0), "=r"(r1), "=r"(r2), "=r"(r3) : "r"(addr));
}
__device__ __forceinline__ void ldm_x2(uint32_t addr, uint32_t& r0, uint32_t& r1) {
    asm volatile("ldmatrix.sync.aligned.m8n8.x2.shared.b16 {%0,%1}, [%2];"
                 : "=r"(r0), "=r"(r1) : "r"(addr));
}
__device__ __forceinline__ uint32_t smem_u32(const void* p) {
    return (uint32_t)__cvta_generic_to_shared(p);
}

// smem layout (bytes):
//   W1h : 256*136*2 = 69632      (W1 as [n][k], ST1=136)
//   W2h : 128*264*2 = 67584      (W2 as [n][k], ST2=264)
//   Ah  : 32*136*2  =  8704
//   Al  : 32*136*2  =  8704
//   X1h : 32*264*2  = 16896
//   X1l : 32*264*2  = 16896
//   s_sum/s_sq: 2*32*16*4 = 4096
#define ST1 136
#define ST2 264
__global__ void __launch_bounds__(512, 1)
k_gemm_fused(const float* __restrict__ W1, const float* __restrict__ b1,
             const float* __restrict__ g1, const float* __restrict__ be1,
             const float* __restrict__ W2, int M)
{
    extern __shared__ char sm[];
    __half* W1h = (__half*)sm;
    __half* W2h = (__half*)(sm + 69632);
    __half* Ah  = (__half*)(sm + 69632 + 67584);
    __half* Al  = (__half*)(sm + 69632 + 67584 + 8704);
    __half* X1h = (__half*)(sm + 69632 + 67584 + 2 * 8704);
    __half* X1l = (__half*)(sm + 69632 + 67584 + 2 * 8704 + 16896);
    float* s_sum = (float*)(sm + 69632 + 67584 + 2 * 8704 + 2 * 16896);
    float* s_sq  = s_sum + 32 * 16;

    int tid = threadIdx.x, lane = tid & 31, wid = tid >> 5;
    int wc = wid;                        // 16 col groups
    int g = lane >> 2, t = lane & 3;
    int tl = lane >> 3, tr = lane & 7;

    // ---- weight conversion ----
    for (int i = tid; i < 128 * 256; i += 512) {
        int k = i >> 8, n = i & 255;
        W1h[n * ST1 + k] = __float2half_rn(W1[i]);
    }
    for (int i = tid; i < 256 * 128; i += 512) {
        int k = i >> 7, n = i & 127;
        W2h[n * ST2 + k] = __float2half_rn(W2[i]);
    }

    // ---- ldmatrix base addresses ----
    uint32_t a_addr[2];
    #pragma unroll
    for (int rt = 0; rt < 2; rt++) {
        int row = rt * 16 + tr + 8 * (tl & 1);
        a_addr[rt] = smem_u32(Ah) + (uint32_t)((row * ST1 + 8 * (tl >> 1)) * 2);
    }
    const uint32_t aloff = 8704u;
    // W1: x4 per warp covers 2 n-tiles (cols wc*16..wc*16+15)
    uint32_t w1_addr;
    {
        int n = wc * 16 + (tl >> 1) * 8 + tr;
        w1_addr = smem_u32(W1h) + (uint32_t)((n * ST1 + 8 * (tl & 1)) * 2);
    }
    // X1 (gemm2 A operand)
    uint32_t x1_addr[2];
    #pragma unroll
    for (int rt = 0; rt < 2; rt++) {
        int row = rt * 16 + tr + 8 * (tl & 1);
        x1_addr[rt] = smem_u32(X1h) + (uint32_t)((row * ST2 + 8 * (tl >> 1)) * 2);
    }
    const uint32_t xloff = 16896u;
    // W2: x2 per warp covers 1 n-tile (cols wc*8..wc*8+7); lanes 0-15 give addrs
    uint32_t w2_addr;
    {
        int n = wc * 8 + tr;
        w2_addr = smem_u32(W2h) + (uint32_t)((n * ST2 + 8 * (tl & 1)) * 2);
    }

    // ---- A prefetch (1 uint4 per thread per matrix) ----
    uint4 pf_h, pf_l;
    const uint4 zero4 = make_uint4(0, 0, 0, 0);
    int m0 = blockIdx.x * 32;
    {
        int r = tid >> 4, c8 = (tid & 15) << 3;
        int row = m0 + r;
        bool ok = row < M;
        pf_h = ok ? *(const uint4*)(g_ah + (size_t)row * 128 + c8) : zero4;
        pf_l = ok ? *(const uint4*)(g_al + (size_t)row * 128 + c8) : zero4;
    }

    for (; m0 < M; m0 += gridDim.x * 32) {
        __syncthreads();
        {
            int r = tid >> 4, c8 = (tid & 15) << 3;
            *(uint4*)(Ah + r * ST1 + c8) = pf_h;
            *(uint4*)(Al + r * ST1 + c8) = pf_l;
        }
        __syncthreads();

        int m1 = m0 + gridDim.x * 32;
        if (m1 < M) {
            int r = tid >> 4, c8 = (tid & 15) << 3;
            int row = m1 + r;
            bool ok = row < M;
            pf_h = ok ? *(const uint4*)(g_ah + (size_t)row * 128 + c8) : zero4;
            pf_l = ok ? *(const uint4*)(g_al + (size_t)row * 128 + c8) : zero4;
        }

        // ================= GEMM1: x1 = A @ W1 =================
        float acc[2][2][4];
        #pragma unroll
        for (int rt = 0; rt < 2; rt++)
            #pragma unroll
            for (int nt = 0; nt < 2; nt++)
                #pragma unroll
                for (int q = 0; q < 4; q++) acc[rt][nt][q] = 0.f;

        #pragma unroll
        for (int kt = 0; kt < 8; kt++) {
            uint32_t koff = (uint32_t)kt * 32u;
            uint32_t ah[2][4], al[2][4], wb[4];
            #pragma unroll
            for (int rt = 0; rt < 2; rt++) {
                ldm_x4(a_addr[rt] + koff, ah[rt][0], ah[rt][1], ah[rt][2], ah[rt][3]);
                ldm_x4(a_addr[rt] + koff + aloff, al[rt][0], al[rt][1], al[rt][2], al[rt][3]);
            }
            ldm_x4(w1_addr + koff, wb[0], wb[1], wb[2], wb[3]);
            #pragma unroll
            for (int nt = 0; nt < 2; nt++) {
                uint32_t b0 = wb[nt * 2], b1 = wb[nt * 2 + 1];
                #pragma unroll
                for (int rt = 0; rt < 2; rt++) {
                    float* c = acc[rt][nt];
                    mma16816(c[0], c[1], c[2], c[3],
                             ah[rt][0], ah[rt][1], ah[rt][2], ah[rt][3], b0, b1);
                    mma16816(c[0], c[1], c[2], c[3],
                             al[rt][0], al[rt][1], al[rt][2], al[rt][3], b0, b1);
                }
            }
        }

        // ---- epilogue1: bias + ReLU + LayerNorm(256) -> X1 smem (fp16 hi/lo) ----
        #pragma unroll
        for (int rt = 0; rt < 2; rt++) {
            float s0 = 0.f, s1 = 0.f, q0 = 0.f, q1 = 0.f;
            #pragma unroll
            for (int nt = 0; nt < 2; nt++) {
                int c0 = wc * 16 + nt * 8 + 2 * t;
                float b0 = b1[c0], b1v = b1[c0 + 1];
                float* c = acc[rt][nt];
                c[0] = fmaxf(c[0] + b0, 0.f);
                c[1] = fmaxf(c[1] + b1v, 0.f);
                c[2] = fmaxf(c[2] + b0, 0.f);
                c[3] = fmaxf(c[3] + b1v, 0.f);
                s0 += c[0] + c[1]; q0 += c[0] * c[0] + c[1] * c[1];
                s1 += c[2] + c[3]; q1 += c[2] * c[2] + c[3] * c[3];
            }
            #pragma unroll
            for (int off = 1; off <= 2; off <<= 1) {
                s0 += __shfl_xor_sync(0xffffffffu, s0, off);
                q0 += __shfl_xor_sync(0xffffffffu, q0, off);
                s1 += __shfl_xor_sync(0xffffffffu, s1, off);
                q1 += __shfl_xor_sync(0xffffffffu, q1, off);
            }
            if (t == 0) {
                int lr = rt * 16 + g;
                s_sum[lr * 16 + wc] = s0; s_sq[lr * 16 + wc] = q0;
                s_sum[(lr + 8) * 16 + wc] = s1; s_sq[(lr + 8) * 16 + wc] = q1;
            }
        }
        __syncthreads();
        #pragma unroll
        for (int rt = 0; rt < 2; rt++) {
            int lr0 = rt * 16 + g;
            float ts0 = 0.f, tq0 = 0.f, ts1 = 0.f, tq1 = 0.f;
            #pragma unroll
            for (int j = 0; j < 16; j += 4) {
                float4 a0 = *(const float4*)(s_sum + lr0 * 16 + j);
                float4 b0v = *(const float4*)(s_sq + lr0 * 16 + j);
                float4 a1 = *(const float4*)(s_sum + (lr0 + 8) * 16 + j);
                float4 b1q = *(const float4*)(s_sq + (lr0 + 8) * 16 + j);
                ts0 += (a0.x + a0.y) + (a0.z + a0.w);
                tq0 += (b0v.x + b0v.y) + (b0v.z + b0v.w);
                ts1 += (a1.x + a1.y) + (a1.z + a1.w);
                tq1 += (b1q.x + b1q.y) + (b1q.z + b1q.w);
            }
            float mu0 = ts0 * (1.f / 256.f);
            float mu1 = ts1 * (1.f / 256.f);
            float v0 = tq0 * (1.f / 256.f) - mu0 * mu0;
            float v1 = tq1 * (1.f / 256.f) - mu1 * mu1;
            float rs0 = rsqrtf(v0 + 1e-5f), rs1 = rsqrtf(v1 + 1e-5f);
            #pragma unroll
            for (int nt = 0; nt < 2; nt++) {
                int c0 = wc * 16 + nt * 8 + 2 * t;
                float ga0 = g1[c0], ga1 = g1[c0 + 1];
                float be0 = be1[c0], be1v = be1[c0 + 1];
                float* c = acc[rt][nt];
                float o0 = (c[0] - mu0) * rs0 * ga0 + be0;
                float o1 = (c[1] - mu0) * rs0 * ga1 + be1v;
                float o2 = (c[2] - mu1) * rs1 * ga0 + be0;
                float o3 = (c[3] - mu1) * rs1 * ga1 + be1v;
                __half h0 = __float2half_rn(o0), h1 = __float2half_rn(o1);
                __half h2 = __float2half_rn(o2), h3 = __float2half_rn(o3);
                *(uint32_t*)(X1h + lr0 * ST2 + c0) = h2pack(h0, h1);
                *(uint32_t*)(X1l + lr0 * ST2 + c0) =
                    h2pack(__float2half_rn(o0 - __half2float(h0)),
                           __float2half_rn(o1 - __half2float(h1)));
                *(uint32_t*)(X1h + (lr0 + 8) * ST2 + c0) = h2pack(h2, h3);
                *(uint32_t*)(X1l + (lr0 + 8) * ST2 + c0) =
                    h2pack(__float2half_rn(o2 - __half2float(h2)),
                           __float2half_rn(o3 - __half2float(h3)));
            }
        }
        __syncthreads();

        // ================= GEMM2: h2 = x1 @ W2 =================
        float acc2[2][4];
        #pragma unroll
        for (int rt = 0; rt < 2; rt++)
            #pragma unroll
            for (int q = 0; q < 4; q++) acc2[rt][q] = 0.f;

        #pragma unroll
        for (int kt = 0; kt < 16; kt++) {
            uint32_t koff = (uint32_t)kt * 32u;
            uint32_t xh[2][4], xl[2][4], b0, b1v;
            #pragma unroll
            for (int rt = 0; rt < 2; rt++) {
                ldm_x4(x1_addr[rt] + koff, xh[rt][0], xh[rt][1], xh[rt][2], xh[rt][3]);
                ldm_x4(x1_addr[rt] + koff + xloff, xl[rt][0], xl[rt][1], xl[rt][2], xl[rt][3]);
            }
            ldm_x2(w2_addr + koff, b0, b1v);
            #pragma unroll
            for (int rt = 0; rt < 2; rt++) {
                float* c = acc2[rt];
                mma16816(c[0], c[1], c[2], c[3],
                         xh[rt][0], xh[rt][1], xh[rt][2], xh[rt][3], b0, b1v);
                mma16816(c[0], c[1], c[2], c[3],
                         xl[rt][0], xl[rt][1], xl[rt][2], xl[rt][3], b0, b1v);
            }
        }

        // ---- epilogue2: * dinv -> g_h2 ----
        #pragma unroll
        for (int rt = 0; rt < 2; rt++) {
            int lr0 = rt * 16 + g;
            int row0 = m0 + lr0, row1 = row0 + 8;
            float d0 = (row0 < M) ? g_dinv[row0] : 0.f;
            float d1 = (row1 < M) ? g_dinv[row1] : 0.f;
            int c0 = wc * 8 + 2 * t;
            float* c = acc2[rt];
            if (row0 < M)
                *(float2*)(g_h2 + (size_t)row0 * 128 + c0) = make_float2(c[0] * d0, c[1] * d0);
            if (row1 < M)
                *(float2*)(g_h2 + (size_t)row1 * 128 + c0) = make_float2(c[2] * d1, c[3] * d1);
        }
    }
}

// ---------------- launch ----------------
extern "C" void kernel_launch(void* const* d_in, const int* in_sizes, int n_in,
                              void* d_out, int out_size) {
    const int*   x_ids = (const int*)d_in[0];
    const int*   ei    = (const int*)d_in[1];
    const float* embed = (const float*)d_in[2];
    const float* W1    = (const float*)d_in[3];
    const float* b1    = (const float*)d_in[4];
    const float* g1    = (const float*)d_in[5];
    const float* be1   = (const float*)d_in[6];
    const float* W2    = (const float*)d_in[7];
    const float* b2    = (const float*)d_in[8];
    const float* g2    = (const float*)d_in[9];
    const float* be2   = (const float*)d_in[10];
    float* out = (float*)d_out;

    int n = in_sizes[0];        // 50000
    int E = in_sizes[1] / 2;    // 800000
    const int* src = ei;
    const int* dst = ei + E;

    const int SMEMSZ = 69632 + 67584 + 2 * 8704 + 2 * 16896 + 4096;   // 192512
    cudaFuncSetAttribute((const void*)k_gemm_fused,
                         cudaFuncAttributeMaxDynamicSharedMemorySize, SMEMSZ);

    int nb = (n + 1023) / 1024;
    int warps_grid = (n * 32 + 255) / 256;

    void* p_cnt = nullptr;  cudaGetSymbolAddress(&p_cnt, g_cnt);
    void* p_flag = nullptr; cudaGetSymbolAddress(&p_flag, g_bflag);
    cudaMemsetAsync(p_cnt, 0, (size_t)n * sizeof(int), 0);
    cudaMemsetAsync(p_flag, 0, 64 * sizeof(int), 0);

    k_histscan<<<nb, 1024>>>(dst, n, E);                       // kernel 0
    k_fill<<<(E + 255) / 256, 256>>>(src, dst, x_ids, E);      // kernel 1

    k_agg0<<<warps_grid, 256>>>(x_ids, (const float4*)embed, n);      // kernel 2
    k_gemm_fused<<<152, 512, SMEMSZ>>>(W1, b1, g1, be1, W2, n);       // kernel 3 (ncu)

    k_agg1<<<warps_grid, 256>>>(b2, g2, be2, (float4*)out, n);        // kernel 4
}

// round 13
// speedup vs baseline: 1.7184x; 1.0798x over previous
#include <cuda_runtime.h>
#include <cuda_fp16.h>
#include <cstdint>

#define NMAX 50000
#define EMAX 800000

// ---------------- scratch ----------------
__device__ __half g_ah[(size_t)NMAX * 128];    // layer-1 agg output, fp16 hi
__device__ __half g_al[(size_t)NMAX * 128];    // layer-1 agg output, fp16 lo
__device__ float g_h2[(size_t)NMAX * 128];
__device__ float g_dinv[NMAX];
__device__ int   g_cnt[NMAX];
__device__ int   g_rowptr[NMAX + 1];
__device__ int   g_fill[NMAX];
__device__ int4  g_cols[EMAX];
__device__ int   g_bsum[64];
__device__ int   g_bflag[64];

// ---------------- CSR build ----------------
__global__ void k_histscan(const int* __restrict__ dst, int n, int E) {
    __shared__ int sh[1024];
    __shared__ int s_off;
    int tid = threadIdx.x, b = blockIdx.x;
    int i0 = b * 1024 + tid;

    for (int i = i0; i < E; i += gridDim.x * 1024)
        atomicAdd(&g_cnt[dst[i]], 1);
    __threadfence();
    __syncthreads();
    if (tid == 0) {
        atomicAdd(&g_bflag[50], 1);
        while (((volatile int*)g_bflag)[50] < (int)gridDim.x) { }
    }
    __syncthreads();

    int c = (i0 < n) ? g_cnt[i0] : 0;
    sh[tid] = c;
    __syncthreads();
    for (int off = 1; off < 1024; off <<= 1) {
        int t = (tid >= off) ? sh[tid - off] : 0;
        __syncthreads();
        sh[tid] += t;
        __syncthreads();
    }
    if (tid == 1023) {
        g_bsum[b] = sh[1023];
        __threadfence();
        g_bflag[b] = 1;
    }
    if (tid == 0) {
        int off = 0;
        for (int j = 0; j < b; j++) {
            while (((volatile int*)g_bflag)[j] == 0) { }
            off += ((volatile int*)g_bsum)[j];
        }
        s_off = off;
    }
    __syncthreads();
    if (i0 < n) {
        int incl = sh[tid] + s_off;
        int excl = incl - c;
        g_rowptr[i0] = excl;
        g_fill[i0] = excl;
        g_dinv[i0] = rsqrtf((float)(c + 1));
    }
    if (i0 == 0) g_rowptr[n] = E;
}

__global__ void k_fill(const int* __restrict__ src, const int* __restrict__ dst,
                       const int* __restrict__ x_ids, int E) {
    int i = blockIdx.x * blockDim.x + threadIdx.x;
    if (i < E) {
        int s = src[i];
        int d = dst[i];
        int pos = atomicAdd(&g_fill[d], 1);
        g_cols[pos] = make_int4(x_ids[s], __float_as_int(g_dinv[s]), s, 0);
    }
}

__device__ __forceinline__ uint32_t h2pack(__half a, __half b) {
    return (uint32_t)__half_as_ushort(a) | ((uint32_t)__half_as_ushort(b) << 16);
}

// ---------------- layer-1 aggregation (writes fp16 hi/lo split) ----------------
__global__ void __launch_bounds__(256, 6)
k_agg0(const int* __restrict__ x_ids, const float4* __restrict__ embed, int n) {
    int t = blockIdx.x * blockDim.x + threadIdx.x;
    int w = t >> 5, lane = t & 31;
    if (w >= n) return;
    float diw = g_dinv[w];
    int sid = x_ids[w];
    float4 sv = embed[(size_t)sid * 32 + lane];
    float4 acc = make_float4(sv.x * diw, sv.y * diw, sv.z * diw, sv.w * diw);
    int s = g_rowptr[w], e = g_rowptr[w + 1];
    for (int p = s; p < e; p += 4) {
        int mm = e - p;
        float dj[4]; float4 vv[4];
        #pragma unroll
        for (int u = 0; u < 4; u++) {
            bool ok = u < mm;
            int4 c = g_cols[ok ? p + u : p];
            dj[u] = ok ? __int_as_float(c.y) : 0.f;
            vv[u] = embed[(size_t)c.x * 32 + lane];
        }
        #pragma unroll
        for (int u = 0; u < 4; u++) {
            acc.x = fmaf(vv[u].x, dj[u], acc.x);
            acc.y = fmaf(vv[u].y, dj[u], acc.y);
            acc.z = fmaf(vv[u].z, dj[u], acc.z);
            acc.w = fmaf(vv[u].w, dj[u], acc.w);
        }
    }
    float4 o = make_float4(acc.x * diw, acc.y * diw, acc.z * diw, acc.w * diw);
    __half h0 = __float2half_rn(o.x), h1 = __float2half_rn(o.y);
    __half h2 = __float2half_rn(o.z), h3 = __float2half_rn(o.w);
    uint2 hp, lp;
    hp.x = h2pack(h0, h1); hp.y = h2pack(h2, h3);
    lp.x = h2pack(__float2half_rn(o.x - __half2float(h0)), __float2half_rn(o.y - __half2float(h1)));
    lp.y = h2pack(__float2half_rn(o.z - __half2float(h2)), __float2half_rn(o.w - __half2float(h3)));
    *(uint2*)(g_ah + (size_t)w * 128 + lane * 4) = hp;
    *(uint2*)(g_al + (size_t)w * 128 + lane * 4) = lp;
}

// ---------------- layer-2 aggregation + bias + LayerNorm ----------------
__global__ void __launch_bounds__(256, 6)
k_agg1(const float* __restrict__ b, const float* __restrict__ gamma,
       const float* __restrict__ beta, float4* __restrict__ outp, int n) {
    int t = blockIdx.x * blockDim.x + threadIdx.x;
    int w = t >> 5, lane = t & 31;
    if (w >= n) return;
    const float4* xs = (const float4*)g_h2;
    float4 acc = xs[(size_t)w * 32 + lane];
    int s = g_rowptr[w], e = g_rowptr[w + 1];
    for (int p = s; p < e; p += 4) {
        int mm = e - p;
        float dj[4]; float4 vv[4];
        #pragma unroll
        for (int u = 0; u < 4; u++) {
            bool ok = u < mm;
            int4 c = g_cols[ok ? p + u : p];
            dj[u] = ok ? 1.f : 0.f;
            vv[u] = xs[(size_t)c.z * 32 + lane];
        }
        #pragma unroll
        for (int u = 0; u < 4; u++) {
            acc.x = fmaf(vv[u].x, dj[u], acc.x);
            acc.y = fmaf(vv[u].y, dj[u], acc.y);
            acc.z = fmaf(vv[u].z, dj[u], acc.z);
            acc.w = fmaf(vv[u].w, dj[u], acc.w);
        }
    }
    float di = g_dinv[w];
    float4 bb = ((const float4*)b)[lane];
    float4 y = make_float4(acc.x * di + bb.x, acc.y * di + bb.y,
                           acc.z * di + bb.z, acc.w * di + bb.w);
    float s1 = y.x + y.y + y.z + y.w;
    #pragma unroll
    for (int off = 16; off; off >>= 1) s1 += __shfl_xor_sync(0xffffffffu, s1, off);
    float mu = s1 * (1.0f / 128.0f);
    float dx = y.x - mu, dy = y.y - mu, dz = y.z - mu, dw = y.w - mu;
    float sq = dx * dx + dy * dy + dz * dz + dw * dw;
    #pragma unroll
    for (int off = 16; off; off >>= 1) sq += __shfl_xor_sync(0xffffffffu, sq, off);
    float rstd = rsqrtf(sq * (1.0f / 128.0f) + 1e-5f);
    float4 gg = ((const float4*)gamma)[lane];
    float4 bt = ((const float4*)beta)[lane];
    outp[(size_t)w * 32 + lane] = make_float4(dx * rstd * gg.x + bt.x,
                                              dy * rstd * gg.y + bt.y,
                                              dz * rstd * gg.z + bt.z,
                                              dw * rstd * gg.w + bt.w);
}

// ======== FUSED double GEMM (fp16 split HMMA; x1 hi-only in smem for GEMM2) ========

__device__ __forceinline__ void mma16816(float& c0, float& c1, float& c2, float& c3,
                                         uint32_t a0, uint32_t a1, uint32_t a2, uint32_t a3,
                                         uint32_t b0, uint32_t b1) {
    asm volatile(
        "mma.sync.aligned.m16n8k16.row.col.f32.f16.f16.f32 "
        "{%0,%1,%2,%3}, {%4,%5,%6,%7}, {%8,%9}, {%0,%1,%2,%3};"
        : "+f"(c0), "+f"(c1), "+f"(c2), "+f"(c3)
        : "r"(a0), "r"(a1), "r"(a2), "r"(a3), "r"(b0), "r"(b1));
}
__device__ __forceinline__ void ldm_x4(uint32_t addr, uint32_t& r0, uint32_t& r1,
                                       uint32_t& r2, uint32_t& r3) {
    asm volatile("ldmatrix.sync.aligned.m8n8.x4.shared.b16 {%0,%1,%2,%3}, [%4];"
                 : "=r"(r0), "=r"(r1), "=r"(r2), "=r"(r3) : "r"(addr));
}
__device__ __forceinline__ void ldm_x2(uint32_t addr, uint32_t& r0, uint32_t& r1) {
    asm volatile("ldmatrix.sync.aligned.m8n8.x2.shared.b16 {%0,%1}, [%2];"
                 : "=r"(r0), "=r"(r1) : "r"(addr));
}
__device__ __forceinline__ uint32_t smem_u32(const void* p) {
    return (uint32_t)__cvta_generic_to_shared(p);
}

// smem layout (bytes):
//   W1h : 256*136*2 = 69632
//   W2h : 128*264*2 = 67584
//   Ah  : 32*136*2  =  8704
//   Al  : 32*136*2  =  8704
//   X1h : 32*264*2  = 16896   (hi only — lo dropped for GEMM2)
//   s_sum/s_sq: 2*32*16*4 = 4096
#define ST1 136
#define ST2 264
__global__ void __launch_bounds__(512, 1)
k_gemm_fused(const float* __restrict__ W1, const float* __restrict__ b1,
             const float* __restrict__ g1, const float* __restrict__ be1,
             const float* __restrict__ W2, int M)
{
    extern __shared__ char sm[];
    __half* W1h = (__half*)sm;
    __half* W2h = (__half*)(sm + 69632);
    __half* Ah  = (__half*)(sm + 69632 + 67584);
    __half* Al  = (__half*)(sm + 69632 + 67584 + 8704);
    __half* X1h = (__half*)(sm + 69632 + 67584 + 2 * 8704);
    float* s_sum = (float*)(sm + 69632 + 67584 + 2 * 8704 + 16896);
    float* s_sq  = s_sum + 32 * 16;

    int tid = threadIdx.x, lane = tid & 31, wid = tid >> 5;
    int wc = wid;                        // 16 col groups
    int g = lane >> 2, t = lane & 3;
    int tl = lane >> 3, tr = lane & 7;

    // ---- weight conversion ----
    for (int i = tid; i < 128 * 256; i += 512) {
        int k = i >> 8, n = i & 255;
        W1h[n * ST1 + k] = __float2half_rn(W1[i]);
    }
    for (int i = tid; i < 256 * 128; i += 512) {
        int k = i >> 7, n = i & 127;
        W2h[n * ST2 + k] = __float2half_rn(W2[i]);
    }

    // ---- ldmatrix base addresses ----
    uint32_t a_addr[2];
    #pragma unroll
    for (int rt = 0; rt < 2; rt++) {
        int row = rt * 16 + tr + 8 * (tl & 1);
        a_addr[rt] = smem_u32(Ah) + (uint32_t)((row * ST1 + 8 * (tl >> 1)) * 2);
    }
    const uint32_t aloff = 8704u;
    uint32_t w1_addr;
    {
        int n = wc * 16 + (tl >> 1) * 8 + tr;
        w1_addr = smem_u32(W1h) + (uint32_t)((n * ST1 + 8 * (tl & 1)) * 2);
    }
    uint32_t x1_addr[2];
    #pragma unroll
    for (int rt = 0; rt < 2; rt++) {
        int row = rt * 16 + tr + 8 * (tl & 1);
        x1_addr[rt] = smem_u32(X1h) + (uint32_t)((row * ST2 + 8 * (tl >> 1)) * 2);
    }
    uint32_t w2_addr;
    {
        int n = wc * 8 + tr;
        w2_addr = smem_u32(W2h) + (uint32_t)((n * ST2 + 8 * (tl & 1)) * 2);
    }

    // ---- A prefetch (1 uint4 per thread per matrix) ----
    uint4 pf_h, pf_l;
    const uint4 zero4 = make_uint4(0, 0, 0, 0);
    int m0 = blockIdx.x * 32;
    {
        int r = tid >> 4, c8 = (tid & 15) << 3;
        int row = m0 + r;
        bool ok = row < M;
        pf_h = ok ? *(const uint4*)(g_ah + (size_t)row * 128 + c8) : zero4;
        pf_l = ok ? *(const uint4*)(g_al + (size_t)row * 128 + c8) : zero4;
    }

    for (; m0 < M; m0 += gridDim.x * 32) {
        __syncthreads();
        {
            int r = tid >> 4, c8 = (tid & 15) << 3;
            *(uint4*)(Ah + r * ST1 + c8) = pf_h;
            *(uint4*)(Al + r * ST1 + c8) = pf_l;
        }
        __syncthreads();

        int m1 = m0 + gridDim.x * 32;
        if (m1 < M) {
            int r = tid >> 4, c8 = (tid & 15) << 3;
            int row = m1 + r;
            bool ok = row < M;
            pf_h = ok ? *(const uint4*)(g_ah + (size_t)row * 128 + c8) : zero4;
            pf_l = ok ? *(const uint4*)(g_al + (size_t)row * 128 + c8) : zero4;
        }

        // ================= GEMM1: x1 = A @ W1 (2-term) =================
        float acc[2][2][4];
        #pragma unroll
        for (int rt = 0; rt < 2; rt++)
            #pragma unroll
            for (int nt = 0; nt < 2; nt++)
                #pragma unroll
                for (int q = 0; q < 4; q++) acc[rt][nt][q] = 0.f;

        #pragma unroll
        for (int kt = 0; kt < 8; kt++) {
            uint32_t koff = (uint32_t)kt * 32u;
            uint32_t ah[2][4], al[2][4], wb[4];
            #pragma unroll
            for (int rt = 0; rt < 2; rt++) {
                ldm_x4(a_addr[rt] + koff, ah[rt][0], ah[rt][1], ah[rt][2], ah[rt][3]);
                ldm_x4(a_addr[rt] + koff + aloff, al[rt][0], al[rt][1], al[rt][2], al[rt][3]);
            }
            ldm_x4(w1_addr + koff, wb[0], wb[1], wb[2], wb[3]);
            #pragma unroll
            for (int nt = 0; nt < 2; nt++) {
                uint32_t b0 = wb[nt * 2], b1 = wb[nt * 2 + 1];
                #pragma unroll
                for (int rt = 0; rt < 2; rt++) {
                    float* c = acc[rt][nt];
                    mma16816(c[0], c[1], c[2], c[3],
                             ah[rt][0], ah[rt][1], ah[rt][2], ah[rt][3], b0, b1);
                    mma16816(c[0], c[1], c[2], c[3],
                             al[rt][0], al[rt][1], al[rt][2], al[rt][3], b0, b1);
                }
            }
        }

        // ---- epilogue1: bias + ReLU + LayerNorm(256) -> X1 smem (fp16 hi only) ----
        #pragma unroll
        for (int rt = 0; rt < 2; rt++) {
            float s0 = 0.f, s1 = 0.f, q0 = 0.f, q1 = 0.f;
            #pragma unroll
            for (int nt = 0; nt < 2; nt++) {
                int c0 = wc * 16 + nt * 8 + 2 * t;
                float b0 = b1[c0], b1v = b1[c0 + 1];
                float* c = acc[rt][nt];
                c[0] = fmaxf(c[0] + b0, 0.f);
                c[1] = fmaxf(c[1] + b1v, 0.f);
                c[2] = fmaxf(c[2] + b0, 0.f);
                c[3] = fmaxf(c[3] + b1v, 0.f);
                s0 += c[0] + c[1]; q0 += c[0] * c[0] + c[1] * c[1];
                s1 += c[2] + c[3]; q1 += c[2] * c[2] + c[3] * c[3];
            }
            #pragma unroll
            for (int off = 1; off <= 2; off <<= 1) {
                s0 += __shfl_xor_sync(0xffffffffu, s0, off);
                q0 += __shfl_xor_sync(0xffffffffu, q0, off);
                s1 += __shfl_xor_sync(0xffffffffu, s1, off);
                q1 += __shfl_xor_sync(0xffffffffu, q1, off);
            }
            if (t == 0) {
                int lr = rt * 16 + g;
                s_sum[lr * 16 + wc] = s0; s_sq[lr * 16 + wc] = q0;
                s_sum[(lr + 8) * 16 + wc] = s1; s_sq[(lr + 8) * 16 + wc] = q1;
            }
        }
        __syncthreads();
        #pragma unroll
        for (int rt = 0; rt < 2; rt++) {
            int lr0 = rt * 16 + g;
            float ts0 = 0.f, tq0 = 0.f, ts1 = 0.f, tq1 = 0.f;
            #pragma unroll
            for (int j = 0; j < 16; j += 4) {
                float4 a0 = *(const float4*)(s_sum + lr0 * 16 + j);
                float4 b0v = *(const float4*)(s_sq + lr0 * 16 + j);
                float4 a1 = *(const float4*)(s_sum + (lr0 + 8) * 16 + j);
                float4 b1q = *(const float4*)(s_sq + (lr0 + 8) * 16 + j);
                ts0 += (a0.x + a0.y) + (a0.z + a0.w);
                tq0 += (b0v.x + b0v.y) + (b0v.z + b0v.w);
                ts1 += (a1.x + a1.y) + (a1.z + a1.w);
                tq1 += (b1q.x + b1q.y) + (b1q.z + b1q.w);
            }
            float mu0 = ts0 * (1.f / 256.f);
            float mu1 = ts1 * (1.f / 256.f);
            float v0 = tq0 * (1.f / 256.f) - mu0 * mu0;
            float v1 = tq1 * (1.f / 256.f) - mu1 * mu1;
            float rs0 = rsqrtf(v0 + 1e-5f), rs1 = rsqrtf(v1 + 1e-5f);
            #pragma unroll
            for (int nt = 0; nt < 2; nt++) {
                int c0 = wc * 16 + nt * 8 + 2 * t;
                float ga0 = g1[c0], ga1 = g1[c0 + 1];
                float be0 = be1[c0], be1v = be1[c0 + 1];
                float* c = acc[rt][nt];
                float o0 = (c[0] - mu0) * rs0 * ga0 + be0;
                float o1 = (c[1] - mu0) * rs0 * ga1 + be1v;
                float o2 = (c[2] - mu1) * rs1 * ga0 + be0;
                float o3 = (c[3] - mu1) * rs1 * ga1 + be1v;
                *(uint32_t*)(X1h + lr0 * ST2 + c0) =
                    h2pack(__float2half_rn(o0), __float2half_rn(o1));
                *(uint32_t*)(X1h + (lr0 + 8) * ST2 + c0) =
                    h2pack(__float2half_rn(o2), __float2half_rn(o3));
            }
        }
        __syncthreads();

        // ================= GEMM2: h2 = x1 @ W2 (hi-only) =================
        float acc2[2][4];
        #pragma unroll
        for (int rt = 0; rt < 2; rt++)
            #pragma unroll
            for (int q = 0; q < 4; q++) acc2[rt][q] = 0.f;

        #pragma unroll
        for (int kt = 0; kt < 16; kt++) {
            uint32_t koff = (uint32_t)kt * 32u;
            uint32_t xh[2][4], b0, b1v;
            #pragma unroll
            for (int rt = 0; rt < 2; rt++)
                ldm_x4(x1_addr[rt] + koff, xh[rt][0], xh[rt][1], xh[rt][2], xh[rt][3]);
            ldm_x2(w2_addr + koff, b0, b1v);
            #pragma unroll
            for (int rt = 0; rt < 2; rt++) {
                float* c = acc2[rt];
                mma16816(c[0], c[1], c[2], c[3],
                         xh[rt][0], xh[rt][1], xh[rt][2], xh[rt][3], b0, b1v);
            }
        }

        // ---- epilogue2: * dinv -> g_h2 ----
        #pragma unroll
        for (int rt = 0; rt < 2; rt++) {
            int lr0 = rt * 16 + g;
            int row0 = m0 + lr0, row1 = row0 + 8;
            float d0 = (row0 < M) ? g_dinv[row0] : 0.f;
            float d1 = (row1 < M) ? g_dinv[row1] : 0.f;
            int c0 = wc * 8 + 2 * t;
            float* c = acc2[rt];
            if (row0 < M)
                *(float2*)(g_h2 + (size_t)row0 * 128 + c0) = make_float2(c[0] * d0, c[1] * d0);
            if (row1 < M)
                *(float2*)(g_h2 + (size_t)row1 * 128 + c0) = make_float2(c[2] * d1, c[3] * d1);
        }
    }
}

// ---------------- launch ----------------
extern "C" void kernel_launch(void* const* d_in, const int* in_sizes, int n_in,
                              void* d_out, int out_size) {
    const int*   x_ids = (const int*)d_in[0];
    const int*   ei    = (const int*)d_in[1];
    const float* embed = (const float*)d_in[2];
    const float* W1    = (const float*)d_in[3];
    const float* b1    = (const float*)d_in[4];
    const float* g1    = (const float*)d_in[5];
    const float* be1   = (const float*)d_in[6];
    const float* W2    = (const float*)d_in[7];
    const float* b2    = (const float*)d_in[8];
    const float* g2    = (const float*)d_in[9];
    const float* be2   = (const float*)d_in[10];
    float* out = (float*)d_out;

    int n = in_sizes[0];        // 50000
    int E = in_sizes[1] / 2;    // 800000
    const int* src = ei;
    const int* dst = ei + E;

    const int SMEMSZ = 69632 + 67584 + 2 * 8704 + 16896 + 4096;   // 175616
    cudaFuncSetAttribute((const void*)k_gemm_fused,
                         cudaFuncAttributeMaxDynamicSharedMemorySize, SMEMSZ);

    int nb = (n + 1023) / 1024;
    int warps_grid = (n * 32 + 255) / 256;

    void* p_cnt = nullptr;  cudaGetSymbolAddress(&p_cnt, g_cnt);
    void* p_flag = nullptr; cudaGetSymbolAddress(&p_flag, g_bflag);
    cudaMemsetAsync(p_cnt, 0, (size_t)n * sizeof(int), 0);
    cudaMemsetAsync(p_flag, 0, 64 * sizeof(int), 0);

    k_histscan<<<nb, 1024>>>(dst, n, E);                       // kernel 0
    k_fill<<<(E + 255) / 256, 256>>>(src, dst, x_ids, E);      // kernel 1

    k_agg0<<<warps_grid, 256>>>(x_ids, (const float4*)embed, n);      // kernel 2
    k_gemm_fused<<<152, 512, SMEMSZ>>>(W1, b1, g1, be1, W2, n);       // kernel 3 (ncu)

    k_agg1<<<warps_grid, 256>>>(b2, g2, be2, (float4*)out, n);        // kernel 4
}

// round 14
// speedup vs baseline: 1.8806x; 1.0944x over previous
#include <cuda_runtime.h>
#include <cuda_fp16.h>
#include <cstdint>

#define NMAX 50000
#define EMAX 800000

// ---------------- scratch ----------------
__device__ __half g_ah[(size_t)NMAX * 128];    // layer-1 agg output, fp16
__device__ __half g_h2h[(size_t)NMAX * 128];   // layer-2 transformed, fp16
__device__ float g_dinv[NMAX];
__device__ int   g_cnt[NMAX];
__device__ int   g_rowptr[NMAX + 1];
__device__ int   g_fill[NMAX];
__device__ int4  g_cols[EMAX];
__device__ int   g_bsum[64];
__device__ int   g_bflag[64];

// ---------------- CSR build ----------------
__global__ void k_histscan(const int* __restrict__ dst, int n, int E) {
    __shared__ int sh[1024];
    __shared__ int s_off;
    int tid = threadIdx.x, b = blockIdx.x;
    int i0 = b * 1024 + tid;

    for (int i = i0; i < E; i += gridDim.x * 1024)
        atomicAdd(&g_cnt[dst[i]], 1);
    __threadfence();
    __syncthreads();
    if (tid == 0) {
        atomicAdd(&g_bflag[50], 1);
        while (((volatile int*)g_bflag)[50] < (int)gridDim.x) { }
    }
    __syncthreads();

    int c = (i0 < n) ? g_cnt[i0] : 0;
    sh[tid] = c;
    __syncthreads();
    for (int off = 1; off < 1024; off <<= 1) {
        int t = (tid >= off) ? sh[tid - off] : 0;
        __syncthreads();
        sh[tid] += t;
        __syncthreads();
    }
    if (tid == 1023) {
        g_bsum[b] = sh[1023];
        __threadfence();
        g_bflag[b] = 1;
    }
    if (tid == 0) {
        int off = 0;
        for (int j = 0; j < b; j++) {
            while (((volatile int*)g_bflag)[j] == 0) { }
            off += ((volatile int*)g_bsum)[j];
        }
        s_off = off;
    }
    __syncthreads();
    if (i0 < n) {
        int incl = sh[tid] + s_off;
        int excl = incl - c;
        g_rowptr[i0] = excl;
        g_fill[i0] = excl;
        g_dinv[i0] = rsqrtf((float)(c + 1));
    }
    if (i0 == 0) g_rowptr[n] = E;
}

__global__ void k_fill(const int* __restrict__ src, const int* __restrict__ dst,
                       const int* __restrict__ x_ids, int E) {
    int i = blockIdx.x * blockDim.x + threadIdx.x;
    if (i < E) {
        int s = src[i];
        int d = dst[i];
        int pos = atomicAdd(&g_fill[d], 1);
        g_cols[pos] = make_int4(x_ids[s], __float_as_int(g_dinv[s]), s, 0);
    }
}

__device__ __forceinline__ uint32_t h2pack(__half a, __half b) {
    return (uint32_t)__half_as_ushort(a) | ((uint32_t)__half_as_ushort(b) << 16);
}
__device__ __forceinline__ float4 h4unpack(uint2 v) {
    __half2 a = *(__half2*)&v.x, b = *(__half2*)&v.y;
    float2 fa = __half22float2(a), fb = __half22float2(b);
    return make_float4(fa.x, fa.y, fb.x, fb.y);
}

// ---------------- layer-1 aggregation (writes fp16) ----------------
__global__ void __launch_bounds__(256, 6)
k_agg0(const int* __restrict__ x_ids, const float4* __restrict__ embed, int n) {
    int t = blockIdx.x * blockDim.x + threadIdx.x;
    int w = t >> 5, lane = t & 31;
    if (w >= n) return;
    float diw = g_dinv[w];
    int sid = x_ids[w];
    float4 sv = embed[(size_t)sid * 32 + lane];
    float4 acc = make_float4(sv.x * diw, sv.y * diw, sv.z * diw, sv.w * diw);
    int s = g_rowptr[w], e = g_rowptr[w + 1];
    for (int p = s; p < e; p += 4) {
        int mm = e - p;
        float dj[4]; float4 vv[4];
        #pragma unroll
        for (int u = 0; u < 4; u++) {
            bool ok = u < mm;
            int4 c = g_cols[ok ? p + u : p];
            dj[u] = ok ? __int_as_float(c.y) : 0.f;
            vv[u] = embed[(size_t)c.x * 32 + lane];
        }
        #pragma unroll
        for (int u = 0; u < 4; u++) {
            acc.x = fmaf(vv[u].x, dj[u], acc.x);
            acc.y = fmaf(vv[u].y, dj[u], acc.y);
            acc.z = fmaf(vv[u].z, dj[u], acc.z);
            acc.w = fmaf(vv[u].w, dj[u], acc.w);
        }
    }
    float4 o = make_float4(acc.x * diw, acc.y * diw, acc.z * diw, acc.w * diw);
    uint2 hp;
    hp.x = h2pack(__float2half_rn(o.x), __float2half_rn(o.y));
    hp.y = h2pack(__float2half_rn(o.z), __float2half_rn(o.w));
    *(uint2*)(g_ah + (size_t)w * 128 + lane * 4) = hp;
}

// ---------------- layer-2 aggregation + bias + LayerNorm (fp16 h2 input) ----------------
__global__ void __launch_bounds__(256, 6)
k_agg1(const float* __restrict__ b, const float* __restrict__ gamma,
       const float* __restrict__ beta, float4* __restrict__ outp, int n) {
    int t = blockIdx.x * blockDim.x + threadIdx.x;
    int w = t >> 5, lane = t & 31;
    if (w >= n) return;
    const uint2* xs = (const uint2*)g_h2h;   // 4 halves per lane
    float4 acc = h4unpack(xs[(size_t)w * 32 + lane]);
    int s = g_rowptr[w], e = g_rowptr[w + 1];
    for (int p = s; p < e; p += 4) {
        int mm = e - p;
        float dj[4]; float4 vv[4];
        #pragma unroll
        for (int u = 0; u < 4; u++) {
            bool ok = u < mm;
            int4 c = g_cols[ok ? p + u : p];
            dj[u] = ok ? 1.f : 0.f;
            vv[u] = h4unpack(xs[(size_t)c.z * 32 + lane]);
        }
        #pragma unroll
        for (int u = 0; u < 4; u++) {
            acc.x = fmaf(vv[u].x, dj[u], acc.x);
            acc.y = fmaf(vv[u].y, dj[u], acc.y);
            acc.z = fmaf(vv[u].z, dj[u], acc.z);
            acc.w = fmaf(vv[u].w, dj[u], acc.w);
        }
    }
    float di = g_dinv[w];
    float4 bb = ((const float4*)b)[lane];
    float4 y = make_float4(acc.x * di + bb.x, acc.y * di + bb.y,
                           acc.z * di + bb.z, acc.w * di + bb.w);
    float s1 = y.x + y.y + y.z + y.w;
    #pragma unroll
    for (int off = 16; off; off >>= 1) s1 += __shfl_xor_sync(0xffffffffu, s1, off);
    float mu = s1 * (1.0f / 128.0f);
    float dx = y.x - mu, dy = y.y - mu, dz = y.z - mu, dw = y.w - mu;
    float sq = dx * dx + dy * dy + dz * dz + dw * dw;
    #pragma unroll
    for (int off = 16; off; off >>= 1) sq += __shfl_xor_sync(0xffffffffu, sq, off);
    float rstd = rsqrtf(sq * (1.0f / 128.0f) + 1e-5f);
    float4 gg = ((const float4*)gamma)[lane];
    float4 bt = ((const float4*)beta)[lane];
    outp[(size_t)w * 32 + lane] = make_float4(dx * rstd * gg.x + bt.x,
                                              dy * rstd * gg.y + bt.y,
                                              dz * rstd * gg.z + bt.z,
                                              dw * rstd * gg.w + bt.w);
}

// ======== FUSED double GEMM (fp16 HMMA, hi-only operands; x1 stays in smem) ========

__device__ __forceinline__ void mma16816(float& c0, float& c1, float& c2, float& c3,
                                         uint32_t a0, uint32_t a1, uint32_t a2, uint32_t a3,
                                         uint32_t b0, uint32_t b1) {
    asm volatile(
        "mma.sync.aligned.m16n8k16.row.col.f32.f16.f16.f32 "
        "{%0,%1,%2,%3}, {%4,%5,%6,%7}, {%8,%9}, {%0,%1,%2,%3};"
        : "+f"(c0), "+f"(c1), "+f"(c2), "+f"(c3)
        : "r"(a0), "r"(a1), "r"(a2), "r"(a3), "r"(b0), "r"(b1));
}
__device__ __forceinline__ void ldm_x4(uint32_t addr, uint32_t& r0, uint32_t& r1,
                                       uint32_t& r2, uint32_t& r3) {
    asm volatile("ldmatrix.sync.aligned.m8n8.x4.shared.b16 {%0,%1,%2,%3}, [%4];"
                 : "=r"(r0), "=r"(r1), "=r"(r2), "=r"(r3) : "r"(addr));
}
__device__ __forceinline__ void ldm_x2(uint32_t addr, uint32_t& r0, uint32_t& r1) {
    asm volatile("ldmatrix.sync.aligned.m8n8.x2.shared.b16 {%0,%1}, [%2];"
                 : "=r"(r0), "=r"(r1) : "r"(addr));
}
__device__ __forceinline__ uint32_t smem_u32(const void* p) {
    return (uint32_t)__cvta_generic_to_shared(p);
}

// smem layout (bytes):
//   W1h : 256*136*2 = 69632
//   W2h : 128*264*2 = 67584
//   Ah  : 32*136*2  =  8704
//   X1h : 32*264*2  = 16896
//   s_sum/s_sq: 2*32*16*4 = 4096
#define ST1 136
#define ST2 264
__global__ void __launch_bounds__(512, 1)
k_gemm_fused(const float* __restrict__ W1, const float* __restrict__ b1,
             const float* __restrict__ g1, const float* __restrict__ be1,
             const float* __restrict__ W2, int M)
{
    extern __shared__ char sm[];
    __half* W1h = (__half*)sm;
    __half* W2h = (__half*)(sm + 69632);
    __half* Ah  = (__half*)(sm + 69632 + 67584);
    __half* X1h = (__half*)(sm + 69632 + 67584 + 8704);
    float* s_sum = (float*)(sm + 69632 + 67584 + 8704 + 16896);
    float* s_sq  = s_sum + 32 * 16;

    int tid = threadIdx.x, lane = tid & 31, wid = tid >> 5;
    int wc = wid;                        // 16 col groups
    int g = lane >> 2, t = lane & 3;
    int tl = lane >> 3, tr = lane & 7;

    // ---- weight conversion ----
    for (int i = tid; i < 128 * 256; i += 512) {
        int k = i >> 8, n = i & 255;
        W1h[n * ST1 + k] = __float2half_rn(W1[i]);
    }
    for (int i = tid; i < 256 * 128; i += 512) {
        int k = i >> 7, n = i & 127;
        W2h[n * ST2 + k] = __float2half_rn(W2[i]);
    }

    // ---- ldmatrix base addresses ----
    uint32_t a_addr[2];
    #pragma unroll
    for (int rt = 0; rt < 2; rt++) {
        int row = rt * 16 + tr + 8 * (tl & 1);
        a_addr[rt] = smem_u32(Ah) + (uint32_t)((row * ST1 + 8 * (tl >> 1)) * 2);
    }
    uint32_t w1_addr;
    {
        int n = wc * 16 + (tl >> 1) * 8 + tr;
        w1_addr = smem_u32(W1h) + (uint32_t)((n * ST1 + 8 * (tl & 1)) * 2);
    }
    uint32_t x1_addr[2];
    #pragma unroll
    for (int rt = 0; rt < 2; rt++) {
        int row = rt * 16 + tr + 8 * (tl & 1);
        x1_addr[rt] = smem_u32(X1h) + (uint32_t)((row * ST2 + 8 * (tl >> 1)) * 2);
    }
    uint32_t w2_addr;
    {
        int n = wc * 8 + tr;
        w2_addr = smem_u32(W2h) + (uint32_t)((n * ST2 + 8 * (tl & 1)) * 2);
    }

    // ---- A prefetch (1 uint4 per thread) ----
    uint4 pf_h;
    const uint4 zero4 = make_uint4(0, 0, 0, 0);
    int m0 = blockIdx.x * 32;
    {
        int r = tid >> 4, c8 = (tid & 15) << 3;
        int row = m0 + r;
        pf_h = (row < M) ? *(const uint4*)(g_ah + (size_t)row * 128 + c8) : zero4;
    }

    for (; m0 < M; m0 += gridDim.x * 32) {
        __syncthreads();
        {
            int r = tid >> 4, c8 = (tid & 15) << 3;
            *(uint4*)(Ah + r * ST1 + c8) = pf_h;
        }
        __syncthreads();

        int m1 = m0 + gridDim.x * 32;
        if (m1 < M) {
            int r = tid >> 4, c8 = (tid & 15) << 3;
            int row = m1 + r;
            pf_h = (row < M) ? *(const uint4*)(g_ah + (size_t)row * 128 + c8) : zero4;
        }

        // ================= GEMM1: x1 = A @ W1 (hi-only) =================
        float acc[2][2][4];
        #pragma unroll
        for (int rt = 0; rt < 2; rt++)
            #pragma unroll
            for (int nt = 0; nt < 2; nt++)
                #pragma unroll
                for (int q = 0; q < 4; q++) acc[rt][nt][q] = 0.f;

        #pragma unroll
        for (int kt = 0; kt < 8; kt++) {
            uint32_t koff = (uint32_t)kt * 32u;
            uint32_t ah[2][4], wb[4];
            #pragma unroll
            for (int rt = 0; rt < 2; rt++)
                ldm_x4(a_addr[rt] + koff, ah[rt][0], ah[rt][1], ah[rt][2], ah[rt][3]);
            ldm_x4(w1_addr + koff, wb[0], wb[1], wb[2], wb[3]);
            #pragma unroll
            for (int nt = 0; nt < 2; nt++) {
                uint32_t b0 = wb[nt * 2], b1 = wb[nt * 2 + 1];
                #pragma unroll
                for (int rt = 0; rt < 2; rt++) {
                    float* c = acc[rt][nt];
                    mma16816(c[0], c[1], c[2], c[3],
                             ah[rt][0], ah[rt][1], ah[rt][2], ah[rt][3], b0, b1);
                }
            }
        }

        // ---- epilogue1: bias + ReLU + LayerNorm(256) -> X1 smem (fp16) ----
        #pragma unroll
        for (int rt = 0; rt < 2; rt++) {
            float s0 = 0.f, s1 = 0.f, q0 = 0.f, q1 = 0.f;
            #pragma unroll
            for (int nt = 0; nt < 2; nt++) {
                int c0 = wc * 16 + nt * 8 + 2 * t;
                float b0 = b1[c0], b1v = b1[c0 + 1];
                float* c = acc[rt][nt];
                c[0] = fmaxf(c[0] + b0, 0.f);
                c[1] = fmaxf(c[1] + b1v, 0.f);
                c[2] = fmaxf(c[2] + b0, 0.f);
                c[3] = fmaxf(c[3] + b1v, 0.f);
                s0 += c[0] + c[1]; q0 += c[0] * c[0] + c[1] * c[1];
                s1 += c[2] + c[3]; q1 += c[2] * c[2] + c[3] * c[3];
            }
            #pragma unroll
            for (int off = 1; off <= 2; off <<= 1) {
                s0 += __shfl_xor_sync(0xffffffffu, s0, off);
                q0 += __shfl_xor_sync(0xffffffffu, q0, off);
                s1 += __shfl_xor_sync(0xffffffffu, s1, off);
                q1 += __shfl_xor_sync(0xffffffffu, q1, off);
            }
            if (t == 0) {
                int lr = rt * 16 + g;
                s_sum[lr * 16 + wc] = s0; s_sq[lr * 16 + wc] = q0;
                s_sum[(lr + 8) * 16 + wc] = s1; s_sq[(lr + 8) * 16 + wc] = q1;
            }
        }
        __syncthreads();
        #pragma unroll
        for (int rt = 0; rt < 2; rt++) {
            int lr0 = rt * 16 + g;
            float ts0 = 0.f, tq0 = 0.f, ts1 = 0.f, tq1 = 0.f;
            #pragma unroll
            for (int j = 0; j < 16; j += 4) {
                float4 a0 = *(const float4*)(s_sum + lr0 * 16 + j);
                float4 b0v = *(const float4*)(s_sq + lr0 * 16 + j);
                float4 a1 = *(const float4*)(s_sum + (lr0 + 8) * 16 + j);
                float4 b1q = *(const float4*)(s_sq + (lr0 + 8) * 16 + j);
                ts0 += (a0.x + a0.y) + (a0.z + a0.w);
                tq0 += (b0v.x + b0v.y) + (b0v.z + b0v.w);
                ts1 += (a1.x + a1.y) + (a1.z + a1.w);
                tq1 += (b1q.x + b1q.y) + (b1q.z + b1q.w);
            }
            float mu0 = ts0 * (1.f / 256.f);
            float mu1 = ts1 * (1.f / 256.f);
            float v0 = tq0 * (1.f / 256.f) - mu0 * mu0;
            float v1 = tq1 * (1.f / 256.f) - mu1 * mu1;
            float rs0 = rsqrtf(v0 + 1e-5f), rs1 = rsqrtf(v1 + 1e-5f);
            #pragma unroll
            for (int nt = 0; nt < 2; nt++) {
                int c0 = wc * 16 + nt * 8 + 2 * t;
                float ga0 = g1[c0], ga1 = g1[c0 + 1];
                float be0 = be1[c0], be1v = be1[c0 + 1];
                float* c = acc[rt][nt];
                float o0 = (c[0] - mu0) * rs0 * ga0 + be0;
                float o1 = (c[1] - mu0) * rs0 * ga1 + be1v;
                float o2 = (c[2] - mu1) * rs1 * ga0 + be0;
                float o3 = (c[3] - mu1) * rs1 * ga1 + be1v;
                *(uint32_t*)(X1h + lr0 * ST2 + c0) =
                    h2pack(__float2half_rn(o0), __float2half_rn(o1));
                *(uint32_t*)(X1h + (lr0 + 8) * ST2 + c0) =
                    h2pack(__float2half_rn(o2), __float2half_rn(o3));
            }
        }
        __syncthreads();

        // ================= GEMM2: h2 = x1 @ W2 (hi-only) =================
        float acc2[2][4];
        #pragma unroll
        for (int rt = 0; rt < 2; rt++)
            #pragma unroll
            for (int q = 0; q < 4; q++) acc2[rt][q] = 0.f;

        #pragma unroll
        for (int kt = 0; kt < 16; kt++) {
            uint32_t koff = (uint32_t)kt * 32u;
            uint32_t xh[2][4], b0, b1v;
            #pragma unroll
            for (int rt = 0; rt < 2; rt++)
                ldm_x4(x1_addr[rt] + koff, xh[rt][0], xh[rt][1], xh[rt][2], xh[rt][3]);
            ldm_x2(w2_addr + koff, b0, b1v);
            #pragma unroll
            for (int rt = 0; rt < 2; rt++) {
                float* c = acc2[rt];
                mma16816(c[0], c[1], c[2], c[3],
                         xh[rt][0], xh[rt][1], xh[rt][2], xh[rt][3], b0, b1v);
            }
        }

        // ---- epilogue2: * dinv -> g_h2h (fp16) ----
        #pragma unroll
        for (int rt = 0; rt < 2; rt++) {
            int lr0 = rt * 16 + g;
            int row0 = m0 + lr0, row1 = row0 + 8;
            float d0 = (row0 < M) ? g_dinv[row0] : 0.f;
            float d1 = (row1 < M) ? g_dinv[row1] : 0.f;
            int c0 = wc * 8 + 2 * t;
            float* c = acc2[rt];
            if (row0 < M)
                *(uint32_t*)(g_h2h + (size_t)row0 * 128 + c0) =
                    h2pack(__float2half_rn(c[0] * d0), __float2half_rn(c[1] * d0));
            if (row1 < M)
                *(uint32_t*)(g_h2h + (size_t)row1 * 128 + c0) =
                    h2pack(__float2half_rn(c[2] * d1), __float2half_rn(c[3] * d1));
        }
    }
}

// ---------------- launch ----------------
extern "C" void kernel_launch(void* const* d_in, const int* in_sizes, int n_in,
                              void* d_out, int out_size) {
    const int*   x_ids = (const int*)d_in[0];
    const int*   ei    = (const int*)d_in[1];
    const float* embed = (const float*)d_in[2];
    const float* W1    = (const float*)d_in[3];
    const float* b1    = (const float*)d_in[4];
    const float* g1    = (const float*)d_in[5];
    const float* be1   = (const float*)d_in[6];
    const float* W2    = (const float*)d_in[7];
    const float* b2    = (const float*)d_in[8];
    const float* g2    = (const float*)d_in[9];
    const float* be2   = (const float*)d_in[10];
    float* out = (float*)d_out;

    int n = in_sizes[0];        // 50000
    int E = in_sizes[1] / 2;    // 800000
    const int* src = ei;
    const int* dst = ei + E;

    const int SMEMSZ = 69632 + 67584 + 8704 + 16896 + 4096;   // 166912
    cudaFuncSetAttribute((const void*)k_gemm_fused,
                         cudaFuncAttributeMaxDynamicSharedMemorySize, SMEMSZ);

    int nb = (n + 1023) / 1024;
    int warps_grid = (n * 32 + 255) / 256;

    void* p_cnt = nullptr;  cudaGetSymbolAddress(&p_cnt, g_cnt);
    void* p_flag = nullptr; cudaGetSymbolAddress(&p_flag, g_bflag);
    cudaMemsetAsync(p_cnt, 0, (size_t)n * sizeof(int), 0);
    cudaMemsetAsync(p_flag, 0, 64 * sizeof(int), 0);

    k_histscan<<<nb, 1024>>>(dst, n, E);                       // kernel 0
    k_fill<<<(E + 255) / 256, 256>>>(src, dst, x_ids, E);      // kernel 1

    k_agg0<<<warps_grid, 256>>>(x_ids, (const float4*)embed, n);      // kernel 2
    k_gemm_fused<<<152, 512, SMEMSZ>>>(W1, b1, g1, be1, W2, n);       // kernel 3 (ncu)

    k_agg1<<<warps_grid, 256>>>(b2, g2, be2, (float4*)out, n);        // kernel 4
}

// round 15
// speedup vs baseline: 1.9658x; 1.0454x over previous
#include <cuda_runtime.h>
#include <cuda_fp16.h>
#include <cstdint>

#define NMAX 50000
#define EMAX 800000

// ---------------- scratch ----------------
__device__ __half g_embh[(size_t)NMAX * 128];  // fp16 copy of embedding table
__device__ __half g_ah[(size_t)NMAX * 128];    // layer-1 agg output, fp16
__device__ __half g_h2h[(size_t)NMAX * 128];   // layer-2 transformed, fp16
__device__ float g_dinv[NMAX];
__device__ int   g_cnt[NMAX];
__device__ int   g_rowptr[NMAX + 1];
__device__ int   g_fill[NMAX];
__device__ int4  g_cols[EMAX];
__device__ int   g_bsum[64];
__device__ int   g_bflag[64];

__device__ __forceinline__ uint32_t h2pack(__half a, __half b) {
    return (uint32_t)__half_as_ushort(a) | ((uint32_t)__half_as_ushort(b) << 16);
}
__device__ __forceinline__ float4 h4unpack(uint2 v) {
    __half2 a = *(__half2*)&v.x, b = *(__half2*)&v.y;
    float2 fa = __half22float2(a), fb = __half22float2(b);
    return make_float4(fa.x, fa.y, fb.x, fb.y);
}

// ---------------- CSR build + embed fp16 conversion (fused) ----------------
__global__ void k_histscan(const int* __restrict__ dst, const float4* __restrict__ embed,
                           int n, int E) {
    __shared__ int sh[1024];
    __shared__ int s_off;
    int tid = threadIdx.x, b = blockIdx.x;
    int i0 = b * 1024 + tid;
    int gstride = gridDim.x * 1024;

    // embed fp32 -> fp16 (overlaps the atomic histogram)
    for (int i = i0; i < n * 32; i += gstride) {
        float4 v = embed[i];
        uint2 hp;
        hp.x = h2pack(__float2half_rn(v.x), __float2half_rn(v.y));
        hp.y = h2pack(__float2half_rn(v.z), __float2half_rn(v.w));
        ((uint2*)g_embh)[i] = hp;
    }
    for (int i = i0; i < E; i += gstride)
        atomicAdd(&g_cnt[dst[i]], 1);
    __threadfence();
    __syncthreads();
    if (tid == 0) {
        atomicAdd(&g_bflag[50], 1);
        while (((volatile int*)g_bflag)[50] < (int)gridDim.x) { }
    }
    __syncthreads();

    int c = (i0 < n) ? g_cnt[i0] : 0;
    sh[tid] = c;
    __syncthreads();
    for (int off = 1; off < 1024; off <<= 1) {
        int t = (tid >= off) ? sh[tid - off] : 0;
        __syncthreads();
        sh[tid] += t;
        __syncthreads();
    }
    if (tid == 1023) {
        g_bsum[b] = sh[1023];
        __threadfence();
        g_bflag[b] = 1;
    }
    if (tid == 0) {
        int off = 0;
        for (int j = 0; j < b; j++) {
            while (((volatile int*)g_bflag)[j] == 0) { }
            off += ((volatile int*)g_bsum)[j];
        }
        s_off = off;
    }
    __syncthreads();
    if (i0 < n) {
        int incl = sh[tid] + s_off;
        int excl = incl - c;
        g_rowptr[i0] = excl;
        g_fill[i0] = excl;
        g_dinv[i0] = rsqrtf((float)(c + 1));
    }
    if (i0 == 0) g_rowptr[n] = E;
}

__global__ void k_fill(const int* __restrict__ src, const int* __restrict__ dst,
                       const int* __restrict__ x_ids, int E) {
    int i = blockIdx.x * blockDim.x + threadIdx.x;
    if (i < E) {
        int s = src[i];
        int d = dst[i];
        int pos = atomicAdd(&g_fill[d], 1);
        g_cols[pos] = make_int4(x_ids[s], __float_as_int(g_dinv[s]), s, 0);
    }
}

// ---------------- layer-1 aggregation (fp16 embed in, fp16 out) ----------------
__global__ void __launch_bounds__(256, 6)
k_agg0(const int* __restrict__ x_ids, int n) {
    int t = blockIdx.x * blockDim.x + threadIdx.x;
    int w = t >> 5, lane = t & 31;
    if (w >= n) return;
    const uint2* embh = (const uint2*)g_embh;
    float diw = g_dinv[w];
    int sid = x_ids[w];
    float4 sv = h4unpack(embh[(size_t)sid * 32 + lane]);
    float4 acc = make_float4(sv.x * diw, sv.y * diw, sv.z * diw, sv.w * diw);
    int s = g_rowptr[w], e = g_rowptr[w + 1];
    for (int p = s; p < e; p += 4) {
        int mm = e - p;
        float dj[4]; float4 vv[4];
        #pragma unroll
        for (int u = 0; u < 4; u++) {
            bool ok = u < mm;
            int4 c = g_cols[ok ? p + u : p];
            dj[u] = ok ? __int_as_float(c.y) : 0.f;
            vv[u] = h4unpack(embh[(size_t)c.x * 32 + lane]);
        }
        #pragma unroll
        for (int u = 0; u < 4; u++) {
            acc.x = fmaf(vv[u].x, dj[u], acc.x);
            acc.y = fmaf(vv[u].y, dj[u], acc.y);
            acc.z = fmaf(vv[u].z, dj[u], acc.z);
            acc.w = fmaf(vv[u].w, dj[u], acc.w);
        }
    }
    float4 o = make_float4(acc.x * diw, acc.y * diw, acc.z * diw, acc.w * diw);
    uint2 hp;
    hp.x = h2pack(__float2half_rn(o.x), __float2half_rn(o.y));
    hp.y = h2pack(__float2half_rn(o.z), __float2half_rn(o.w));
    *(uint2*)(g_ah + (size_t)w * 128 + lane * 4) = hp;
}

// ---------------- layer-2 aggregation + bias + LayerNorm (fp16 h2 input) ----------------
__global__ void __launch_bounds__(256, 6)
k_agg1(const float* __restrict__ b, const float* __restrict__ gamma,
       const float* __restrict__ beta, float4* __restrict__ outp, int n) {
    int t = blockIdx.x * blockDim.x + threadIdx.x;
    int w = t >> 5, lane = t & 31;
    if (w >= n) return;
    const uint2* xs = (const uint2*)g_h2h;
    float4 acc = h4unpack(xs[(size_t)w * 32 + lane]);
    int s = g_rowptr[w], e = g_rowptr[w + 1];
    for (int p = s; p < e; p += 4) {
        int mm = e - p;
        float dj[4]; float4 vv[4];
        #pragma unroll
        for (int u = 0; u < 4; u++) {
            bool ok = u < mm;
            int4 c = g_cols[ok ? p + u : p];
            dj[u] = ok ? 1.f : 0.f;
            vv[u] = h4unpack(xs[(size_t)c.z * 32 + lane]);
        }
        #pragma unroll
        for (int u = 0; u < 4; u++) {
            acc.x = fmaf(vv[u].x, dj[u], acc.x);
            acc.y = fmaf(vv[u].y, dj[u], acc.y);
            acc.z = fmaf(vv[u].z, dj[u], acc.z);
            acc.w = fmaf(vv[u].w, dj[u], acc.w);
        }
    }
    float di = g_dinv[w];
    float4 bb = ((const float4*)b)[lane];
    float4 y = make_float4(acc.x * di + bb.x, acc.y * di + bb.y,
                           acc.z * di + bb.z, acc.w * di + bb.w);
    float s1 = y.x + y.y + y.z + y.w;
    #pragma unroll
    for (int off = 16; off; off >>= 1) s1 += __shfl_xor_sync(0xffffffffu, s1, off);
    float mu = s1 * (1.0f / 128.0f);
    float dx = y.x - mu, dy = y.y - mu, dz = y.z - mu, dw = y.w - mu;
    float sq = dx * dx + dy * dy + dz * dz + dw * dw;
    #pragma unroll
    for (int off = 16; off; off >>= 1) sq += __shfl_xor_sync(0xffffffffu, sq, off);
    float rstd = rsqrtf(sq * (1.0f / 128.0f) + 1e-5f);
    float4 gg = ((const float4*)gamma)[lane];
    float4 bt = ((const float4*)beta)[lane];
    outp[(size_t)w * 32 + lane] = make_float4(dx * rstd * gg.x + bt.x,
                                              dy * rstd * gg.y + bt.y,
                                              dz * rstd * gg.z + bt.z,
                                              dw * rstd * gg.w + bt.w);
}

// ======== FUSED double GEMM (fp16 HMMA; TILE_M=64; 2 row-halves x 8 col-groups) ========

__device__ __forceinline__ void mma16816(float& c0, float& c1, float& c2, float& c3,
                                         uint32_t a0, uint32_t a1, uint32_t a2, uint32_t a3,
                                         uint32_t b0, uint32_t b1) {
    asm volatile(
        "mma.sync.aligned.m16n8k16.row.col.f32.f16.f16.f32 "
        "{%0,%1,%2,%3}, {%4,%5,%6,%7}, {%8,%9}, {%0,%1,%2,%3};"
        : "+f"(c0), "+f"(c1), "+f"(c2), "+f"(c3)
        : "r"(a0), "r"(a1), "r"(a2), "r"(a3), "r"(b0), "r"(b1));
}
__device__ __forceinline__ void ldm_x4(uint32_t addr, uint32_t& r0, uint32_t& r1,
                                       uint32_t& r2, uint32_t& r3) {
    asm volatile("ldmatrix.sync.aligned.m8n8.x4.shared.b16 {%0,%1,%2,%3}, [%4];"
                 : "=r"(r0), "=r"(r1), "=r"(r2), "=r"(r3) : "r"(addr));
}
__device__ __forceinline__ uint32_t smem_u32(const void* p) {
    return (uint32_t)__cvta_generic_to_shared(p);
}

// smem layout (bytes):
//   W1h : 256*136*2 = 69632
//   W2h : 128*264*2 = 67584
//   Ah  : 64*136*2  = 17408
//   X1h : 64*264*2  = 33792
//   s_sum/s_sq: 2*64*8*4 = 4096
#define ST1 136
#define ST2 264
__global__ void __launch_bounds__(512, 1)
k_gemm_fused(const float* __restrict__ W1, const float* __restrict__ b1,
             const float* __restrict__ g1, const float* __restrict__ be1,
             const float* __restrict__ W2, int M)
{
    extern __shared__ char sm[];
    __half* W1h = (__half*)sm;
    __half* W2h = (__half*)(sm + 69632);
    __half* Ah  = (__half*)(sm + 69632 + 67584);
    __half* X1h = (__half*)(sm + 69632 + 67584 + 17408);
    float* s_sum = (float*)(sm + 69632 + 67584 + 17408 + 33792);
    float* s_sq  = s_sum + 64 * 8;

    int tid = threadIdx.x, lane = tid & 31, wid = tid >> 5;
    int wr = wid & 1;            // row half (rows wr*32 .. wr*32+31)
    int wc = wid >> 1;           // col group 0..7
    int g = lane >> 2, t = lane & 3;
    int tl = lane >> 3, tr = lane & 7;

    // ---- weight conversion ----
    for (int i = tid; i < 128 * 256; i += 512) {
        int k = i >> 8, n = i & 255;
        W1h[n * ST1 + k] = __float2half_rn(W1[i]);
    }
    for (int i = tid; i < 256 * 128; i += 512) {
        int k = i >> 7, n = i & 127;
        W2h[n * ST2 + k] = __float2half_rn(W2[i]);
    }

    // ---- ldmatrix base addresses ----
    uint32_t a_addr[2];
    #pragma unroll
    for (int rt = 0; rt < 2; rt++) {
        int row = wr * 32 + rt * 16 + tr + 8 * (tl & 1);
        a_addr[rt] = smem_u32(Ah) + (uint32_t)((row * ST1 + 8 * (tl >> 1)) * 2);
    }
    uint32_t w1_addr[2];     // GEMM1: 32 cols per warp = 2 x4 pairs
    #pragma unroll
    for (int p = 0; p < 2; p++) {
        int n = wc * 32 + p * 16 + (tl >> 1) * 8 + tr;
        w1_addr[p] = smem_u32(W1h) + (uint32_t)((n * ST1 + 8 * (tl & 1)) * 2);
    }
    uint32_t x1_addr[2];
    #pragma unroll
    for (int rt = 0; rt < 2; rt++) {
        int row = wr * 32 + rt * 16 + tr + 8 * (tl & 1);
        x1_addr[rt] = smem_u32(X1h) + (uint32_t)((row * ST2 + 8 * (tl >> 1)) * 2);
    }
    uint32_t w2_addr;        // GEMM2: 16 cols per warp = 1 x4
    {
        int n = wc * 16 + (tl >> 1) * 8 + tr;
        w2_addr = smem_u32(W2h) + (uint32_t)((n * ST2 + 8 * (tl & 1)) * 2);
    }

    // ---- A prefetch (2 uint4 per thread) ----
    uint4 pf[2];
    const uint4 zero4 = make_uint4(0, 0, 0, 0);
    int m0 = blockIdx.x * 64;
    {
        #pragma unroll
        for (int c = 0; c < 2; c++) {
            int idx = tid + c * 512;
            int r = idx >> 4, c8 = (idx & 15) << 3;
            int row = m0 + r;
            pf[c] = (row < M) ? *(const uint4*)(g_ah + (size_t)row * 128 + c8) : zero4;
        }
    }

    for (; m0 < M; m0 += gridDim.x * 64) {
        __syncthreads();
        #pragma unroll
        for (int c = 0; c < 2; c++) {
            int idx = tid + c * 512;
            int r = idx >> 4, c8 = (idx & 15) << 3;
            *(uint4*)(Ah + r * ST1 + c8) = pf[c];
        }
        __syncthreads();

        int m1 = m0 + gridDim.x * 64;
        if (m1 < M) {
            #pragma unroll
            for (int c = 0; c < 2; c++) {
                int idx = tid + c * 512;
                int r = idx >> 4, c8 = (idx & 15) << 3;
                int row = m1 + r;
                pf[c] = (row < M) ? *(const uint4*)(g_ah + (size_t)row * 128 + c8) : zero4;
            }
        }

        // ================= GEMM1: x1 = A @ W1 =================
        float acc[2][4][4];
        #pragma unroll
        for (int rt = 0; rt < 2; rt++)
            #pragma unroll
            for (int nt = 0; nt < 4; nt++)
                #pragma unroll
                for (int q = 0; q < 4; q++) acc[rt][nt][q] = 0.f;

        #pragma unroll
        for (int kt = 0; kt < 8; kt++) {
            uint32_t koff = (uint32_t)kt * 32u;
            uint32_t ah[2][4], wb[2][4];
            #pragma unroll
            for (int rt = 0; rt < 2; rt++)
                ldm_x4(a_addr[rt] + koff, ah[rt][0], ah[rt][1], ah[rt][2], ah[rt][3]);
            #pragma unroll
            for (int p = 0; p < 2; p++)
                ldm_x4(w1_addr[p] + koff, wb[p][0], wb[p][1], wb[p][2], wb[p][3]);
            #pragma unroll
            for (int nt = 0; nt < 4; nt++) {
                uint32_t b0 = wb[nt >> 1][(nt & 1) * 2];
                uint32_t b1 = wb[nt >> 1][(nt & 1) * 2 + 1];
                #pragma unroll
                for (int rt = 0; rt < 2; rt++) {
                    float* c = acc[rt][nt];
                    mma16816(c[0], c[1], c[2], c[3],
                             ah[rt][0], ah[rt][1], ah[rt][2], ah[rt][3], b0, b1);
                }
            }
        }

        // ---- epilogue1: bias + ReLU + LayerNorm(256) -> X1 smem (fp16) ----
        #pragma unroll
        for (int rt = 0; rt < 2; rt++) {
            float s0 = 0.f, s1 = 0.f, q0 = 0.f, q1 = 0.f;
            #pragma unroll
            for (int nt = 0; nt < 4; nt++) {
                int c0 = wc * 32 + nt * 8 + 2 * t;
                float b0 = b1[c0], b1v = b1[c0 + 1];
                float* c = acc[rt][nt];
                c[0] = fmaxf(c[0] + b0, 0.f);
                c[1] = fmaxf(c[1] + b1v, 0.f);
                c[2] = fmaxf(c[2] + b0, 0.f);
                c[3] = fmaxf(c[3] + b1v, 0.f);
                s0 += c[0] + c[1]; q0 += c[0] * c[0] + c[1] * c[1];
                s1 += c[2] + c[3]; q1 += c[2] * c[2] + c[3] * c[3];
            }
            #pragma unroll
            for (int off = 1; off <= 2; off <<= 1) {
                s0 += __shfl_xor_sync(0xffffffffu, s0, off);
                q0 += __shfl_xor_sync(0xffffffffu, q0, off);
                s1 += __shfl_xor_sync(0xffffffffu, s1, off);
                q1 += __shfl_xor_sync(0xffffffffu, q1, off);
            }
            if (t == 0) {
                int lr = wr * 32 + rt * 16 + g;
                s_sum[lr * 8 + wc] = s0; s_sq[lr * 8 + wc] = q0;
                s_sum[(lr + 8) * 8 + wc] = s1; s_sq[(lr + 8) * 8 + wc] = q1;
            }
        }
        __syncthreads();
        #pragma unroll
        for (int rt = 0; rt < 2; rt++) {
            int lr0 = wr * 32 + rt * 16 + g;
            float ts0 = 0.f, tq0 = 0.f, ts1 = 0.f, tq1 = 0.f;
            #pragma unroll
            for (int j = 0; j < 8; j += 4) {
                float4 a0 = *(const float4*)(s_sum + lr0 * 8 + j);
                float4 b0v = *(const float4*)(s_sq + lr0 * 8 + j);
                float4 a1 = *(const float4*)(s_sum + (lr0 + 8) * 8 + j);
                float4 b1q = *(const float4*)(s_sq + (lr0 + 8) * 8 + j);
                ts0 += (a0.x + a0.y) + (a0.z + a0.w);
                tq0 += (b0v.x + b0v.y) + (b0v.z + b0v.w);
                ts1 += (a1.x + a1.y) + (a1.z + a1.w);
                tq1 += (b1q.x + b1q.y) + (b1q.z + b1q.w);
            }
            float mu0 = ts0 * (1.f / 256.f);
            float mu1 = ts1 * (1.f / 256.f);
            float v0 = tq0 * (1.f / 256.f) - mu0 * mu0;
            float v1 = tq1 * (1.f / 256.f) - mu1 * mu1;
            float rs0 = rsqrtf(v0 + 1e-5f), rs1 = rsqrtf(v1 + 1e-5f);
            #pragma unroll
            for (int nt = 0; nt < 4; nt++) {
                int c0 = wc * 32 + nt * 8 + 2 * t;
                float ga0 = g1[c0], ga1 = g1[c0 + 1];
                float be0 = be1[c0], be1v = be1[c0 + 1];
                float* c = acc[rt][nt];
                float o0 = (c[0] - mu0) * rs0 * ga0 + be0;
                float o1 = (c[1] - mu0) * rs0 * ga1 + be1v;
                float o2 = (c[2] - mu1) * rs1 * ga0 + be0;
                float o3 = (c[3] - mu1) * rs1 * ga1 + be1v;
                *(uint32_t*)(X1h + lr0 * ST2 + c0) =
                    h2pack(__float2half_rn(o0), __float2half_rn(o1));
                *(uint32_t*)(X1h + (lr0 + 8) * ST2 + c0) =
                    h2pack(__float2half_rn(o2), __float2half_rn(o3));
            }
        }
        __syncthreads();

        // ================= GEMM2: h2 = x1 @ W2 =================
        float acc2[2][2][4];
        #pragma unroll
        for (int rt = 0; rt < 2; rt++)
            #pragma unroll
            for (int nt = 0; nt < 2; nt++)
                #pragma unroll
                for (int q = 0; q < 4; q++) acc2[rt][nt][q] = 0.f;

        #pragma unroll
        for (int kt = 0; kt < 16; kt++) {
            uint32_t koff = (uint32_t)kt * 32u;
            uint32_t xh[2][4], wb2[4];
            #pragma unroll
            for (int rt = 0; rt < 2; rt++)
                ldm_x4(x1_addr[rt] + koff, xh[rt][0], xh[rt][1], xh[rt][2], xh[rt][3]);
            ldm_x4(w2_addr + koff, wb2[0], wb2[1], wb2[2], wb2[3]);
            #pragma unroll
            for (int nt = 0; nt < 2; nt++) {
                uint32_t b0 = wb2[nt * 2], b1v = wb2[nt * 2 + 1];
                #pragma unroll
                for (int rt = 0; rt < 2; rt++) {
                    float* c = acc2[rt][nt];
                    mma16816(c[0], c[1], c[2], c[3],
                             xh[rt][0], xh[rt][1], xh[rt][2], xh[rt][3], b0, b1v);
                }
            }
        }

        // ---- epilogue2: * dinv -> g_h2h (fp16) ----
        #pragma unroll
        for (int rt = 0; rt < 2; rt++) {
            int lr0 = wr * 32 + rt * 16 + g;
            int row0 = m0 + lr0, row1 = row0 + 8;
            float d0 = (row0 < M) ? g_dinv[row0] : 0.f;
            float d1 = (row1 < M) ? g_dinv[row1] : 0.f;
            #pragma unroll
            for (int nt = 0; nt < 2; nt++) {
                int c0 = wc * 16 + nt * 8 + 2 * t;
                float* c = acc2[rt][nt];
                if (row0 < M)
                    *(uint32_t*)(g_h2h + (size_t)row0 * 128 + c0) =
                        h2pack(__float2half_rn(c[0] * d0), __float2half_rn(c[1] * d0));
                if (row1 < M)
                    *(uint32_t*)(g_h2h + (size_t)row1 * 128 + c0) =
                        h2pack(__float2half_rn(c[2] * d1), __float2half_rn(c[3] * d1));
            }
        }
    }
}

// ---------------- launch ----------------
extern "C" void kernel_launch(void* const* d_in, const int* in_sizes, int n_in,
                              void* d_out, int out_size) {
    const int*   x_ids = (const int*)d_in[0];
    const int*   ei    = (const int*)d_in[1];
    const float* embed = (const float*)d_in[2];
    const float* W1    = (const float*)d_in[3];
    const float* b1    = (const float*)d_in[4];
    const float* g1    = (const float*)d_in[5];
    const float* be1   = (const float*)d_in[6];
    const float* W2    = (const float*)d_in[7];
    const float* b2    = (const float*)d_in[8];
    const float* g2    = (const float*)d_in[9];
    const float* be2   = (const float*)d_in[10];
    float* out = (float*)d_out;

    int n = in_sizes[0];        // 50000
    int E = in_sizes[1] / 2;    // 800000
    const int* src = ei;
    const int* dst = ei + E;

    const int SMEMSZ = 69632 + 67584 + 17408 + 33792 + 4096;   // 192512
    cudaFuncSetAttribute((const void*)k_gemm_fused,
                         cudaFuncAttributeMaxDynamicSharedMemorySize, SMEMSZ);

    int nb = (n + 1023) / 1024;
    int warps_grid = (n * 32 + 255) / 256;

    void* p_cnt = nullptr;  cudaGetSymbolAddress(&p_cnt, g_cnt);
    void* p_flag = nullptr; cudaGetSymbolAddress(&p_flag, g_bflag);
    cudaMemsetAsync(p_cnt, 0, (size_t)n * sizeof(int), 0);
    cudaMemsetAsync(p_flag, 0, 64 * sizeof(int), 0);

    k_histscan<<<nb, 1024>>>(dst, (const float4*)embed, n, E);   // kernel 0 (+embed cvt)
    k_fill<<<(E + 255) / 256, 256>>>(src, dst, x_ids, E);        // kernel 1

    k_agg0<<<warps_grid, 256>>>(x_ids, n);                       // kernel 2
    k_gemm_fused<<<152, 512, SMEMSZ>>>(W1, b1, g1, be1, W2, n);  // kernel 3 (ncu)

    k_agg1<<<warps_grid, 256>>>(b2, g2, be2, (float4*)out, n);   // kernel 4
}

// round 16
// speedup vs baseline: 1.9985x; 1.0166x over previous
#include <cuda_runtime.h>
#include <cuda_fp16.h>
#include <cstdint>

#define NMAX 50000
#define EMAX 800000

// ---------------- scratch ----------------
__device__ __half g_embh[(size_t)NMAX * 128];  // fp16 gathered embeddings (embh[i]=embed[x_ids[i]])
__device__ __half g_ah[(size_t)NMAX * 128];    // layer-1 agg output, fp16
__device__ __half g_h2h[(size_t)NMAX * 128];   // layer-2 transformed, fp16
__device__ float g_dinv[NMAX];
__device__ int   g_cnt[NMAX];
__device__ int   g_rowptr[NMAX + 1];
__device__ int   g_fill[NMAX];
__device__ int2  g_cols[EMAX];                 // {src, dinv[src] bits}
__device__ int   g_bsum[64];
__device__ int   g_bflag[64];                  // [0..48] scan flags, [56..58] grid barriers

__device__ __forceinline__ uint32_t h2pack(__half a, __half b) {
    return (uint32_t)__half_as_ushort(a) | ((uint32_t)__half_as_ushort(b) << 16);
}
__device__ __forceinline__ float4 h4unpack(uint2 v) {
    __half2 a = *(__half2*)&v.x, b = *(__half2*)&v.y;
    float2 fa = __half22float2(a), fb = __half22float2(b);
    return make_float4(fa.x, fa.y, fb.x, fb.y);
}

// grid-wide barrier (all blocks resident; distinct counter per use)
__device__ __forceinline__ void gbar(int idx, int expect) {
    __syncthreads();
    if (threadIdx.x == 0) {
        __threadfence();
        atomicAdd(&g_bflag[idx], 1);
        while (((volatile int*)g_bflag)[idx] < expect) { }
    }
    __syncthreads();
}

// ============ PREP: embed-cvt + histogram -> scan -> fill -> agg0, one kernel ============
__global__ void __launch_bounds__(1024, 1)
k_prep(const int* __restrict__ dst, const int* __restrict__ src,
       const int* __restrict__ x_ids, const float4* __restrict__ embed, int n, int E) {
    __shared__ int sh[1024];
    __shared__ int s_off;
    int tid = threadIdx.x, b = blockIdx.x;
    int gt = b * 1024 + tid;
    int gstride = gridDim.x * 1024;
    int nblocks = (int)gridDim.x;

    // ---- phase A: gathered embed fp32 -> fp16, + degree histogram ----
    for (int i = gt; i < n * 32; i += gstride) {
        int node = i >> 5, lane = i & 31;
        int id = __ldg(x_ids + node);            // uniform within warp
        float4 v = embed[(size_t)id * 32 + lane];
        uint2 hp;
        hp.x = h2pack(__float2half_rn(v.x), __float2half_rn(v.y));
        hp.y = h2pack(__float2half_rn(v.z), __float2half_rn(v.w));
        ((uint2*)g_embh)[i] = hp;
    }
    for (int i = gt; i < E; i += gstride)
        atomicAdd(&g_cnt[dst[i]], 1);
    gbar(56, nblocks);

    // ---- phase B: exclusive scan (blocks 0..48 handle 1024 nodes each) ----
    int nb = (n + 1023) / 1024;
    if (b < nb) {
        int i0 = b * 1024 + tid;
        int c = (i0 < n) ? g_cnt[i0] : 0;
        sh[tid] = c;
        __syncthreads();
        for (int off = 1; off < 1024; off <<= 1) {
            int t = (tid >= off) ? sh[tid - off] : 0;
            __syncthreads();
            sh[tid] += t;
            __syncthreads();
        }
        if (tid == 1023) {
            g_bsum[b] = sh[1023];
            __threadfence();
            g_bflag[b] = 1;
        }
        if (tid == 0) {
            int off = 0;
            for (int j = 0; j < b; j++) {
                while (((volatile int*)g_bflag)[j] == 0) { }
                off += ((volatile int*)g_bsum)[j];
            }
            s_off = off;
        }
        __syncthreads();
        if (i0 < n) {
            int incl = sh[tid] + s_off;
            int excl = incl - c;
            g_rowptr[i0] = excl;
            g_fill[i0] = excl;
            g_dinv[i0] = rsqrtf((float)(c + 1));
        }
        if (i0 == 0) g_rowptr[n] = E;
    }
    gbar(57, nblocks);

    // ---- phase C: CSR fill ----
    for (int i = gt; i < E; i += gstride) {
        int s = src[i];
        int d = dst[i];
        int pos = atomicAdd(&g_fill[d], 1);
        g_cols[pos] = make_int2(s, __float_as_int(g_dinv[s]));
    }
    gbar(58, nblocks);

    // ---- phase D: layer-1 aggregation (warp per node, grid-strided) ----
    int wtot = (gridDim.x * 1024) >> 5;
    int w0 = gt >> 5, lane = gt & 31;
    const uint2* embh = (const uint2*)g_embh;
    for (int w = w0; w < n; w += wtot) {
        float diw = g_dinv[w];
        float4 sv = h4unpack(embh[(size_t)w * 32 + lane]);
        float4 acc = make_float4(sv.x * diw, sv.y * diw, sv.z * diw, sv.w * diw);
        int s = g_rowptr[w], e = g_rowptr[w + 1];
        for (int p = s; p < e; p += 4) {
            int mm = e - p;
            float dj[4]; float4 vv[4];
            #pragma unroll
            for (int u = 0; u < 4; u++) {
                bool ok = u < mm;
                int2 c = g_cols[ok ? p + u : p];
                dj[u] = ok ? __int_as_float(c.y) : 0.f;
                vv[u] = h4unpack(embh[(size_t)c.x * 32 + lane]);
            }
            #pragma unroll
            for (int u = 0; u < 4; u++) {
                acc.x = fmaf(vv[u].x, dj[u], acc.x);
                acc.y = fmaf(vv[u].y, dj[u], acc.y);
                acc.z = fmaf(vv[u].z, dj[u], acc.z);
                acc.w = fmaf(vv[u].w, dj[u], acc.w);
            }
        }
        float4 o = make_float4(acc.x * diw, acc.y * diw, acc.z * diw, acc.w * diw);
        uint2 hp;
        hp.x = h2pack(__float2half_rn(o.x), __float2half_rn(o.y));
        hp.y = h2pack(__float2half_rn(o.z), __float2half_rn(o.w));
        *(uint2*)(g_ah + (size_t)w * 128 + lane * 4) = hp;
    }
}

// ---------------- layer-2 aggregation + bias + LayerNorm ----------------
__global__ void __launch_bounds__(256, 6)
k_agg1(const float* __restrict__ b, const float* __restrict__ gamma,
       const float* __restrict__ beta, float4* __restrict__ outp, int n) {
    int t = blockIdx.x * blockDim.x + threadIdx.x;
    int w = t >> 5, lane = t & 31;
    if (w >= n) return;
    const uint2* xs = (const uint2*)g_h2h;
    float4 acc = h4unpack(xs[(size_t)w * 32 + lane]);
    int s = g_rowptr[w], e = g_rowptr[w + 1];
    for (int p = s; p < e; p += 4) {
        int mm = e - p;
        float dj[4]; float4 vv[4];
        #pragma unroll
        for (int u = 0; u < 4; u++) {
            bool ok = u < mm;
            int2 c = g_cols[ok ? p + u : p];
            dj[u] = ok ? 1.f : 0.f;
            vv[u] = h4unpack(xs[(size_t)c.x * 32 + lane]);
        }
        #pragma unroll
        for (int u = 0; u < 4; u++) {
            acc.x = fmaf(vv[u].x, dj[u], acc.x);
            acc.y = fmaf(vv[u].y, dj[u], acc.y);
            acc.z = fmaf(vv[u].z, dj[u], acc.z);
            acc.w = fmaf(vv[u].w, dj[u], acc.w);
        }
    }
    float di = g_dinv[w];
    float4 bb = ((const float4*)b)[lane];
    float4 y = make_float4(acc.x * di + bb.x, acc.y * di + bb.y,
                           acc.z * di + bb.z, acc.w * di + bb.w);
    float s1 = y.x + y.y + y.z + y.w;
    #pragma unroll
    for (int off = 16; off; off >>= 1) s1 += __shfl_xor_sync(0xffffffffu, s1, off);
    float mu = s1 * (1.0f / 128.0f);
    float dx = y.x - mu, dy = y.y - mu, dz = y.z - mu, dw = y.w - mu;
    float sq = dx * dx + dy * dy + dz * dz + dw * dw;
    #pragma unroll
    for (int off = 16; off; off >>= 1) sq += __shfl_xor_sync(0xffffffffu, sq, off);
    float rstd = rsqrtf(sq * (1.0f / 128.0f) + 1e-5f);
    float4 gg = ((const float4*)gamma)[lane];
    float4 bt = ((const float4*)beta)[lane];
    outp[(size_t)w * 32 + lane] = make_float4(dx * rstd * gg.x + bt.x,
                                              dy * rstd * gg.y + bt.y,
                                              dz * rstd * gg.z + bt.z,
                                              dw * rstd * gg.w + bt.w);
}

// ======== FUSED double GEMM (fp16 HMMA; TILE_M=64; double-buffered A) ========

__device__ __forceinline__ void mma16816(float& c0, float& c1, float& c2, float& c3,
                                         uint32_t a0, uint32_t a1, uint32_t a2, uint32_t a3,
                                         uint32_t b0, uint32_t b1) {
    asm volatile(
        "mma.sync.aligned.m16n8k16.row.col.f32.f16.f16.f32 "
        "{%0,%1,%2,%3}, {%4,%5,%6,%7}, {%8,%9}, {%0,%1,%2,%3};"
        : "+f"(c0), "+f"(c1), "+f"(c2), "+f"(c3)
        : "r"(a0), "r"(a1), "r"(a2), "r"(a3), "r"(b0), "r"(b1));
}
__device__ __forceinline__ void ldm_x4(uint32_t addr, uint32_t& r0, uint32_t& r1,
                                       uint32_t& r2, uint32_t& r3) {
    asm volatile("ldmatrix.sync.aligned.m8n8.x4.shared.b16 {%0,%1,%2,%3}, [%4];"
                 : "=r"(r0), "=r"(r1), "=r"(r2), "=r"(r3) : "r"(addr));
}
__device__ __forceinline__ uint32_t smem_u32(const void* p) {
    return (uint32_t)__cvta_generic_to_shared(p);
}

// smem layout (bytes):
//   W1h : 256*136*2 = 69632
//   W2h : 128*264*2 = 67584
//   Ah0 : 64*136*2  = 17408
//   Ah1 : 64*136*2  = 17408
//   X1h : 64*264*2  = 33792
//   s_sum/s_sq: 2*64*8*4 = 4096     -> total 209920
#define ST1 136
#define ST2 264
#define ABUF 17408u
__global__ void __launch_bounds__(512, 1)
k_gemm_fused(const float* __restrict__ W1, const float* __restrict__ b1,
             const float* __restrict__ g1, const float* __restrict__ be1,
             const float* __restrict__ W2, int M)
{
    extern __shared__ char sm[];
    __half* W1h = (__half*)sm;
    __half* W2h = (__half*)(sm + 69632);
    __half* Ah0 = (__half*)(sm + 69632 + 67584);
    __half* X1h = (__half*)(sm + 69632 + 67584 + 2 * ABUF);
    float* s_sum = (float*)(sm + 69632 + 67584 + 2 * ABUF + 33792);
    float* s_sq  = s_sum + 64 * 8;

    int tid = threadIdx.x, lane = tid & 31, wid = tid >> 5;
    int wr = wid & 1;            // row half
    int wc = wid >> 1;           // col group 0..7
    int g = lane >> 2, t = lane & 3;
    int tl = lane >> 3, tr = lane & 7;

    // ---- weight conversion ----
    for (int i = tid; i < 128 * 256; i += 512) {
        int k = i >> 8, n = i & 255;
        W1h[n * ST1 + k] = __float2half_rn(W1[i]);
    }
    for (int i = tid; i < 256 * 128; i += 512) {
        int k = i >> 7, n = i & 127;
        W2h[n * ST2 + k] = __float2half_rn(W2[i]);
    }

    // ---- ldmatrix base addresses ----
    uint32_t a_addr[2];
    #pragma unroll
    for (int rt = 0; rt < 2; rt++) {
        int row = wr * 32 + rt * 16 + tr + 8 * (tl & 1);
        a_addr[rt] = smem_u32(Ah0) + (uint32_t)((row * ST1 + 8 * (tl >> 1)) * 2);
    }
    uint32_t w1_addr[2];
    #pragma unroll
    for (int p = 0; p < 2; p++) {
        int n = wc * 32 + p * 16 + (tl >> 1) * 8 + tr;
        w1_addr[p] = smem_u32(W1h) + (uint32_t)((n * ST1 + 8 * (tl & 1)) * 2);
    }
    uint32_t x1_addr[2];
    #pragma unroll
    for (int rt = 0; rt < 2; rt++) {
        int row = wr * 32 + rt * 16 + tr + 8 * (tl & 1);
        x1_addr[rt] = smem_u32(X1h) + (uint32_t)((row * ST2 + 8 * (tl >> 1)) * 2);
    }
    uint32_t w2_addr;
    {
        int n = wc * 16 + (tl >> 1) * 8 + tr;
        w2_addr = smem_u32(W2h) + (uint32_t)((n * ST2 + 8 * (tl & 1)) * 2);
    }

    // ---- A prefetch ----
    uint4 pf[2];
    const uint4 zero4 = make_uint4(0, 0, 0, 0);
    int m0 = blockIdx.x * 64;
    {
        #pragma unroll
        for (int c = 0; c < 2; c++) {
            int idx = tid + c * 512;
            int r = idx >> 4, c8 = (idx & 15) << 3;
            int row = m0 + r;
            pf[c] = (row < M) ? *(const uint4*)(g_ah + (size_t)row * 128 + c8) : zero4;
        }
    }

    uint32_t buf = 0;
    for (; m0 < M; m0 += gridDim.x * 64) {
        // store A into current buffer (no sync needed: nobody reads this buffer now)
        __half* Ab = Ah0 + (buf ? ABUF / 2 : 0);
        #pragma unroll
        for (int c = 0; c < 2; c++) {
            int idx = tid + c * 512;
            int r = idx >> 4, c8 = (idx & 15) << 3;
            *(uint4*)(Ab + r * ST1 + c8) = pf[c];
        }
        int m1 = m0 + gridDim.x * 64;
        if (m1 < M) {
            #pragma unroll
            for (int c = 0; c < 2; c++) {
                int idx = tid + c * 512;
                int r = idx >> 4, c8 = (idx & 15) << 3;
                int row = m1 + r;
                pf[c] = (row < M) ? *(const uint4*)(g_ah + (size_t)row * 128 + c8) : zero4;
            }
        }
        __syncthreads();   // A stores visible before ldmatrix

        uint32_t aoff = buf ? ABUF : 0u;

        // ================= GEMM1: x1 = A @ W1 =================
        float acc[2][4][4];
        #pragma unroll
        for (int rt = 0; rt < 2; rt++)
            #pragma unroll
            for (int nt = 0; nt < 4; nt++)
                #pragma unroll
                for (int q = 0; q < 4; q++) acc[rt][nt][q] = 0.f;

        #pragma unroll
        for (int kt = 0; kt < 8; kt++) {
            uint32_t koff = (uint32_t)kt * 32u + aoff;
            uint32_t koffw = (uint32_t)kt * 32u;
            uint32_t ah[2][4], wb[2][4];
            #pragma unroll
            for (int rt = 0; rt < 2; rt++)
                ldm_x4(a_addr[rt] + koff, ah[rt][0], ah[rt][1], ah[rt][2], ah[rt][3]);
            #pragma unroll
            for (int p = 0; p < 2; p++)
                ldm_x4(w1_addr[p] + koffw, wb[p][0], wb[p][1], wb[p][2], wb[p][3]);
            #pragma unroll
            for (int nt = 0; nt < 4; nt++) {
                uint32_t b0 = wb[nt >> 1][(nt & 1) * 2];
                uint32_t b1 = wb[nt >> 1][(nt & 1) * 2 + 1];
                #pragma unroll
                for (int rt = 0; rt < 2; rt++) {
                    float* c = acc[rt][nt];
                    mma16816(c[0], c[1], c[2], c[3],
                             ah[rt][0], ah[rt][1], ah[rt][2], ah[rt][3], b0, b1);
                }
            }
        }
        buf ^= 1;

        // ---- epilogue1: bias + ReLU + LayerNorm(256) -> X1 smem (fp16) ----
        #pragma unroll
        for (int rt = 0; rt < 2; rt++) {
            float s0 = 0.f, s1 = 0.f, q0 = 0.f, q1 = 0.f;
            #pragma unroll
            for (int nt = 0; nt < 4; nt++) {
                int c0 = wc * 32 + nt * 8 + 2 * t;
                float b0 = b1[c0], b1v = b1[c0 + 1];
                float* c = acc[rt][nt];
                c[0] = fmaxf(c[0] + b0, 0.f);
                c[1] = fmaxf(c[1] + b1v, 0.f);
                c[2] = fmaxf(c[2] + b0, 0.f);
                c[3] = fmaxf(c[3] + b1v, 0.f);
                s0 += c[0] + c[1]; q0 += c[0] * c[0] + c[1] * c[1];
                s1 += c[2] + c[3]; q1 += c[2] * c[2] + c[3] * c[3];
            }
            #pragma unroll
            for (int off = 1; off <= 2; off <<= 1) {
                s0 += __shfl_xor_sync(0xffffffffu, s0, off);
                q0 += __shfl_xor_sync(0xffffffffu, q0, off);
                s1 += __shfl_xor_sync(0xffffffffu, s1, off);
                q1 += __shfl_xor_sync(0xffffffffu, q1, off);
            }
            if (t == 0) {
                int lr = wr * 32 + rt * 16 + g;
                s_sum[lr * 8 + wc] = s0; s_sq[lr * 8 + wc] = q0;
                s_sum[(lr + 8) * 8 + wc] = s1; s_sq[(lr + 8) * 8 + wc] = q1;
            }
        }
        __syncthreads();
        #pragma unroll
        for (int rt = 0; rt < 2; rt++) {
            int lr0 = wr * 32 + rt * 16 + g;
            float ts0 = 0.f, tq0 = 0.f, ts1 = 0.f, tq1 = 0.f;
            #pragma unroll
            for (int j = 0; j < 8; j += 4) {
                float4 a0 = *(const float4*)(s_sum + lr0 * 8 + j);
                float4 b0v = *(const float4*)(s_sq + lr0 * 8 + j);
                float4 a1 = *(const float4*)(s_sum + (lr0 + 8) * 8 + j);
                float4 b1q = *(const float4*)(s_sq + (lr0 + 8) * 8 + j);
                ts0 += (a0.x + a0.y) + (a0.z + a0.w);
                tq0 += (b0v.x + b0v.y) + (b0v.z + b0v.w);
                ts1 += (a1.x + a1.y) + (a1.z + a1.w);
                tq1 += (b1q.x + b1q.y) + (b1q.z + b1q.w);
            }
            float mu0 = ts0 * (1.f / 256.f);
            float mu1 = ts1 * (1.f / 256.f);
            float v0 = tq0 * (1.f / 256.f) - mu0 * mu0;
            float v1 = tq1 * (1.f / 256.f) - mu1 * mu1;
            float rs0 = rsqrtf(v0 + 1e-5f), rs1 = rsqrtf(v1 + 1e-5f);
            #pragma unroll
            for (int nt = 0; nt < 4; nt++) {
                int c0 = wc * 32 + nt * 8 + 2 * t;
                float ga0 = g1[c0], ga1 = g1[c0 + 1];
                float be0 = be1[c0], be1v = be1[c0 + 1];
                float* c = acc[rt][nt];
                float o0 = (c[0] - mu0) * rs0 * ga0 + be0;
                float o1 = (c[1] - mu0) * rs0 * ga1 + be1v;
                float o2 = (c[2] - mu1) * rs1 * ga0 + be0;
                float o3 = (c[3] - mu1) * rs1 * ga1 + be1v;
                *(uint32_t*)(X1h + lr0 * ST2 + c0) =
                    h2pack(__float2half_rn(o0), __float2half_rn(o1));
                *(uint32_t*)(X1h + (lr0 + 8) * ST2 + c0) =
                    h2pack(__float2half_rn(o2), __float2half_rn(o3));
            }
        }
        __syncthreads();

        // ================= GEMM2: h2 = x1 @ W2 =================
        float acc2[2][2][4];
        #pragma unroll
        for (int rt = 0; rt < 2; rt++)
            #pragma unroll
            for (int nt = 0; nt < 2; nt++)
                #pragma unroll
                for (int q = 0; q < 4; q++) acc2[rt][nt][q] = 0.f;

        #pragma unroll
        for (int kt = 0; kt < 16; kt++) {
            uint32_t koff = (uint32_t)kt * 32u;
            uint32_t xh[2][4], wb2[4];
            #pragma unroll
            for (int rt = 0; rt < 2; rt++)
                ldm_x4(x1_addr[rt] + koff, xh[rt][0], xh[rt][1], xh[rt][2], xh[rt][3]);
            ldm_x4(w2_addr + koff, wb2[0], wb2[1], wb2[2], wb2[3]);
            #pragma unroll
            for (int nt = 0; nt < 2; nt++) {
                uint32_t b0 = wb2[nt * 2], b1v = wb2[nt * 2 + 1];
                #pragma unroll
                for (int rt = 0; rt < 2; rt++) {
                    float* c = acc2[rt][nt];
                    mma16816(c[0], c[1], c[2], c[3],
                             xh[rt][0], xh[rt][1], xh[rt][2], xh[rt][3], b0, b1v);
                }
            }
        }

        // ---- epilogue2: * dinv -> g_h2h (fp16) ----
        #pragma unroll
        for (int rt = 0; rt < 2; rt++) {
            int lr0 = wr * 32 + rt * 16 + g;
            int row0 = m0 + lr0, row1 = row0 + 8;
            float d0 = (row0 < M) ? g_dinv[row0] : 0.f;
            float d1 = (row1 < M) ? g_dinv[row1] : 0.f;
            #pragma unroll
            for (int nt = 0; nt < 2; nt++) {
                int c0 = wc * 16 + nt * 8 + 2 * t;
                float* c = acc2[rt][nt];
                if (row0 < M)
                    *(uint32_t*)(g_h2h + (size_t)row0 * 128 + c0) =
                        h2pack(__float2half_rn(c[0] * d0), __float2half_rn(c[1] * d0));
                if (row1 < M)
                    *(uint32_t*)(g_h2h + (size_t)row1 * 128 + c0) =
                        h2pack(__float2half_rn(c[2] * d1), __float2half_rn(c[3] * d1));
            }
        }
        __syncthreads();   // X1h / s_sum free for next tile
    }
}

// ---------------- launch ----------------
extern "C" void kernel_launch(void* const* d_in, const int* in_sizes, int n_in,
                              void* d_out, int out_size) {
    const int*   x_ids = (const int*)d_in[0];
    const int*   ei    = (const int*)d_in[1];
    const float* embed = (const float*)d_in[2];
    const float* W1    = (const float*)d_in[3];
    const float* b1    = (const float*)d_in[4];
    const float* g1    = (const float*)d_in[5];
    const float* be1   = (const float*)d_in[6];
    const float* W2    = (const float*)d_in[7];
    const float* b2    = (const float*)d_in[8];
    const float* g2    = (const float*)d_in[9];
    const float* be2   = (const float*)d_in[10];
    float* out = (float*)d_out;

    int n = in_sizes[0];        // 50000
    int E = in_sizes[1] / 2;    // 800000
    const int* src = ei;
    const int* dst = ei + E;

    const int SMEMSZ = 69632 + 67584 + 2 * 17408 + 33792 + 4096;   // 209920
    cudaFuncSetAttribute((const void*)k_gemm_fused,
                         cudaFuncAttributeMaxDynamicSharedMemorySize, SMEMSZ);

    int warps_grid = (n * 32 + 255) / 256;

    void* p_cnt = nullptr;  cudaGetSymbolAddress(&p_cnt, g_cnt);
    void* p_flag = nullptr; cudaGetSymbolAddress(&p_flag, g_bflag);
    cudaMemsetAsync(p_cnt, 0, (size_t)n * sizeof(int), 0);
    cudaMemsetAsync(p_flag, 0, 64 * sizeof(int), 0);

    k_prep<<<152, 1024>>>(dst, src, x_ids, (const float4*)embed, n, E);  // kernel 0
    k_gemm_fused<<<152, 512, SMEMSZ>>>(W1, b1, g1, be1, W2, n);          // kernel 1
    k_agg1<<<warps_grid, 256>>>(b2, g2, be2, (float4*)out, n);           // kernel 2
}